// round 1
// baseline (speedup 1.0000x reference)
#include <cuda_runtime.h>
#include <math.h>

#define N_HEADS 8
#define EMBED 640
#define CROSS 768
#define HEAD 80
#define BATCH 8
#define SEQ_T 4096
#define SEQ_S 77

// Scratch (no cudaMalloc allowed)
__device__ float g_q[BATCH * SEQ_T * EMBED];
__device__ float g_attn[BATCH * SEQ_T * EMBED];
__device__ float g_k[BATCH * SEQ_S * EMBED];
__device__ float g_v[BATCH * SEQ_S * EMBED];

// ---------------------------------------------------------------------------
// Tiled FP32 GEMM: C[M,N] = A[M,K] @ B[K,N] + bias[N]
// BM=BN=128, BK=8, 256 threads, 8x8 micro-tile per thread.
// Requires N % 128 == 0 and K % 8 == 0 (true for all our shapes).
// M is bounds-checked.
// ---------------------------------------------------------------------------
__global__ __launch_bounds__(256, 2)
void gemm128(const float* __restrict__ A, const float* __restrict__ B,
             const float* __restrict__ bias, float* __restrict__ C,
             int M, int N, int K) {
    __shared__ float As[8][128];
    __shared__ float Bs[8][128];

    const int tid = threadIdx.x;
    const int bm = blockIdx.y * 128;
    const int bn = blockIdx.x * 128;

    // A-load mapping: one float4 per thread
    const int aRow = tid >> 1;             // 0..127
    const int aCol = (tid & 1) * 4;        // 0 or 4
    // B-load mapping: one float4 per thread
    const int bRow = tid >> 5;             // 0..7
    const int bCol = (tid & 31) * 4;       // 0..124

    const int tx = tid & 15;               // 0..15
    const int ty = tid >> 4;               // 0..15

    float c[8][8];
#pragma unroll
    for (int i = 0; i < 8; i++)
#pragma unroll
        for (int j = 0; j < 8; j++) c[i][j] = 0.0f;

    const int nK = K >> 3;
    for (int kt = 0; kt < nK; kt++) {
        // load A tile (transposed into smem)
        int gRow = bm + aRow;
        float4 av = make_float4(0.f, 0.f, 0.f, 0.f);
        if (gRow < M)
            av = *reinterpret_cast<const float4*>(&A[(size_t)gRow * K + kt * 8 + aCol]);
        As[aCol + 0][aRow] = av.x;
        As[aCol + 1][aRow] = av.y;
        As[aCol + 2][aRow] = av.z;
        As[aCol + 3][aRow] = av.w;
        // load B tile
        float4 bv = *reinterpret_cast<const float4*>(&B[(size_t)(kt * 8 + bRow) * N + bn + bCol]);
        *reinterpret_cast<float4*>(&Bs[bRow][bCol]) = bv;
        __syncthreads();

#pragma unroll
        for (int kk = 0; kk < 8; kk++) {
            float a[8], bb[8];
            *reinterpret_cast<float4*>(&a[0]) = *reinterpret_cast<const float4*>(&As[kk][ty * 4]);
            *reinterpret_cast<float4*>(&a[4]) = *reinterpret_cast<const float4*>(&As[kk][64 + ty * 4]);
            *reinterpret_cast<float4*>(&bb[0]) = *reinterpret_cast<const float4*>(&Bs[kk][tx * 4]);
            *reinterpret_cast<float4*>(&bb[4]) = *reinterpret_cast<const float4*>(&Bs[kk][64 + tx * 4]);
#pragma unroll
            for (int i = 0; i < 8; i++)
#pragma unroll
                for (int j = 0; j < 8; j++)
                    c[i][j] += a[i] * bb[j];
        }
        __syncthreads();
    }

    // epilogue with bias
#pragma unroll
    for (int ih = 0; ih < 2; ih++) {
#pragma unroll
        for (int ii = 0; ii < 4; ii++) {
            int row = bm + ih * 64 + ty * 4 + ii;
            if (row >= M) continue;
#pragma unroll
            for (int jh = 0; jh < 2; jh++) {
                int col = bn + jh * 64 + tx * 4;
                float4 r;
                r.x = c[ih * 4 + ii][jh * 4 + 0] + bias[col + 0];
                r.y = c[ih * 4 + ii][jh * 4 + 1] + bias[col + 1];
                r.z = c[ih * 4 + ii][jh * 4 + 2] + bias[col + 2];
                r.w = c[ih * 4 + ii][jh * 4 + 3] + bias[col + 3];
                *reinterpret_cast<float4*>(&C[(size_t)row * N + col]) = r;
            }
        }
    }
}

// ---------------------------------------------------------------------------
// Fused attention core: for each (b, h, tile of 32 t-rows):
//   scores = q @ k^T / sqrt(D); softmax over S=77; out = scores @ v
// k,v,q,scores all staged in dynamic smem (69760 B).
// ---------------------------------------------------------------------------
__global__ __launch_bounds__(256)
void attn_kernel(const float* __restrict__ q, const float* __restrict__ k,
                 const float* __restrict__ v, float* __restrict__ o) {
    extern __shared__ float sm[];
    float* ks = sm;               // 77*80
    float* vs = ks + SEQ_S * 80;  // 77*80
    float* qs = vs + SEQ_S * 80;  // 32*80
    float* sc = qs + 32 * 80;     // 32*80

    const int b = blockIdx.z;
    const int h = blockIdx.y;
    const int t0 = blockIdx.x * 32;
    const int tid = threadIdx.x;

    // stage k, v for this (b,h)
    for (int i = tid; i < SEQ_S * 80; i += 256) {
        int s = i / 80, d = i % 80;
        size_t gi = ((size_t)(b * SEQ_S + s)) * EMBED + h * 80 + d;
        ks[i] = k[gi];
        vs[i] = v[gi];
    }
    // stage q tile
    for (int i = tid; i < 32 * 80; i += 256) {
        int t = i / 80, d = i % 80;
        qs[i] = q[((size_t)(b * SEQ_T + t0 + t)) * EMBED + h * 80 + d];
    }
    __syncthreads();

    // scores
    const float scale = 0.11180339887498949f; // 1/sqrt(80)
    for (int i = tid; i < 32 * SEQ_S; i += 256) {
        int t = i / SEQ_S, s = i % SEQ_S;
        const float4* qp = reinterpret_cast<const float4*>(&qs[t * 80]);
        const float4* kp = reinterpret_cast<const float4*>(&ks[s * 80]);
        float acc = 0.f;
#pragma unroll
        for (int d4 = 0; d4 < 20; d4++) {
            float4 a = qp[d4], c2 = kp[d4];
            acc += a.x * c2.x + a.y * c2.y + a.z * c2.z + a.w * c2.w;
        }
        sc[t * 80 + s] = acc * scale;
    }
    __syncthreads();

    // softmax: warp w handles rows 4w..4w+3; lane l covers s = l, l+32, l+64
    const int w = tid >> 5, l = tid & 31;
    for (int r = w * 4; r < w * 4 + 4; r++) {
        float v0 = sc[r * 80 + l];
        float v1 = sc[r * 80 + 32 + l];
        float v2 = (l < 13) ? sc[r * 80 + 64 + l] : -1e30f;
        float m = fmaxf(v0, fmaxf(v1, v2));
#pragma unroll
        for (int off = 16; off; off >>= 1) m = fmaxf(m, __shfl_xor_sync(0xFFFFFFFFu, m, off));
        float e0 = __expf(v0 - m);
        float e1 = __expf(v1 - m);
        float e2 = (l < 13) ? __expf(v2 - m) : 0.f;
        float su = e0 + e1 + e2;
#pragma unroll
        for (int off = 16; off; off >>= 1) su += __shfl_xor_sync(0xFFFFFFFFu, su, off);
        float inv = 1.f / su;
        sc[r * 80 + l] = e0 * inv;
        sc[r * 80 + 32 + l] = e1 * inv;
        if (l < 13) sc[r * 80 + 64 + l] = e2 * inv;
    }
    __syncthreads();

    // out = P @ V : one float4 column-chunk per work item
    for (int i = tid; i < 32 * 20; i += 256) {
        int t = i / 20, d4 = i % 20;
        float4 acc = make_float4(0.f, 0.f, 0.f, 0.f);
#pragma unroll 7
        for (int s = 0; s < SEQ_S; s++) {
            float p = sc[t * 80 + s];
            float4 vv = *reinterpret_cast<const float4*>(&vs[s * 80 + d4 * 4]);
            acc.x += p * vv.x;
            acc.y += p * vv.y;
            acc.z += p * vv.z;
            acc.w += p * vv.w;
        }
        *reinterpret_cast<float4*>(&o[((size_t)(b * SEQ_T + t0 + t)) * EMBED + h * 80 + d4 * 4]) = acc;
    }
}

// ---------------------------------------------------------------------------
extern "C" void kernel_launch(void* const* d_in, const int* in_sizes, int n_in,
                              void* d_out, int out_size) {
    const float* x  = (const float*)d_in[0];
    const float* y  = (const float*)d_in[1];
    const float* Wq = (const float*)d_in[2];
    const float* bq = (const float*)d_in[3];
    const float* Wk = (const float*)d_in[4];
    const float* bk = (const float*)d_in[5];
    const float* Wv = (const float*)d_in[6];
    const float* bv = (const float*)d_in[7];
    const float* Wo = (const float*)d_in[8];
    const float* bo = (const float*)d_in[9];
    float* out = (float*)d_out;

    float *qb, *ab, *kb, *vb;
    cudaGetSymbolAddress((void**)&qb, g_q);
    cudaGetSymbolAddress((void**)&ab, g_attn);
    cudaGetSymbolAddress((void**)&kb, g_k);
    cudaGetSymbolAddress((void**)&vb, g_v);

    const int smem_attn = (SEQ_S * 80 * 2 + 32 * 80 * 2) * (int)sizeof(float); // 69760
    cudaFuncSetAttribute(attn_kernel, cudaFuncAttributeMaxDynamicSharedMemorySize, smem_attn);

    // Q projection: [32768,640] @ [640,640]
    {
        dim3 grid(EMBED / 128, (BATCH * SEQ_T + 127) / 128);
        gemm128<<<grid, 256>>>(x, Wq, bq, qb, BATCH * SEQ_T, EMBED, EMBED);
    }
    // K projection: [616,768] @ [768,640]
    {
        dim3 grid(EMBED / 128, (BATCH * SEQ_S + 127) / 128);
        gemm128<<<grid, 256>>>(y, Wk, bk, kb, BATCH * SEQ_S, EMBED, CROSS);
        gemm128<<<grid, 256>>>(y, Wv, bv, vb, BATCH * SEQ_S, EMBED, CROSS);
    }
    // attention
    {
        dim3 grid(SEQ_T / 32, N_HEADS, BATCH);
        attn_kernel<<<grid, 256, smem_attn>>>(qb, kb, vb, ab);
    }
    // output projection
    {
        dim3 grid(EMBED / 128, (BATCH * SEQ_T + 127) / 128);
        gemm128<<<grid, 256>>>(ab, Wo, bo, out, BATCH * SEQ_T, EMBED, EMBED);
    }
}

// round 3
// speedup vs baseline: 1.1923x; 1.1923x over previous
#include <cuda_runtime.h>
#include <cuda_bf16.h>
#include <cstdint>
#include <math.h>

#define N_HEADS 8
#define EMBED 640
#define CROSS 768
#define HEAD 80
#define BATCH 8
#define SEQ_T 4096
#define SEQ_S 77

#define GK 640          // K dim of the big GEMMs
#define BKT 32          // K per pipeline stage
#define NST (GK / BKT)  // 20 stages

// ---------------------------------------------------------------------------
// Scratch (no cudaMalloc allowed)
// ---------------------------------------------------------------------------
__device__ float g_q[BATCH * SEQ_T * EMBED];
__device__ float g_attn[BATCH * SEQ_T * EMBED];
__device__ float g_k[BATCH * SEQ_S * EMBED];
__device__ float g_v[BATCH * SEQ_S * EMBED];
__device__ __align__(16) unsigned short g_xhi[BATCH * SEQ_T * EMBED];
__device__ __align__(16) unsigned short g_xlo[BATCH * SEQ_T * EMBED];
__device__ __align__(16) unsigned short g_wthi[EMBED * EMBED];
__device__ __align__(16) unsigned short g_wtlo[EMBED * EMBED];

// ---------------------------------------------------------------------------
// PTX helpers (all non-'a' features: ldmatrix, mma.sync, cp.async)
// ---------------------------------------------------------------------------
__device__ __forceinline__ uint32_t smem_to_u32(const void* smem_ptr) {
    uint32_t addr;
    asm("{ .reg .u64 tmp; cvta.to.shared.u64 tmp, %1; cvt.u32.u64 %0, tmp; }"
        : "=r"(addr) : "l"(smem_ptr));
    return addr;
}

#define LDSM4(r, addr) \
    asm volatile("ldmatrix.sync.aligned.m8n8.x4.shared.b16 {%0,%1,%2,%3},[%4];" \
        : "=r"((r)[0]), "=r"((r)[1]), "=r"((r)[2]), "=r"((r)[3]) : "r"(addr))

#define MMA16816(d, a, b) \
    asm volatile("mma.sync.aligned.m16n8k16.row.col.f32.bf16.bf16.f32 " \
        "{%0,%1,%2,%3},{%4,%5,%6,%7},{%8,%9},{%0,%1,%2,%3};" \
        : "+f"((d)[0]), "+f"((d)[1]), "+f"((d)[2]), "+f"((d)[3]) \
        : "r"((a)[0]), "r"((a)[1]), "r"((a)[2]), "r"((a)[3]), \
          "r"((b)[0]), "r"((b)[1]))

#define CP16(sp, gp) \
    asm volatile("cp.async.cg.shared.global [%0],[%1],16;" :: "r"(sp), "l"(gp))
#define CP_COMMIT() asm volatile("cp.async.commit_group;")
#define CP_WAIT1()  asm volatile("cp.async.wait_group 1;")
#define CP_WAIT0()  asm volatile("cp.async.wait_group 0;")

// ---------------------------------------------------------------------------
// FP32 -> bf16 hi/lo split (elementwise)
// ---------------------------------------------------------------------------
__global__ void split_fp32(const float* __restrict__ in,
                           __nv_bfloat16* __restrict__ hi,
                           __nv_bfloat16* __restrict__ lo, int n) {
    int i = blockIdx.x * blockDim.x + threadIdx.x;
    if (i < n) {
        float v = in[i];
        __nv_bfloat16 h = __float2bfloat16(v);
        hi[i] = h;
        lo[i] = __float2bfloat16(v - __bfloat162float(h));
    }
}

// W[K,N] -> Wt[N,K] bf16 hi/lo (transpose + split); K = N = 640
__global__ void wsplit_tr(const float* __restrict__ W,
                          __nv_bfloat16* __restrict__ thi,
                          __nv_bfloat16* __restrict__ tlo) {
    int idx = blockIdx.x * blockDim.x + threadIdx.x;
    if (idx >= EMBED * EMBED) return;
    int n = idx / EMBED, k = idx - n * EMBED;
    float v = W[k * EMBED + n];
    __nv_bfloat16 h = __float2bfloat16(v);
    thi[idx] = h;
    tlo[idx] = __float2bfloat16(v - __bfloat162float(h));
}

// ---------------------------------------------------------------------------
// Tensor-core GEMM via mma.sync (bf16 3-term split, fp32 accumulate):
//   C[M,640] = A[M,640] @ W[640,640] + bias,  A as hi/lo [M,K] bf16 K-major,
//   W as Bt hi/lo [N,K] bf16 K-major.
// CTA tile 128x128, BK=32, 8 warps (warp tile 64x32), cp.async 2-stage pipe.
// smem rows padded to 40 bf16 (80B): 80*r mod 128 hits all 8 16B banks ->
// conflict-free ldmatrix without XOR swizzle.
// ---------------------------------------------------------------------------
__global__ __launch_bounds__(256, 1)
void gemm_mma(const __nv_bfloat16* __restrict__ Ahi,
              const __nv_bfloat16* __restrict__ Alo,
              const __nv_bfloat16* __restrict__ Bhi,
              const __nv_bfloat16* __restrict__ Blo,
              const float* __restrict__ bias, float* __restrict__ C) {
    extern __shared__ char smem[];
    const uint32_t sbase = smem_to_u32(smem);
    const int tid = threadIdx.x;
    const int lane = tid & 31;
    const int wid = tid >> 5;
    const int wm = wid >> 2;       // 0..1  (M warp)
    const int wn = wid & 3;        // 0..3  (N warp)
    const int bm = blockIdx.y * 128;
    const int bn = blockIdx.x * 128;

    // per-term global tile base pointers (uint4 granularity, row = 80 uint4)
    const uint4* gA0 = (const uint4*)(Ahi + (size_t)bm * GK);
    const uint4* gA1 = (const uint4*)(Alo + (size_t)bm * GK);
    const uint4* gB0 = (const uint4*)(Bhi + (size_t)bn * GK);
    const uint4* gB1 = (const uint4*)(Blo + (size_t)bn * GK);

    float d[4][4][4];
#pragma unroll
    for (int i = 0; i < 4; i++)
#pragma unroll
        for (int j = 0; j < 4; j++)
#pragma unroll
            for (int r = 0; r < 4; r++) d[i][j][r] = 0.f;

    // ---- stage loader: buffer slot b (0/1), k-chunk kt ----
    auto load_stage = [&](int b, int kt) {
        uint32_t sb = sbase + (uint32_t)b * 40960u;
#pragma unroll
        for (int j = 0; j < 8; j++) {
            int gidx = j * 256 + tid;         // 0..2047
            int term = gidx >> 9;             // 0..3 : Ahi, Alo, Bhi, Blo
            int idx = gidx & 511;             // 0..511
            int r = idx >> 2;                 // row 0..127
            int c = idx & 3;                  // uint4 col 0..3
            const uint4* src = (term == 0) ? gA0 : (term == 1) ? gA1
                             : (term == 2) ? gB0 : gB1;
            const uint4* gp = src + (size_t)r * 80 + kt * 4 + c;
            uint32_t sp = sb + (uint32_t)term * 10240u
                        + (uint32_t)(r * 80 + c * 16);
            CP16(sp, gp);
        }
        CP_COMMIT();
    };

    // ---- compute one stage from buffer slot b ----
    auto compute_stage = [&](int b) {
        uint32_t sb = sbase + (uint32_t)b * 40960u;
        const uint32_t aOff[2] = {sb, sb + 10240u};
        const uint32_t bOff[2] = {sb + 20480u, sb + 30720u};
#pragma unroll
        for (int kk = 0; kk < 2; kk++) {
            const uint32_t colB = (uint32_t)(kk * 32) + ((lane & 16) ? 16u : 0u);
            uint32_t ah[4][4], al[4][4];
#pragma unroll
            for (int mt = 0; mt < 4; mt++) {
                int row = wm * 64 + mt * 16 + (lane & 15);
                LDSM4(ah[mt], aOff[0] + (uint32_t)(row * 80) + colB);
                LDSM4(al[mt], aOff[1] + (uint32_t)(row * 80) + colB);
            }
            uint32_t bh[4][2], bl[4][2];
#pragma unroll
            for (int nt2 = 0; nt2 < 2; nt2++) {
                int row = wn * 32 + nt2 * 16 + (lane & 15);
                uint32_t r4[4];
                LDSM4(r4, bOff[0] + (uint32_t)(row * 80) + colB);
                bh[nt2 * 2 + 0][0] = r4[0]; bh[nt2 * 2 + 0][1] = r4[2];
                bh[nt2 * 2 + 1][0] = r4[1]; bh[nt2 * 2 + 1][1] = r4[3];
                LDSM4(r4, bOff[1] + (uint32_t)(row * 80) + colB);
                bl[nt2 * 2 + 0][0] = r4[0]; bl[nt2 * 2 + 0][1] = r4[2];
                bl[nt2 * 2 + 1][0] = r4[1]; bl[nt2 * 2 + 1][1] = r4[3];
            }
#pragma unroll
            for (int mt = 0; mt < 4; mt++)
#pragma unroll
                for (int nt = 0; nt < 4; nt++) {
                    MMA16816(d[mt][nt], ah[mt], bh[nt]);
                    MMA16816(d[mt][nt], ah[mt], bl[nt]);
                    MMA16816(d[mt][nt], al[mt], bh[nt]);
                }
        }
    };

    load_stage(0, 0);
    load_stage(1, 1);
    for (int s = 0; s < NST; s++) {
        if (s + 1 < NST) { CP_WAIT1(); } else { CP_WAIT0(); }
        __syncthreads();
        compute_stage(s & 1);
        __syncthreads();
        if (s + 2 < NST) load_stage(s & 1, s + 2);
    }

    // epilogue: fragment -> global with bias
#pragma unroll
    for (int mt = 0; mt < 4; mt++) {
        int row0 = bm + wm * 64 + mt * 16 + (lane >> 2);
#pragma unroll
        for (int nt = 0; nt < 4; nt++) {
            int col = bn + wn * 32 + nt * 8 + (lane & 3) * 2;
            float2 bv = *(const float2*)&bias[col];
            float2 o0 = make_float2(d[mt][nt][0] + bv.x, d[mt][nt][1] + bv.y);
            float2 o1 = make_float2(d[mt][nt][2] + bv.x, d[mt][nt][3] + bv.y);
            *(float2*)&C[(size_t)row0 * EMBED + col] = o0;
            *(float2*)&C[(size_t)(row0 + 8) * EMBED + col] = o1;
        }
    }
}

// ---------------------------------------------------------------------------
// FP32 tiled GEMM (small K/V projections)
// ---------------------------------------------------------------------------
__global__ __launch_bounds__(256, 2)
void gemm128(const float* __restrict__ A, const float* __restrict__ B,
             const float* __restrict__ bias, float* __restrict__ C,
             int M, int N, int K) {
    __shared__ float As[8][128];
    __shared__ float Bs[8][128];

    const int tid = threadIdx.x;
    const int bm = blockIdx.y * 128;
    const int bn = blockIdx.x * 128;

    const int aRow = tid >> 1;
    const int aCol = (tid & 1) * 4;
    const int bRow = tid >> 5;
    const int bCol = (tid & 31) * 4;

    const int tx = tid & 15;
    const int ty = tid >> 4;

    float c[8][8];
#pragma unroll
    for (int i = 0; i < 8; i++)
#pragma unroll
        for (int j = 0; j < 8; j++) c[i][j] = 0.0f;

    const int nK = K >> 3;
    for (int kt = 0; kt < nK; kt++) {
        int gRow = bm + aRow;
        float4 av = make_float4(0.f, 0.f, 0.f, 0.f);
        if (gRow < M)
            av = *reinterpret_cast<const float4*>(&A[(size_t)gRow * K + kt * 8 + aCol]);
        As[aCol + 0][aRow] = av.x;
        As[aCol + 1][aRow] = av.y;
        As[aCol + 2][aRow] = av.z;
        As[aCol + 3][aRow] = av.w;
        float4 bv = *reinterpret_cast<const float4*>(&B[(size_t)(kt * 8 + bRow) * N + bn + bCol]);
        *reinterpret_cast<float4*>(&Bs[bRow][bCol]) = bv;
        __syncthreads();

#pragma unroll
        for (int kk = 0; kk < 8; kk++) {
            float a[8], bb[8];
            *reinterpret_cast<float4*>(&a[0]) = *reinterpret_cast<const float4*>(&As[kk][ty * 4]);
            *reinterpret_cast<float4*>(&a[4]) = *reinterpret_cast<const float4*>(&As[kk][64 + ty * 4]);
            *reinterpret_cast<float4*>(&bb[0]) = *reinterpret_cast<const float4*>(&Bs[kk][tx * 4]);
            *reinterpret_cast<float4*>(&bb[4]) = *reinterpret_cast<const float4*>(&Bs[kk][64 + tx * 4]);
#pragma unroll
            for (int i = 0; i < 8; i++)
#pragma unroll
                for (int j = 0; j < 8; j++)
                    c[i][j] += a[i] * bb[j];
        }
        __syncthreads();
    }

#pragma unroll
    for (int ih = 0; ih < 2; ih++) {
#pragma unroll
        for (int ii = 0; ii < 4; ii++) {
            int row = bm + ih * 64 + ty * 4 + ii;
            if (row >= M) continue;
#pragma unroll
            for (int jh = 0; jh < 2; jh++) {
                int col = bn + jh * 64 + tx * 4;
                float4 r;
                r.x = c[ih * 4 + ii][jh * 4 + 0] + bias[col + 0];
                r.y = c[ih * 4 + ii][jh * 4 + 1] + bias[col + 1];
                r.z = c[ih * 4 + ii][jh * 4 + 2] + bias[col + 2];
                r.w = c[ih * 4 + ii][jh * 4 + 3] + bias[col + 3];
                *reinterpret_cast<float4*>(&C[(size_t)row * N + col]) = r;
            }
        }
    }
}

// ---------------------------------------------------------------------------
// Fused attention core (unchanged)
// ---------------------------------------------------------------------------
__global__ __launch_bounds__(256)
void attn_kernel(const float* __restrict__ q, const float* __restrict__ k,
                 const float* __restrict__ v, float* __restrict__ o) {
    extern __shared__ float sm[];
    float* ks = sm;
    float* vs = ks + SEQ_S * 80;
    float* qs = vs + SEQ_S * 80;
    float* sc = qs + 32 * 80;

    const int b = blockIdx.z;
    const int h = blockIdx.y;
    const int t0 = blockIdx.x * 32;
    const int tid = threadIdx.x;

    for (int i = tid; i < SEQ_S * 80; i += 256) {
        int s = i / 80, d = i % 80;
        size_t gi = ((size_t)(b * SEQ_S + s)) * EMBED + h * 80 + d;
        ks[i] = k[gi];
        vs[i] = v[gi];
    }
    for (int i = tid; i < 32 * 80; i += 256) {
        int t = i / 80, d = i % 80;
        qs[i] = q[((size_t)(b * SEQ_T + t0 + t)) * EMBED + h * 80 + d];
    }
    __syncthreads();

    const float scale = 0.11180339887498949f;
    for (int i = tid; i < 32 * SEQ_S; i += 256) {
        int t = i / SEQ_S, s = i % SEQ_S;
        const float4* qp = reinterpret_cast<const float4*>(&qs[t * 80]);
        const float4* kp = reinterpret_cast<const float4*>(&ks[s * 80]);
        float acc = 0.f;
#pragma unroll
        for (int d4 = 0; d4 < 20; d4++) {
            float4 a = qp[d4], c2 = kp[d4];
            acc += a.x * c2.x + a.y * c2.y + a.z * c2.z + a.w * c2.w;
        }
        sc[t * 80 + s] = acc * scale;
    }
    __syncthreads();

    const int w = tid >> 5, l = tid & 31;
    for (int r = w * 4; r < w * 4 + 4; r++) {
        float v0 = sc[r * 80 + l];
        float v1 = sc[r * 80 + 32 + l];
        float v2 = (l < 13) ? sc[r * 80 + 64 + l] : -1e30f;
        float m = fmaxf(v0, fmaxf(v1, v2));
#pragma unroll
        for (int off = 16; off; off >>= 1) m = fmaxf(m, __shfl_xor_sync(0xFFFFFFFFu, m, off));
        float e0 = __expf(v0 - m);
        float e1 = __expf(v1 - m);
        float e2 = (l < 13) ? __expf(v2 - m) : 0.f;
        float su = e0 + e1 + e2;
#pragma unroll
        for (int off = 16; off; off >>= 1) su += __shfl_xor_sync(0xFFFFFFFFu, su, off);
        float inv = 1.f / su;
        sc[r * 80 + l] = e0 * inv;
        sc[r * 80 + 32 + l] = e1 * inv;
        if (l < 13) sc[r * 80 + 64 + l] = e2 * inv;
    }
    __syncthreads();

    for (int i = tid; i < 32 * 20; i += 256) {
        int t = i / 20, d4 = i % 20;
        float4 acc = make_float4(0.f, 0.f, 0.f, 0.f);
#pragma unroll 7
        for (int s = 0; s < SEQ_S; s++) {
            float p = sc[t * 80 + s];
            float4 vv = *reinterpret_cast<const float4*>(&vs[s * 80 + d4 * 4]);
            acc.x += p * vv.x;
            acc.y += p * vv.y;
            acc.z += p * vv.z;
            acc.w += p * vv.w;
        }
        *reinterpret_cast<float4*>(&o[((size_t)(b * SEQ_T + t0 + t)) * EMBED + h * 80 + d4 * 4]) = acc;
    }
}

// ---------------------------------------------------------------------------
extern "C" void kernel_launch(void* const* d_in, const int* in_sizes, int n_in,
                              void* d_out, int out_size) {
    const float* x  = (const float*)d_in[0];
    const float* y  = (const float*)d_in[1];
    const float* Wq = (const float*)d_in[2];
    const float* bq = (const float*)d_in[3];
    const float* Wk = (const float*)d_in[4];
    const float* bk = (const float*)d_in[5];
    const float* Wv = (const float*)d_in[6];
    const float* bv = (const float*)d_in[7];
    const float* Wo = (const float*)d_in[8];
    const float* bo = (const float*)d_in[9];
    float* out = (float*)d_out;

    float *qb, *ab, *kb, *vb;
    cudaGetSymbolAddress((void**)&qb, g_q);
    cudaGetSymbolAddress((void**)&ab, g_attn);
    cudaGetSymbolAddress((void**)&kb, g_k);
    cudaGetSymbolAddress((void**)&vb, g_v);
    __nv_bfloat16 *xhi, *xlo, *wthi, *wtlo;
    cudaGetSymbolAddress((void**)&xhi, g_xhi);
    cudaGetSymbolAddress((void**)&xlo, g_xlo);
    cudaGetSymbolAddress((void**)&wthi, g_wthi);
    cudaGetSymbolAddress((void**)&wtlo, g_wtlo);

    const int smem_attn = (SEQ_S * 80 * 2 + 32 * 80 * 2) * (int)sizeof(float);
    cudaFuncSetAttribute(attn_kernel, cudaFuncAttributeMaxDynamicSharedMemorySize, smem_attn);
    const int smem_mma = 2 * 40960;  // 81920
    cudaFuncSetAttribute(gemm_mma, cudaFuncAttributeMaxDynamicSharedMemorySize, smem_mma);

    const int NX = BATCH * SEQ_T * EMBED;
    const int NW = EMBED * EMBED;

    // --- Q projection on tensor cores (bf16 3-term split) ---
    split_fp32<<<(NX + 255) / 256, 256>>>(x, xhi, xlo, NX);
    wsplit_tr<<<(NW + 255) / 256, 256>>>(Wq, wthi, wtlo);
    {
        dim3 grid(EMBED / 128, (BATCH * SEQ_T) / 128);
        gemm_mma<<<grid, 256, smem_mma>>>(xhi, xlo, wthi, wtlo, bq, qb);
    }

    // --- K/V projections (small, fp32 SIMT) ---
    {
        dim3 grid(EMBED / 128, (BATCH * SEQ_S + 127) / 128);
        gemm128<<<grid, 256>>>(y, Wk, bk, kb, BATCH * SEQ_S, EMBED, CROSS);
        gemm128<<<grid, 256>>>(y, Wv, bv, vb, BATCH * SEQ_S, EMBED, CROSS);
    }

    // --- attention ---
    {
        dim3 grid(SEQ_T / 32, N_HEADS, BATCH);
        attn_kernel<<<grid, 256, smem_attn>>>(qb, kb, vb, ab);
    }

    // --- O projection on tensor cores (bf16 3-term split) ---
    split_fp32<<<(NX + 255) / 256, 256>>>(ab, xhi, xlo, NX);
    wsplit_tr<<<(NW + 255) / 256, 256>>>(Wo, wthi, wtlo);
    {
        dim3 grid(EMBED / 128, (BATCH * SEQ_T) / 128);
        gemm_mma<<<grid, 256, smem_mma>>>(xhi, xlo, wthi, wtlo, bo, out);
    }
}

// round 5
// speedup vs baseline: 2.0626x; 1.7299x over previous
#include <cuda_runtime.h>
#include <cuda_bf16.h>
#include <cstdint>
#include <math.h>

#define N_HEADS 8
#define EMBED 640
#define CROSS 768
#define HEAD 80
#define BATCH 8
#define SEQ_T 4096
#define SEQ_S 77

// ---------------------------------------------------------------------------
// Scratch (no cudaMalloc allowed)
// ---------------------------------------------------------------------------
__device__ float g_q[BATCH * SEQ_T * EMBED];
__device__ float g_attn[BATCH * SEQ_T * EMBED];
__device__ float g_k[BATCH * SEQ_S * EMBED];
__device__ float g_v[BATCH * SEQ_S * EMBED];
__device__ __align__(16) unsigned short g_xhi[BATCH * SEQ_T * EMBED];
__device__ __align__(16) unsigned short g_xlo[BATCH * SEQ_T * EMBED];
__device__ __align__(16) unsigned short g_yhi[BATCH * SEQ_S * CROSS];
__device__ __align__(16) unsigned short g_ylo[BATCH * SEQ_S * CROSS];
__device__ __align__(16) unsigned short g_wthi[EMBED * CROSS];
__device__ __align__(16) unsigned short g_wtlo[EMBED * CROSS];

// ---------------------------------------------------------------------------
// PTX helpers (non-'a' features only: ldmatrix, mma.sync, cp.async)
// ---------------------------------------------------------------------------
__device__ __forceinline__ uint32_t smem_to_u32(const void* smem_ptr) {
    uint32_t addr;
    asm("{ .reg .u64 tmp; cvta.to.shared.u64 tmp, %1; cvt.u32.u64 %0, tmp; }"
        : "=r"(addr) : "l"(smem_ptr));
    return addr;
}

#define LDSM4(r, addr) \
    asm volatile("ldmatrix.sync.aligned.m8n8.x4.shared.b16 {%0,%1,%2,%3},[%4];" \
        : "=r"((r)[0]), "=r"((r)[1]), "=r"((r)[2]), "=r"((r)[3]) : "r"(addr))

#define MMA16816(d, a, b) \
    asm volatile("mma.sync.aligned.m16n8k16.row.col.f32.bf16.bf16.f32 " \
        "{%0,%1,%2,%3},{%4,%5,%6,%7},{%8,%9},{%0,%1,%2,%3};" \
        : "+f"((d)[0]), "+f"((d)[1]), "+f"((d)[2]), "+f"((d)[3]) \
        : "r"((a)[0]), "r"((a)[1]), "r"((a)[2]), "r"((a)[3]), \
          "r"((b)[0]), "r"((b)[1]))

#define CP16(sp, gp) \
    asm volatile("cp.async.cg.shared.global [%0],[%1],16;" :: "r"(sp), "l"(gp))
#define CP_COMMIT() asm volatile("cp.async.commit_group;")
#define CP_WAIT1()  asm volatile("cp.async.wait_group 1;")
#define CP_WAIT0()  asm volatile("cp.async.wait_group 0;")

// ---------------------------------------------------------------------------
// FP32 -> bf16 hi/lo split (elementwise)
// ---------------------------------------------------------------------------
__global__ void split_fp32(const float* __restrict__ in,
                           __nv_bfloat16* __restrict__ hi,
                           __nv_bfloat16* __restrict__ lo, int n) {
    int i = blockIdx.x * blockDim.x + threadIdx.x;
    if (i < n) {
        float v = in[i];
        __nv_bfloat16 h = __float2bfloat16(v);
        hi[i] = h;
        lo[i] = __float2bfloat16(v - __bfloat162float(h));
    }
}

// W[K,640] -> Wt[640,K] bf16 hi/lo (transpose + split), runtime K
__global__ void wsplit_tr(const float* __restrict__ W,
                          __nv_bfloat16* __restrict__ thi,
                          __nv_bfloat16* __restrict__ tlo, int K) {
    int idx = blockIdx.x * blockDim.x + threadIdx.x;
    if (idx >= EMBED * K) return;
    int n = idx / K, k = idx - n * K;
    float v = W[k * EMBED + n];
    __nv_bfloat16 h = __float2bfloat16(v);
    thi[idx] = h;
    tlo[idx] = __float2bfloat16(v - __bfloat162float(h));
}

// ---------------------------------------------------------------------------
// Tensor-core GEMM via mma.sync (bf16 3-term split, fp32 accumulate):
//   C[M,640] = A[M,K] @ W[K,640] + bias
//   A as hi/lo [M,K] bf16 K-major; W as Bt hi/lo [640,K] bf16 K-major.
//   Runtime M (bounds-checked) and K (multiple of 32, nst=K/32 stages).
// CTA tile 128x128, BK=32, 8 warps (warp tile 64x32), cp.async 2-stage pipe.
// smem rows padded to 40 bf16 (80B) -> conflict-free ldmatrix, no swizzle.
// ---------------------------------------------------------------------------
__global__ __launch_bounds__(256, 1)
void gemm_mma(const __nv_bfloat16* __restrict__ Ahi,
              const __nv_bfloat16* __restrict__ Alo,
              const __nv_bfloat16* __restrict__ Bhi,
              const __nv_bfloat16* __restrict__ Blo,
              const float* __restrict__ bias, float* __restrict__ C,
              int M, int K) {
    extern __shared__ char smem[];
    const uint32_t sbase = smem_to_u32(smem);
    const int tid = threadIdx.x;
    const int lane = tid & 31;
    const int wid = tid >> 5;
    const int wm = wid >> 2;       // 0..1  (M warp)
    const int wn = wid & 3;        // 0..3  (N warp)
    const int bm = blockIdx.y * 128;
    const int bn = blockIdx.x * 128;
    const int rowU4 = K >> 3;      // uint4 per global row
    const int nst = K >> 5;        // pipeline stages
    const int maxAr = (M - bm - 1 < 127) ? (M - bm - 1) : 127;  // clamp for A rows

    const uint4* gA0 = (const uint4*)(Ahi + (size_t)bm * K);
    const uint4* gA1 = (const uint4*)(Alo + (size_t)bm * K);
    const uint4* gB0 = (const uint4*)(Bhi + (size_t)bn * K);
    const uint4* gB1 = (const uint4*)(Blo + (size_t)bn * K);

    float d[4][4][4];
#pragma unroll
    for (int i = 0; i < 4; i++)
#pragma unroll
        for (int j = 0; j < 4; j++)
#pragma unroll
            for (int r = 0; r < 4; r++) d[i][j][r] = 0.f;

    auto load_stage = [&](int b, int kt) {
        uint32_t sb = sbase + (uint32_t)b * 40960u;
#pragma unroll
        for (int j = 0; j < 8; j++) {
            int gidx = j * 256 + tid;         // 0..2047
            int term = gidx >> 9;             // 0..3 : Ahi, Alo, Bhi, Blo
            int idx = gidx & 511;
            int r = idx >> 2;                 // row 0..127
            int c = idx & 3;                  // uint4 col 0..3
            int re = (term < 2 && r > maxAr) ? maxAr : r;  // clamp A rows
            const uint4* src = (term == 0) ? gA0 : (term == 1) ? gA1
                             : (term == 2) ? gB0 : gB1;
            const uint4* gp = src + (size_t)re * rowU4 + kt * 4 + c;
            uint32_t sp = sb + (uint32_t)term * 10240u
                        + (uint32_t)(r * 80 + c * 16);
            CP16(sp, gp);
        }
        CP_COMMIT();
    };

    auto compute_stage = [&](int b) {
        uint32_t sb = sbase + (uint32_t)b * 40960u;
        const uint32_t aOff[2] = {sb, sb + 10240u};
        const uint32_t bOff[2] = {sb + 20480u, sb + 30720u};
#pragma unroll
        for (int kk = 0; kk < 2; kk++) {
            const uint32_t colB = (uint32_t)(kk * 32) + ((lane & 16) ? 16u : 0u);
            uint32_t ah[4][4], al[4][4];
#pragma unroll
            for (int mt = 0; mt < 4; mt++) {
                int row = wm * 64 + mt * 16 + (lane & 15);
                LDSM4(ah[mt], aOff[0] + (uint32_t)(row * 80) + colB);
                LDSM4(al[mt], aOff[1] + (uint32_t)(row * 80) + colB);
            }
            uint32_t bh[4][2], bl[4][2];
#pragma unroll
            for (int nt2 = 0; nt2 < 2; nt2++) {
                int row = wn * 32 + nt2 * 16 + (lane & 15);
                uint32_t r4[4];
                LDSM4(r4, bOff[0] + (uint32_t)(row * 80) + colB);
                bh[nt2 * 2 + 0][0] = r4[0]; bh[nt2 * 2 + 0][1] = r4[2];
                bh[nt2 * 2 + 1][0] = r4[1]; bh[nt2 * 2 + 1][1] = r4[3];
                LDSM4(r4, bOff[1] + (uint32_t)(row * 80) + colB);
                bl[nt2 * 2 + 0][0] = r4[0]; bl[nt2 * 2 + 0][1] = r4[2];
                bl[nt2 * 2 + 1][0] = r4[1]; bl[nt2 * 2 + 1][1] = r4[3];
            }
#pragma unroll
            for (int mt = 0; mt < 4; mt++)
#pragma unroll
                for (int nt = 0; nt < 4; nt++) {
                    MMA16816(d[mt][nt], ah[mt], bh[nt]);
                    MMA16816(d[mt][nt], ah[mt], bl[nt]);
                    MMA16816(d[mt][nt], al[mt], bh[nt]);
                }
        }
    };

    load_stage(0, 0);
    load_stage(1, 1);
    for (int s = 0; s < nst; s++) {
        if (s + 1 < nst) { CP_WAIT1(); } else { CP_WAIT0(); }
        __syncthreads();
        compute_stage(s & 1);
        __syncthreads();
        if (s + 2 < nst) load_stage(s & 1, s + 2);
    }

#pragma unroll
    for (int mt = 0; mt < 4; mt++) {
        int row0 = bm + wm * 64 + mt * 16 + (lane >> 2);
#pragma unroll
        for (int nt = 0; nt < 4; nt++) {
            int col = bn + wn * 32 + nt * 8 + (lane & 3) * 2;
            float2 bv = *(const float2*)&bias[col];
            if (row0 < M) {
                float2 o0 = make_float2(d[mt][nt][0] + bv.x, d[mt][nt][1] + bv.y);
                *(float2*)&C[(size_t)row0 * EMBED + col] = o0;
            }
            if (row0 + 8 < M) {
                float2 o1 = make_float2(d[mt][nt][2] + bv.x, d[mt][nt][3] + bv.y);
                *(float2*)&C[(size_t)(row0 + 8) * EMBED + col] = o1;
            }
        }
    }
}

// ---------------------------------------------------------------------------
// Register-blocked fused attention: block = 64 t-rows x one (b,h).
// smem order (float4 users first, all 16B-aligned):
//   vs (stride 84, 77 rows) | qs (stride 80, 64 rows) | sc (stride 80, 64)
//   | ks (stride 81, scalar-access only) at the end.
// 256 threads (8 warps x 8 t-rows each).
// ---------------------------------------------------------------------------
#define KS_STR 81
#define VS_STR 84
__global__ __launch_bounds__(256)
void attn_kernel(const float* __restrict__ q, const float* __restrict__ k,
                 const float* __restrict__ v, float* __restrict__ o) {
    extern __shared__ float sm[];
    float* vs = sm;                        // 77*84 = 6468 floats (16B-mult rows)
    float* qs = vs + SEQ_S * VS_STR;       // 64*80 (offset 25872B, aligned)
    float* sc = qs + 64 * 80;              // 64*80
    float* ks = sc + 64 * 80;              // 77*81 (scalar access only)

    const int b = blockIdx.z;
    const int h = blockIdx.y;
    const int t0g = blockIdx.x * 64;
    const int tid = threadIdx.x;
    const int w = tid >> 5;
    const int lane = tid & 31;

    // ---- stage k, v (coalesced global reads; conflict-free smem writes) ----
    for (int i = tid; i < SEQ_S * 80; i += 256) {
        int s = i / 80, d2 = i - s * 80;
        size_t gi = ((size_t)(b * SEQ_S + s)) * EMBED + h * 80 + d2;
        ks[s * KS_STR + d2] = k[gi];
        vs[s * VS_STR + d2] = v[gi];
    }
    // ---- stage q tile (64 rows) ----
    for (int i = tid; i < 64 * 80; i += 256) {
        int t = i / 80, d2 = i - t * 80;
        qs[i] = q[((size_t)(b * SEQ_T + t0g + t)) * EMBED + h * 80 + d2];
    }
    __syncthreads();

    // ---- QK: warp w owns t rows [w*8, w*8+8); lane owns s = lane, lane+32, lane+64 ----
    const float scale = 0.11180339887498949f;  // 1/sqrt(80)
    {
        const int t0 = w * 8;
        const int s2ok = (lane < SEQ_S - 64);
        const int s2 = s2ok ? (lane + 64) : 0;
        float acc[8][3];
#pragma unroll
        for (int i = 0; i < 8; i++)
#pragma unroll
            for (int j = 0; j < 3; j++) acc[i][j] = 0.f;

        for (int d4 = 0; d4 < 20; d4++) {
            float4 q4[8];
#pragma unroll
            for (int i = 0; i < 8; i++)
                q4[i] = *(const float4*)&qs[(t0 + i) * 80 + d4 * 4];
            float k0[4], k1[4], k2[4];
#pragma unroll
            for (int c = 0; c < 4; c++) {
                k0[c] = ks[lane * KS_STR + d4 * 4 + c];
                k1[c] = ks[(lane + 32) * KS_STR + d4 * 4 + c];
                k2[c] = ks[s2 * KS_STR + d4 * 4 + c];
            }
#pragma unroll
            for (int i = 0; i < 8; i++) {
                acc[i][0] += q4[i].x * k0[0] + q4[i].y * k0[1] + q4[i].z * k0[2] + q4[i].w * k0[3];
                acc[i][1] += q4[i].x * k1[0] + q4[i].y * k1[1] + q4[i].z * k1[2] + q4[i].w * k1[3];
                acc[i][2] += q4[i].x * k2[0] + q4[i].y * k2[1] + q4[i].z * k2[2] + q4[i].w * k2[3];
            }
        }
#pragma unroll
        for (int i = 0; i < 8; i++) {
            sc[(t0 + i) * 80 + lane] = acc[i][0] * scale;
            sc[(t0 + i) * 80 + lane + 32] = acc[i][1] * scale;
            if (s2ok) sc[(t0 + i) * 80 + lane + 64] = acc[i][2] * scale;
        }
    }
    __syncthreads();

    // ---- softmax: warp w handles rows w*8 .. w*8+7 ----
    {
        const int l = lane;
#pragma unroll
        for (int i = 0; i < 8; i++) {
            int r = w * 8 + i;
            float v0 = sc[r * 80 + l];
            float v1 = sc[r * 80 + 32 + l];
            float v2 = (l < 13) ? sc[r * 80 + 64 + l] : -1e30f;
            float m = fmaxf(v0, fmaxf(v1, v2));
#pragma unroll
            for (int off = 16; off; off >>= 1) m = fmaxf(m, __shfl_xor_sync(0xFFFFFFFFu, m, off));
            float e0 = __expf(v0 - m);
            float e1 = __expf(v1 - m);
            float e2 = (l < 13) ? __expf(v2 - m) : 0.f;
            float su = e0 + e1 + e2;
#pragma unroll
            for (int off = 16; off; off >>= 1) su += __shfl_xor_sync(0xFFFFFFFFu, su, off);
            float inv = 1.f / su;
            sc[r * 80 + l] = e0 * inv;
            sc[r * 80 + 32 + l] = e1 * inv;
            if (l < 13) sc[r * 80 + 64 + l] = e2 * inv;
        }
    }
    __syncthreads();

    // ---- PV: warp w owns same 8 t-rows; lane = (t within 8) x (d-group of 5 float4) ----
    {
        const int tl = w * 8 + (lane & 7);  // local t row
        const int g = lane >> 3;            // 0..3 -> d4 chunks g*5 .. g*5+4
        float4 acc4[5];
#pragma unroll
        for (int j = 0; j < 5; j++) acc4[j] = make_float4(0.f, 0.f, 0.f, 0.f);

#pragma unroll 7
        for (int s = 0; s < SEQ_S; s++) {
            float p = sc[tl * 80 + s];
#pragma unroll
            for (int j = 0; j < 5; j++) {
                float4 v4 = *(const float4*)&vs[s * VS_STR + (g * 5 + j) * 4];
                acc4[j].x += p * v4.x;
                acc4[j].y += p * v4.y;
                acc4[j].z += p * v4.z;
                acc4[j].w += p * v4.w;
            }
        }
        float* orow = o + ((size_t)(b * SEQ_T + t0g + tl)) * EMBED + h * 80;
#pragma unroll
        for (int j = 0; j < 5; j++)
            *(float4*)&orow[(g * 5 + j) * 4] = acc4[j];
    }
}

// ---------------------------------------------------------------------------
extern "C" void kernel_launch(void* const* d_in, const int* in_sizes, int n_in,
                              void* d_out, int out_size) {
    const float* x  = (const float*)d_in[0];
    const float* y  = (const float*)d_in[1];
    const float* Wq = (const float*)d_in[2];
    const float* bq = (const float*)d_in[3];
    const float* Wk = (const float*)d_in[4];
    const float* bk = (const float*)d_in[5];
    const float* Wv = (const float*)d_in[6];
    const float* bv = (const float*)d_in[7];
    const float* Wo = (const float*)d_in[8];
    const float* bo = (const float*)d_in[9];
    float* out = (float*)d_out;

    float *qb, *ab, *kb, *vb;
    cudaGetSymbolAddress((void**)&qb, g_q);
    cudaGetSymbolAddress((void**)&ab, g_attn);
    cudaGetSymbolAddress((void**)&kb, g_k);
    cudaGetSymbolAddress((void**)&vb, g_v);
    __nv_bfloat16 *xhi, *xlo, *yhi, *ylo, *wthi, *wtlo;
    cudaGetSymbolAddress((void**)&xhi, g_xhi);
    cudaGetSymbolAddress((void**)&xlo, g_xlo);
    cudaGetSymbolAddress((void**)&yhi, g_yhi);
    cudaGetSymbolAddress((void**)&ylo, g_ylo);
    cudaGetSymbolAddress((void**)&wthi, g_wthi);
    cudaGetSymbolAddress((void**)&wtlo, g_wtlo);

    const int smem_attn = (SEQ_S * VS_STR + 64 * 80 * 2 + SEQ_S * KS_STR) * (int)sizeof(float);
    cudaFuncSetAttribute(attn_kernel, cudaFuncAttributeMaxDynamicSharedMemorySize, smem_attn);
    const int smem_mma = 2 * 40960;  // 81920
    cudaFuncSetAttribute(gemm_mma, cudaFuncAttributeMaxDynamicSharedMemorySize, smem_mma);

    const int NX = BATCH * SEQ_T * EMBED;      // 21.0M
    const int NY = BATCH * SEQ_S * CROSS;      // 473k
    const int MKV = BATCH * SEQ_S;             // 616

    // --- Q projection (tensor cores, bf16 3-term split) ---
    split_fp32<<<(NX + 255) / 256, 256>>>(x, xhi, xlo, NX);
    wsplit_tr<<<(EMBED * EMBED + 255) / 256, 256>>>(Wq, wthi, wtlo, EMBED);
    {
        dim3 grid(EMBED / 128, (BATCH * SEQ_T) / 128);
        gemm_mma<<<grid, 256, smem_mma>>>(xhi, xlo, wthi, wtlo, bq, qb, BATCH * SEQ_T, EMBED);
    }

    // --- K/V projections (tensor cores too) ---
    split_fp32<<<(NY + 255) / 256, 256>>>(y, yhi, ylo, NY);
    {
        dim3 grid(EMBED / 128, (MKV + 127) / 128);
        wsplit_tr<<<(EMBED * CROSS + 255) / 256, 256>>>(Wk, wthi, wtlo, CROSS);
        gemm_mma<<<grid, 256, smem_mma>>>(yhi, ylo, wthi, wtlo, bk, kb, MKV, CROSS);
        wsplit_tr<<<(EMBED * CROSS + 255) / 256, 256>>>(Wv, wthi, wtlo, CROSS);
        gemm_mma<<<grid, 256, smem_mma>>>(yhi, ylo, wthi, wtlo, bv, vb, MKV, CROSS);
    }

    // --- attention (register-blocked) ---
    {
        dim3 grid(SEQ_T / 64, N_HEADS, BATCH);
        attn_kernel<<<grid, 256, smem_attn>>>(qb, kb, vb, ab);
    }

    // --- O projection (tensor cores) ---
    split_fp32<<<(NX + 255) / 256, 256>>>(ab, xhi, xlo, NX);
    wsplit_tr<<<(EMBED * EMBED + 255) / 256, 256>>>(Wo, wthi, wtlo, EMBED);
    {
        dim3 grid(EMBED / 128, (BATCH * SEQ_T) / 128);
        gemm_mma<<<grid, 256, smem_mma>>>(xhi, xlo, wthi, wtlo, bo, out, BATCH * SEQ_T, EMBED);
    }
}

// round 6
// speedup vs baseline: 2.2371x; 1.0846x over previous
#include <cuda_runtime.h>
#include <cuda_bf16.h>
#include <cstdint>
#include <math.h>

#define N_HEADS 8
#define EMBED 640
#define CROSS 768
#define HEAD 80
#define BATCH 8
#define SEQ_T 4096
#define SEQ_S 77

// ---------------------------------------------------------------------------
// Scratch (no cudaMalloc allowed)
// ---------------------------------------------------------------------------
__device__ float g_q[BATCH * SEQ_T * EMBED];
__device__ float g_k[BATCH * SEQ_S * EMBED];
__device__ float g_v[BATCH * SEQ_S * EMBED];
__device__ __align__(16) unsigned short g_xhi[BATCH * SEQ_T * EMBED];
__device__ __align__(16) unsigned short g_xlo[BATCH * SEQ_T * EMBED];
__device__ __align__(16) unsigned short g_yhi[BATCH * SEQ_S * CROSS];
__device__ __align__(16) unsigned short g_ylo[BATCH * SEQ_S * CROSS];
__device__ __align__(16) unsigned short g_wthi[EMBED * CROSS];
__device__ __align__(16) unsigned short g_wtlo[EMBED * CROSS];

// ---------------------------------------------------------------------------
// PTX helpers (non-'a' features only: ldmatrix, mma.sync, cp.async)
// ---------------------------------------------------------------------------
__device__ __forceinline__ uint32_t smem_to_u32(const void* smem_ptr) {
    uint32_t addr;
    asm("{ .reg .u64 tmp; cvta.to.shared.u64 tmp, %1; cvt.u32.u64 %0, tmp; }"
        : "=r"(addr) : "l"(smem_ptr));
    return addr;
}

#define LDSM4(r, addr) \
    asm volatile("ldmatrix.sync.aligned.m8n8.x4.shared.b16 {%0,%1,%2,%3},[%4];" \
        : "=r"((r)[0]), "=r"((r)[1]), "=r"((r)[2]), "=r"((r)[3]) : "r"(addr))

#define MMA16816(d, a, b) \
    asm volatile("mma.sync.aligned.m16n8k16.row.col.f32.bf16.bf16.f32 " \
        "{%0,%1,%2,%3},{%4,%5,%6,%7},{%8,%9},{%0,%1,%2,%3};" \
        : "+f"((d)[0]), "+f"((d)[1]), "+f"((d)[2]), "+f"((d)[3]) \
        : "r"((a)[0]), "r"((a)[1]), "r"((a)[2]), "r"((a)[3]), \
          "r"((b)[0]), "r"((b)[1]))

#define CP16(sp, gp) \
    asm volatile("cp.async.cg.shared.global [%0],[%1],16;" :: "r"(sp), "l"(gp))
#define CP_COMMIT() asm volatile("cp.async.commit_group;")
#define CP_WAIT2()  asm volatile("cp.async.wait_group 2;")
#define CP_WAIT1()  asm volatile("cp.async.wait_group 1;")
#define CP_WAIT0()  asm volatile("cp.async.wait_group 0;")

__device__ __forceinline__ unsigned short bf16_hi(float f, float& rem) {
    __nv_bfloat16 h = __float2bfloat16(f);
    rem = f - __bfloat162float(h);
    return *(unsigned short*)&h;
}
__device__ __forceinline__ unsigned short bf16_of(float f) {
    __nv_bfloat16 h = __float2bfloat16(f);
    return *(unsigned short*)&h;
}

// ---------------------------------------------------------------------------
// Vectorized FP32 -> bf16 hi/lo split: 8 elements per thread
// ---------------------------------------------------------------------------
__global__ void split_fp32_v(const float4* __restrict__ in,
                             uint4* __restrict__ hi,
                             uint4* __restrict__ lo, int n8) {
    int i = blockIdx.x * blockDim.x + threadIdx.x;
    if (i >= n8) return;
    float4 a = in[2 * i];
    float4 b = in[2 * i + 1];
    float r[8];
    unsigned short h[8];
    h[0] = bf16_hi(a.x, r[0]); h[1] = bf16_hi(a.y, r[1]);
    h[2] = bf16_hi(a.z, r[2]); h[3] = bf16_hi(a.w, r[3]);
    h[4] = bf16_hi(b.x, r[4]); h[5] = bf16_hi(b.y, r[5]);
    h[6] = bf16_hi(b.z, r[6]); h[7] = bf16_hi(b.w, r[7]);
    uint4 hv, lv;
    hv.x = (uint32_t)h[0] | ((uint32_t)h[1] << 16);
    hv.y = (uint32_t)h[2] | ((uint32_t)h[3] << 16);
    hv.z = (uint32_t)h[4] | ((uint32_t)h[5] << 16);
    hv.w = (uint32_t)h[6] | ((uint32_t)h[7] << 16);
    lv.x = (uint32_t)bf16_of(r[0]) | ((uint32_t)bf16_of(r[1]) << 16);
    lv.y = (uint32_t)bf16_of(r[2]) | ((uint32_t)bf16_of(r[3]) << 16);
    lv.z = (uint32_t)bf16_of(r[4]) | ((uint32_t)bf16_of(r[5]) << 16);
    lv.w = (uint32_t)bf16_of(r[6]) | ((uint32_t)bf16_of(r[7]) << 16);
    hi[i] = hv;
    lo[i] = lv;
}

// ---------------------------------------------------------------------------
// Coalesced transpose + split: W[K,640] -> Wt hi/lo [640,K]
// 32x32 smem tiles, block (32,8). Grid (EMBED/32, K/32).
// ---------------------------------------------------------------------------
__global__ void wsplit_tr(const float* __restrict__ W,
                          unsigned short* __restrict__ thi,
                          unsigned short* __restrict__ tlo, int K) {
    __shared__ float tile[32][33];
    const int tx = threadIdx.x, ty = threadIdx.y;
    const int n0 = blockIdx.x * 32;
    const int k0 = blockIdx.y * 32;
#pragma unroll
    for (int i = 0; i < 32; i += 8)
        tile[ty + i][tx] = W[(size_t)(k0 + ty + i) * EMBED + n0 + tx];
    __syncthreads();
#pragma unroll
    for (int i = 0; i < 32; i += 8) {
        float v = tile[tx][ty + i];
        float rem;
        unsigned short h = bf16_hi(v, rem);
        size_t oi = (size_t)(n0 + ty + i) * K + k0 + tx;
        thi[oi] = h;
        tlo[oi] = bf16_of(rem);
    }
}

// ---------------------------------------------------------------------------
// Tensor-core GEMM via mma.sync (bf16 3-term split, fp32 accumulate):
//   C[M,640] = A[M,K] @ W[K,640] + bias
// CTA tile 128x128, BK=32, 8 warps (warp tile 64x32), cp.async 3-stage pipe.
// smem rows padded to 40 bf16 (80B) -> conflict-free ldmatrix, no swizzle.
// ---------------------------------------------------------------------------
#define SLOT 40960u
__global__ __launch_bounds__(256, 1)
void gemm_mma(const __nv_bfloat16* __restrict__ Ahi,
              const __nv_bfloat16* __restrict__ Alo,
              const __nv_bfloat16* __restrict__ Bhi,
              const __nv_bfloat16* __restrict__ Blo,
              const float* __restrict__ bias, float* __restrict__ C,
              int M, int K) {
    extern __shared__ char smem[];
    const uint32_t sbase = smem_to_u32(smem);
    const int tid = threadIdx.x;
    const int lane = tid & 31;
    const int wid = tid >> 5;
    const int wm = wid >> 2;
    const int wn = wid & 3;
    const int bm = blockIdx.y * 128;
    const int bn = blockIdx.x * 128;
    const int rowU4 = K >> 3;
    const int nst = K >> 5;
    const int maxAr = (M - bm - 1 < 127) ? (M - bm - 1) : 127;

    const uint4* gA0 = (const uint4*)(Ahi + (size_t)bm * K);
    const uint4* gA1 = (const uint4*)(Alo + (size_t)bm * K);
    const uint4* gB0 = (const uint4*)(Bhi + (size_t)bn * K);
    const uint4* gB1 = (const uint4*)(Blo + (size_t)bn * K);

    float d[4][4][4];
#pragma unroll
    for (int i = 0; i < 4; i++)
#pragma unroll
        for (int j = 0; j < 4; j++)
#pragma unroll
            for (int r = 0; r < 4; r++) d[i][j][r] = 0.f;

    auto load_stage = [&](int slot, int kt) {
        uint32_t sb = sbase + (uint32_t)slot * SLOT;
#pragma unroll
        for (int j = 0; j < 8; j++) {
            int gidx = j * 256 + tid;
            int term = gidx >> 9;
            int idx = gidx & 511;
            int r = idx >> 2;
            int c = idx & 3;
            int re = (term < 2 && r > maxAr) ? maxAr : r;
            const uint4* src = (term == 0) ? gA0 : (term == 1) ? gA1
                             : (term == 2) ? gB0 : gB1;
            const uint4* gp = src + (size_t)re * rowU4 + kt * 4 + c;
            uint32_t sp = sb + (uint32_t)term * 10240u
                        + (uint32_t)(r * 80 + c * 16);
            CP16(sp, gp);
        }
        CP_COMMIT();
    };

    auto compute_stage = [&](int slot) {
        uint32_t sb = sbase + (uint32_t)slot * SLOT;
        const uint32_t aOff[2] = {sb, sb + 10240u};
        const uint32_t bOff[2] = {sb + 20480u, sb + 30720u};
#pragma unroll
        for (int kk = 0; kk < 2; kk++) {
            const uint32_t colB = (uint32_t)(kk * 32) + ((lane & 16) ? 16u : 0u);
            uint32_t ah[4][4], al[4][4];
#pragma unroll
            for (int mt = 0; mt < 4; mt++) {
                int row = wm * 64 + mt * 16 + (lane & 15);
                LDSM4(ah[mt], aOff[0] + (uint32_t)(row * 80) + colB);
                LDSM4(al[mt], aOff[1] + (uint32_t)(row * 80) + colB);
            }
            uint32_t bh[4][2], bl[4][2];
#pragma unroll
            for (int nt2 = 0; nt2 < 2; nt2++) {
                int row = wn * 32 + nt2 * 16 + (lane & 15);
                uint32_t r4[4];
                LDSM4(r4, bOff[0] + (uint32_t)(row * 80) + colB);
                bh[nt2 * 2 + 0][0] = r4[0]; bh[nt2 * 2 + 0][1] = r4[2];
                bh[nt2 * 2 + 1][0] = r4[1]; bh[nt2 * 2 + 1][1] = r4[3];
                LDSM4(r4, bOff[1] + (uint32_t)(row * 80) + colB);
                bl[nt2 * 2 + 0][0] = r4[0]; bl[nt2 * 2 + 0][1] = r4[2];
                bl[nt2 * 2 + 1][0] = r4[1]; bl[nt2 * 2 + 1][1] = r4[3];
            }
#pragma unroll
            for (int mt = 0; mt < 4; mt++)
#pragma unroll
                for (int nt = 0; nt < 4; nt++) {
                    MMA16816(d[mt][nt], ah[mt], bh[nt]);
                    MMA16816(d[mt][nt], ah[mt], bl[nt]);
                    MMA16816(d[mt][nt], al[mt], bh[nt]);
                }
        }
    };

    load_stage(0, 0);
    load_stage(1, 1);
    load_stage(2, 2);
    for (int s = 0; s < nst; s++) {
        if (s + 2 < nst) { CP_WAIT2(); }
        else if (s + 1 < nst) { CP_WAIT1(); }
        else { CP_WAIT0(); }
        __syncthreads();
        compute_stage(s % 3);
        __syncthreads();
        if (s + 3 < nst) load_stage(s % 3, s + 3);
    }

#pragma unroll
    for (int mt = 0; mt < 4; mt++) {
        int row0 = bm + wm * 64 + mt * 16 + (lane >> 2);
#pragma unroll
        for (int nt = 0; nt < 4; nt++) {
            int col = bn + wn * 32 + nt * 8 + (lane & 3) * 2;
            float2 bv = *(const float2*)&bias[col];
            if (row0 < M) {
                float2 o0 = make_float2(d[mt][nt][0] + bv.x, d[mt][nt][1] + bv.y);
                *(float2*)&C[(size_t)row0 * EMBED + col] = o0;
            }
            if (row0 + 8 < M) {
                float2 o1 = make_float2(d[mt][nt][2] + bv.x, d[mt][nt][3] + bv.y);
                *(float2*)&C[(size_t)(row0 + 8) * EMBED + col] = o1;
            }
        }
    }
}

// ---------------------------------------------------------------------------
// Register-blocked fused attention: block = 64 t-rows x one (b,h).
// Output written directly as bf16 hi/lo (feeds the O-projection GEMM).
// ---------------------------------------------------------------------------
#define KS_STR 81
#define VS_STR 84
__global__ __launch_bounds__(256)
void attn_kernel(const float* __restrict__ q, const float* __restrict__ k,
                 const float* __restrict__ v,
                 unsigned short* __restrict__ ohi,
                 unsigned short* __restrict__ olo) {
    extern __shared__ float sm[];
    float* vs = sm;                        // 77*84 (16B-mult rows)
    float* qs = vs + SEQ_S * VS_STR;       // 64*80
    float* sc = qs + 64 * 80;              // 64*80
    float* ks = sc + 64 * 80;              // 77*81 (scalar access only)

    const int b = blockIdx.z;
    const int h = blockIdx.y;
    const int t0g = blockIdx.x * 64;
    const int tid = threadIdx.x;
    const int w = tid >> 5;
    const int lane = tid & 31;

    for (int i = tid; i < SEQ_S * 80; i += 256) {
        int s = i / 80, d2 = i - s * 80;
        size_t gi = ((size_t)(b * SEQ_S + s)) * EMBED + h * 80 + d2;
        ks[s * KS_STR + d2] = k[gi];
        vs[s * VS_STR + d2] = v[gi];
    }
    for (int i = tid; i < 64 * 80; i += 256) {
        int t = i / 80, d2 = i - t * 80;
        qs[i] = q[((size_t)(b * SEQ_T + t0g + t)) * EMBED + h * 80 + d2];
    }
    __syncthreads();

    const float scale = 0.11180339887498949f;  // 1/sqrt(80)
    {
        const int t0 = w * 8;
        const int s2ok = (lane < SEQ_S - 64);
        const int s2 = s2ok ? (lane + 64) : 0;
        float acc[8][3];
#pragma unroll
        for (int i = 0; i < 8; i++)
#pragma unroll
            for (int j = 0; j < 3; j++) acc[i][j] = 0.f;

        for (int d4 = 0; d4 < 20; d4++) {
            float4 q4[8];
#pragma unroll
            for (int i = 0; i < 8; i++)
                q4[i] = *(const float4*)&qs[(t0 + i) * 80 + d4 * 4];
            float k0[4], k1[4], k2[4];
#pragma unroll
            for (int c = 0; c < 4; c++) {
                k0[c] = ks[lane * KS_STR + d4 * 4 + c];
                k1[c] = ks[(lane + 32) * KS_STR + d4 * 4 + c];
                k2[c] = ks[s2 * KS_STR + d4 * 4 + c];
            }
#pragma unroll
            for (int i = 0; i < 8; i++) {
                acc[i][0] += q4[i].x * k0[0] + q4[i].y * k0[1] + q4[i].z * k0[2] + q4[i].w * k0[3];
                acc[i][1] += q4[i].x * k1[0] + q4[i].y * k1[1] + q4[i].z * k1[2] + q4[i].w * k1[3];
                acc[i][2] += q4[i].x * k2[0] + q4[i].y * k2[1] + q4[i].z * k2[2] + q4[i].w * k2[3];
            }
        }
#pragma unroll
        for (int i = 0; i < 8; i++) {
            sc[(t0 + i) * 80 + lane] = acc[i][0] * scale;
            sc[(t0 + i) * 80 + lane + 32] = acc[i][1] * scale;
            if (s2ok) sc[(t0 + i) * 80 + lane + 64] = acc[i][2] * scale;
        }
    }
    __syncthreads();

    {
        const int l = lane;
#pragma unroll
        for (int i = 0; i < 8; i++) {
            int r = w * 8 + i;
            float v0 = sc[r * 80 + l];
            float v1 = sc[r * 80 + 32 + l];
            float v2 = (l < 13) ? sc[r * 80 + 64 + l] : -1e30f;
            float m = fmaxf(v0, fmaxf(v1, v2));
#pragma unroll
            for (int off = 16; off; off >>= 1) m = fmaxf(m, __shfl_xor_sync(0xFFFFFFFFu, m, off));
            float e0 = __expf(v0 - m);
            float e1 = __expf(v1 - m);
            float e2 = (l < 13) ? __expf(v2 - m) : 0.f;
            float su = e0 + e1 + e2;
#pragma unroll
            for (int off = 16; off; off >>= 1) su += __shfl_xor_sync(0xFFFFFFFFu, su, off);
            float inv = 1.f / su;
            sc[r * 80 + l] = e0 * inv;
            sc[r * 80 + 32 + l] = e1 * inv;
            if (l < 13) sc[r * 80 + 64 + l] = e2 * inv;
        }
    }
    __syncthreads();

    {
        const int tl = w * 8 + (lane & 7);
        const int g = lane >> 3;
        float4 acc4[5];
#pragma unroll
        for (int j = 0; j < 5; j++) acc4[j] = make_float4(0.f, 0.f, 0.f, 0.f);

#pragma unroll 7
        for (int s = 0; s < SEQ_S; s++) {
            float p = sc[tl * 80 + s];
#pragma unroll
            for (int j = 0; j < 5; j++) {
                float4 v4 = *(const float4*)&vs[s * VS_STR + (g * 5 + j) * 4];
                acc4[j].x += p * v4.x;
                acc4[j].y += p * v4.y;
                acc4[j].z += p * v4.z;
                acc4[j].w += p * v4.w;
            }
        }
        size_t obase = ((size_t)(b * SEQ_T + t0g + tl)) * EMBED + h * 80;
#pragma unroll
        for (int j = 0; j < 5; j++) {
            float r0, r1, r2, r3;
            ushort4 hv, lv;
            hv.x = bf16_hi(acc4[j].x, r0);
            hv.y = bf16_hi(acc4[j].y, r1);
            hv.z = bf16_hi(acc4[j].z, r2);
            hv.w = bf16_hi(acc4[j].w, r3);
            lv.x = bf16_of(r0); lv.y = bf16_of(r1);
            lv.z = bf16_of(r2); lv.w = bf16_of(r3);
            *(ushort4*)&ohi[obase + (g * 5 + j) * 4] = hv;
            *(ushort4*)&olo[obase + (g * 5 + j) * 4] = lv;
        }
    }
}

// ---------------------------------------------------------------------------
extern "C" void kernel_launch(void* const* d_in, const int* in_sizes, int n_in,
                              void* d_out, int out_size) {
    const float* x  = (const float*)d_in[0];
    const float* y  = (const float*)d_in[1];
    const float* Wq = (const float*)d_in[2];
    const float* bq = (const float*)d_in[3];
    const float* Wk = (const float*)d_in[4];
    const float* bk = (const float*)d_in[5];
    const float* Wv = (const float*)d_in[6];
    const float* bv = (const float*)d_in[7];
    const float* Wo = (const float*)d_in[8];
    const float* bo = (const float*)d_in[9];
    float* out = (float*)d_out;

    float *qb, *kb, *vb;
    cudaGetSymbolAddress((void**)&qb, g_q);
    cudaGetSymbolAddress((void**)&kb, g_k);
    cudaGetSymbolAddress((void**)&vb, g_v);
    unsigned short *xhi, *xlo, *yhi, *ylo, *wthi, *wtlo;
    cudaGetSymbolAddress((void**)&xhi, g_xhi);
    cudaGetSymbolAddress((void**)&xlo, g_xlo);
    cudaGetSymbolAddress((void**)&yhi, g_yhi);
    cudaGetSymbolAddress((void**)&ylo, g_ylo);
    cudaGetSymbolAddress((void**)&wthi, g_wthi);
    cudaGetSymbolAddress((void**)&wtlo, g_wtlo);

    const int smem_attn = (SEQ_S * VS_STR + 64 * 80 * 2 + SEQ_S * KS_STR) * (int)sizeof(float);
    cudaFuncSetAttribute(attn_kernel, cudaFuncAttributeMaxDynamicSharedMemorySize, smem_attn);
    const int smem_mma = 3 * (int)SLOT;  // 122880
    cudaFuncSetAttribute(gemm_mma, cudaFuncAttributeMaxDynamicSharedMemorySize, smem_mma);

    const int NX = BATCH * SEQ_T * EMBED;      // 21.0M
    const int NY = BATCH * SEQ_S * CROSS;      // 473k
    const int MKV = BATCH * SEQ_S;             // 616

    // --- Q projection (tensor cores, bf16 3-term split) ---
    split_fp32_v<<<(NX / 8 + 255) / 256, 256>>>((const float4*)x, (uint4*)xhi, (uint4*)xlo, NX / 8);
    wsplit_tr<<<dim3(EMBED / 32, EMBED / 32), dim3(32, 8)>>>(Wq, wthi, wtlo, EMBED);
    {
        dim3 grid(EMBED / 128, (BATCH * SEQ_T) / 128);
        gemm_mma<<<grid, 256, smem_mma>>>((const __nv_bfloat16*)xhi, (const __nv_bfloat16*)xlo,
                                          (const __nv_bfloat16*)wthi, (const __nv_bfloat16*)wtlo,
                                          bq, qb, BATCH * SEQ_T, EMBED);
    }

    // --- K/V projections ---
    split_fp32_v<<<(NY / 8 + 255) / 256, 256>>>((const float4*)y, (uint4*)yhi, (uint4*)ylo, NY / 8);
    {
        dim3 grid(EMBED / 128, (MKV + 127) / 128);
        wsplit_tr<<<dim3(EMBED / 32, CROSS / 32), dim3(32, 8)>>>(Wk, wthi, wtlo, CROSS);
        gemm_mma<<<grid, 256, smem_mma>>>((const __nv_bfloat16*)yhi, (const __nv_bfloat16*)ylo,
                                          (const __nv_bfloat16*)wthi, (const __nv_bfloat16*)wtlo,
                                          bk, kb, MKV, CROSS);
        wsplit_tr<<<dim3(EMBED / 32, CROSS / 32), dim3(32, 8)>>>(Wv, wthi, wtlo, CROSS);
        gemm_mma<<<grid, 256, smem_mma>>>((const __nv_bfloat16*)yhi, (const __nv_bfloat16*)ylo,
                                          (const __nv_bfloat16*)wthi, (const __nv_bfloat16*)wtlo,
                                          bv, vb, MKV, CROSS);
    }

    // --- attention (writes bf16 hi/lo directly) ---
    {
        dim3 grid(SEQ_T / 64, N_HEADS, BATCH);
        attn_kernel<<<grid, 256, smem_attn>>>(qb, kb, vb, xhi, xlo);
    }

    // --- O projection ---
    wsplit_tr<<<dim3(EMBED / 32, EMBED / 32), dim3(32, 8)>>>(Wo, wthi, wtlo, EMBED);
    {
        dim3 grid(EMBED / 128, (BATCH * SEQ_T) / 128);
        gemm_mma<<<grid, 256, smem_mma>>>((const __nv_bfloat16*)xhi, (const __nv_bfloat16*)xlo,
                                          (const __nv_bfloat16*)wthi, (const __nv_bfloat16*)wtlo,
                                          bo, out, BATCH * SEQ_T, EMBED);
    }
}

// round 7
// speedup vs baseline: 2.7996x; 1.2515x over previous
#include <cuda_runtime.h>
#include <cuda_fp16.h>
#include <cstdint>
#include <math.h>

#define N_HEADS 8
#define EMBED 640
#define CROSS 768
#define HEAD 80
#define BATCH 8
#define SEQ_T 4096
#define SEQ_S 77

// ---------------------------------------------------------------------------
// Scratch (no cudaMalloc allowed)
// ---------------------------------------------------------------------------
__device__ float g_q[BATCH * SEQ_T * EMBED];
__device__ float g_k[BATCH * SEQ_S * EMBED];
__device__ float g_v[BATCH * SEQ_S * EMBED];
__device__ __align__(16) unsigned short g_xhi[BATCH * SEQ_T * EMBED];
__device__ __align__(16) unsigned short g_xlo[BATCH * SEQ_T * EMBED];
__device__ __align__(16) unsigned short g_yhi[BATCH * SEQ_S * CROSS];
__device__ __align__(16) unsigned short g_ylo[BATCH * SEQ_S * CROSS];
__device__ __align__(16) unsigned short g_wthi[EMBED * CROSS];
__device__ __align__(16) unsigned short g_wtlo[EMBED * CROSS];

// ---------------------------------------------------------------------------
// PTX helpers (non-'a' features only: ldmatrix, mma.sync, cp.async)
// ---------------------------------------------------------------------------
__device__ __forceinline__ uint32_t smem_to_u32(const void* smem_ptr) {
    uint32_t addr;
    asm("{ .reg .u64 tmp; cvta.to.shared.u64 tmp, %1; cvt.u32.u64 %0, tmp; }"
        : "=r"(addr) : "l"(smem_ptr));
    return addr;
}

#define LDSM4(r, addr) \
    asm volatile("ldmatrix.sync.aligned.m8n8.x4.shared.b16 {%0,%1,%2,%3},[%4];" \
        : "=r"((r)[0]), "=r"((r)[1]), "=r"((r)[2]), "=r"((r)[3]) : "r"(addr))

#define MMAF16(d, a, b) \
    asm volatile("mma.sync.aligned.m16n8k16.row.col.f32.f16.f16.f32 " \
        "{%0,%1,%2,%3},{%4,%5,%6,%7},{%8,%9},{%0,%1,%2,%3};" \
        : "+f"((d)[0]), "+f"((d)[1]), "+f"((d)[2]), "+f"((d)[3]) \
        : "r"((a)[0]), "r"((a)[1]), "r"((a)[2]), "r"((a)[3]), \
          "r"((b)[0]), "r"((b)[1]))

#define CP16(sp, gp) \
    asm volatile("cp.async.cg.shared.global [%0],[%1],16;" :: "r"(sp), "l"(gp))
#define CP_COMMIT() asm volatile("cp.async.commit_group;")
#define CP_WAIT3()  asm volatile("cp.async.wait_group 3;")
#define CP_WAIT2()  asm volatile("cp.async.wait_group 2;")
#define CP_WAIT1()  asm volatile("cp.async.wait_group 1;")
#define CP_WAIT0()  asm volatile("cp.async.wait_group 0;")

__device__ __forceinline__ unsigned short f16_hi(float f, float& rem) {
    __half h = __float2half_rn(f);
    rem = f - __half2float(h);
    return *(unsigned short*)&h;
}
__device__ __forceinline__ unsigned short f16_of(float f) {
    __half h = __float2half_rn(f);
    return *(unsigned short*)&h;
}

// ---------------------------------------------------------------------------
// Vectorized FP32 -> fp16 hi/lo split: 8 elements per thread
// ---------------------------------------------------------------------------
__global__ void split_fp32_v(const float4* __restrict__ in,
                             uint4* __restrict__ hi,
                             uint4* __restrict__ lo, int n8) {
    int i = blockIdx.x * blockDim.x + threadIdx.x;
    if (i >= n8) return;
    float4 a = in[2 * i];
    float4 b = in[2 * i + 1];
    float r[8];
    unsigned short h[8];
    h[0] = f16_hi(a.x, r[0]); h[1] = f16_hi(a.y, r[1]);
    h[2] = f16_hi(a.z, r[2]); h[3] = f16_hi(a.w, r[3]);
    h[4] = f16_hi(b.x, r[4]); h[5] = f16_hi(b.y, r[5]);
    h[6] = f16_hi(b.z, r[6]); h[7] = f16_hi(b.w, r[7]);
    uint4 hv, lv;
    hv.x = (uint32_t)h[0] | ((uint32_t)h[1] << 16);
    hv.y = (uint32_t)h[2] | ((uint32_t)h[3] << 16);
    hv.z = (uint32_t)h[4] | ((uint32_t)h[5] << 16);
    hv.w = (uint32_t)h[6] | ((uint32_t)h[7] << 16);
    lv.x = (uint32_t)f16_of(r[0]) | ((uint32_t)f16_of(r[1]) << 16);
    lv.y = (uint32_t)f16_of(r[2]) | ((uint32_t)f16_of(r[3]) << 16);
    lv.z = (uint32_t)f16_of(r[4]) | ((uint32_t)f16_of(r[5]) << 16);
    lv.w = (uint32_t)f16_of(r[6]) | ((uint32_t)f16_of(r[7]) << 16);
    hi[i] = hv;
    lo[i] = lv;
}

// ---------------------------------------------------------------------------
// Coalesced transpose + split: W[K,640] -> Wt hi/lo [640,K] (fp16)
// ---------------------------------------------------------------------------
__global__ void wsplit_tr(const float* __restrict__ W,
                          unsigned short* __restrict__ thi,
                          unsigned short* __restrict__ tlo, int K) {
    __shared__ float tile[32][33];
    const int tx = threadIdx.x, ty = threadIdx.y;
    const int n0 = blockIdx.x * 32;
    const int k0 = blockIdx.y * 32;
#pragma unroll
    for (int i = 0; i < 32; i += 8)
        tile[ty + i][tx] = W[(size_t)(k0 + ty + i) * EMBED + n0 + tx];
    __syncthreads();
#pragma unroll
    for (int i = 0; i < 32; i += 8) {
        float v = tile[tx][ty + i];
        float rem;
        unsigned short h = f16_hi(v, rem);
        size_t oi = (size_t)(n0 + ty + i) * K + k0 + tx;
        thi[oi] = h;
        tlo[oi] = f16_of(rem);
    }
}

// ---------------------------------------------------------------------------
// 3-term fp16 split GEMM (high precision; used for K/V projections)
//   C[M,640] = A[M,K] @ W[K,640] + bias
// CTA 128x128, BK=32, 8 warps, 3-stage cp.async pipe.
// ---------------------------------------------------------------------------
#define SLOT3 40960u
__global__ __launch_bounds__(256, 1)
void gemm_mma3(const unsigned short* __restrict__ Ahi,
               const unsigned short* __restrict__ Alo,
               const unsigned short* __restrict__ Bhi,
               const unsigned short* __restrict__ Blo,
               const float* __restrict__ bias, float* __restrict__ C,
               int M, int K) {
    extern __shared__ char smem[];
    const uint32_t sbase = smem_to_u32(smem);
    const int tid = threadIdx.x;
    const int lane = tid & 31;
    const int wid = tid >> 5;
    const int wm = wid >> 2;
    const int wn = wid & 3;
    const int bm = blockIdx.y * 128;
    const int bn = blockIdx.x * 128;
    const int rowU4 = K >> 3;
    const int nst = K >> 5;
    const int maxAr = (M - bm - 1 < 127) ? (M - bm - 1) : 127;

    const uint4* gA0 = (const uint4*)(Ahi + (size_t)bm * K);
    const uint4* gA1 = (const uint4*)(Alo + (size_t)bm * K);
    const uint4* gB0 = (const uint4*)(Bhi + (size_t)bn * K);
    const uint4* gB1 = (const uint4*)(Blo + (size_t)bn * K);

    float d[4][4][4];
#pragma unroll
    for (int i = 0; i < 4; i++)
#pragma unroll
        for (int j = 0; j < 4; j++)
#pragma unroll
            for (int r = 0; r < 4; r++) d[i][j][r] = 0.f;

    auto load_stage = [&](int slot, int kt) {
        uint32_t sb = sbase + (uint32_t)slot * SLOT3;
#pragma unroll
        for (int j = 0; j < 8; j++) {
            int gidx = j * 256 + tid;
            int term = gidx >> 9;
            int idx = gidx & 511;
            int r = idx >> 2;
            int c = idx & 3;
            int re = (term < 2 && r > maxAr) ? maxAr : r;
            const uint4* src = (term == 0) ? gA0 : (term == 1) ? gA1
                             : (term == 2) ? gB0 : gB1;
            const uint4* gp = src + (size_t)re * rowU4 + kt * 4 + c;
            uint32_t sp = sb + (uint32_t)term * 10240u
                        + (uint32_t)(r * 80 + c * 16);
            CP16(sp, gp);
        }
        CP_COMMIT();
    };

    auto compute_stage = [&](int slot) {
        uint32_t sb = sbase + (uint32_t)slot * SLOT3;
        const uint32_t aOff[2] = {sb, sb + 10240u};
        const uint32_t bOff[2] = {sb + 20480u, sb + 30720u};
#pragma unroll
        for (int kk = 0; kk < 2; kk++) {
            const uint32_t colB = (uint32_t)(kk * 32) + ((lane & 16) ? 16u : 0u);
            uint32_t ah[4][4], al[4][4];
#pragma unroll
            for (int mt = 0; mt < 4; mt++) {
                int row = wm * 64 + mt * 16 + (lane & 15);
                LDSM4(ah[mt], aOff[0] + (uint32_t)(row * 80) + colB);
                LDSM4(al[mt], aOff[1] + (uint32_t)(row * 80) + colB);
            }
            uint32_t bh[4][2], bl[4][2];
#pragma unroll
            for (int nt2 = 0; nt2 < 2; nt2++) {
                int row = wn * 32 + nt2 * 16 + (lane & 15);
                uint32_t r4[4];
                LDSM4(r4, bOff[0] + (uint32_t)(row * 80) + colB);
                bh[nt2 * 2 + 0][0] = r4[0]; bh[nt2 * 2 + 0][1] = r4[2];
                bh[nt2 * 2 + 1][0] = r4[1]; bh[nt2 * 2 + 1][1] = r4[3];
                LDSM4(r4, bOff[1] + (uint32_t)(row * 80) + colB);
                bl[nt2 * 2 + 0][0] = r4[0]; bl[nt2 * 2 + 0][1] = r4[2];
                bl[nt2 * 2 + 1][0] = r4[1]; bl[nt2 * 2 + 1][1] = r4[3];
            }
#pragma unroll
            for (int mt = 0; mt < 4; mt++)
#pragma unroll
                for (int nt = 0; nt < 4; nt++) {
                    MMAF16(d[mt][nt], ah[mt], bh[nt]);
                    MMAF16(d[mt][nt], ah[mt], bl[nt]);
                    MMAF16(d[mt][nt], al[mt], bh[nt]);
                }
        }
    };

    load_stage(0, 0);
    load_stage(1, 1);
    load_stage(2, 2);
    for (int s = 0; s < nst; s++) {
        if (s + 2 < nst) { CP_WAIT2(); }
        else if (s + 1 < nst) { CP_WAIT1(); }
        else { CP_WAIT0(); }
        __syncthreads();
        compute_stage(s % 3);
        __syncthreads();
        if (s + 3 < nst) load_stage(s % 3, s + 3);
    }

#pragma unroll
    for (int mt = 0; mt < 4; mt++) {
        int row0 = bm + wm * 64 + mt * 16 + (lane >> 2);
#pragma unroll
        for (int nt = 0; nt < 4; nt++) {
            int col = bn + wn * 32 + nt * 8 + (lane & 3) * 2;
            float2 bv = *(const float2*)&bias[col];
            if (row0 < M) {
                float2 o0 = make_float2(d[mt][nt][0] + bv.x, d[mt][nt][1] + bv.y);
                *(float2*)&C[(size_t)row0 * EMBED + col] = o0;
            }
            if (row0 + 8 < M) {
                float2 o1 = make_float2(d[mt][nt][2] + bv.x, d[mt][nt][3] + bv.y);
                *(float2*)&C[(size_t)(row0 + 8) * EMBED + col] = o1;
            }
        }
    }
}

// ---------------------------------------------------------------------------
// 2-term fp16 split GEMM (fast path; Q and O projections):
//   C = (Ah + Al) @ Bh  with A exact in fp16 hi/lo, B rounded once to fp16.
// CTA 128x128, BK=32, 8 warps, 4-stage cp.async pipe (3 tiles x 10KB/stage).
// ---------------------------------------------------------------------------
#define SLOT2 30720u
__global__ __launch_bounds__(256, 1)
void gemm_mma2(const unsigned short* __restrict__ Ahi,
               const unsigned short* __restrict__ Alo,
               const unsigned short* __restrict__ Bh,
               const float* __restrict__ bias, float* __restrict__ C,
               int M, int K) {
    extern __shared__ char smem[];
    const uint32_t sbase = smem_to_u32(smem);
    const int tid = threadIdx.x;
    const int lane = tid & 31;
    const int wid = tid >> 5;
    const int wm = wid >> 2;
    const int wn = wid & 3;
    const int bm = blockIdx.y * 128;
    const int bn = blockIdx.x * 128;
    const int rowU4 = K >> 3;
    const int nst = K >> 5;
    const int maxAr = (M - bm - 1 < 127) ? (M - bm - 1) : 127;

    const uint4* gA0 = (const uint4*)(Ahi + (size_t)bm * K);
    const uint4* gA1 = (const uint4*)(Alo + (size_t)bm * K);
    const uint4* gB0 = (const uint4*)(Bh + (size_t)bn * K);

    float d[4][4][4];
#pragma unroll
    for (int i = 0; i < 4; i++)
#pragma unroll
        for (int j = 0; j < 4; j++)
#pragma unroll
            for (int r = 0; r < 4; r++) d[i][j][r] = 0.f;

    auto load_stage = [&](int slot, int kt) {
        uint32_t sb = sbase + (uint32_t)slot * SLOT2;
#pragma unroll
        for (int j = 0; j < 6; j++) {
            int gidx = j * 256 + tid;         // 0..1535
            int term = gidx >> 9;             // 0,1,2 : Ahi, Alo, Bh
            int idx = gidx & 511;
            int r = idx >> 2;
            int c = idx & 3;
            int re = (term < 2 && r > maxAr) ? maxAr : r;
            const uint4* src = (term == 0) ? gA0 : (term == 1) ? gA1 : gB0;
            const uint4* gp = src + (size_t)re * rowU4 + kt * 4 + c;
            uint32_t sp = sb + (uint32_t)term * 10240u
                        + (uint32_t)(r * 80 + c * 16);
            CP16(sp, gp);
        }
        CP_COMMIT();
    };

    auto compute_stage = [&](int slot) {
        uint32_t sb = sbase + (uint32_t)slot * SLOT2;
        const uint32_t aOff[2] = {sb, sb + 10240u};
        const uint32_t bOff = sb + 20480u;
#pragma unroll
        for (int kk = 0; kk < 2; kk++) {
            const uint32_t colB = (uint32_t)(kk * 32) + ((lane & 16) ? 16u : 0u);
            uint32_t ah[4][4], al[4][4];
#pragma unroll
            for (int mt = 0; mt < 4; mt++) {
                int row = wm * 64 + mt * 16 + (lane & 15);
                LDSM4(ah[mt], aOff[0] + (uint32_t)(row * 80) + colB);
                LDSM4(al[mt], aOff[1] + (uint32_t)(row * 80) + colB);
            }
            uint32_t bh[4][2];
#pragma unroll
            for (int nt2 = 0; nt2 < 2; nt2++) {
                int row = wn * 32 + nt2 * 16 + (lane & 15);
                uint32_t r4[4];
                LDSM4(r4, bOff + (uint32_t)(row * 80) + colB);
                bh[nt2 * 2 + 0][0] = r4[0]; bh[nt2 * 2 + 0][1] = r4[2];
                bh[nt2 * 2 + 1][0] = r4[1]; bh[nt2 * 2 + 1][1] = r4[3];
            }
#pragma unroll
            for (int mt = 0; mt < 4; mt++)
#pragma unroll
                for (int nt = 0; nt < 4; nt++) {
                    MMAF16(d[mt][nt], ah[mt], bh[nt]);
                    MMAF16(d[mt][nt], al[mt], bh[nt]);
                }
        }
    };

    load_stage(0, 0);
    load_stage(1, 1);
    load_stage(2, 2);
    load_stage(3, 3);
    for (int s = 0; s < nst; s++) {
        if (s + 3 < nst) { CP_WAIT3(); }
        else if (s + 2 < nst) { CP_WAIT2(); }
        else if (s + 1 < nst) { CP_WAIT1(); }
        else { CP_WAIT0(); }
        __syncthreads();
        compute_stage(s & 3);
        __syncthreads();
        if (s + 4 < nst) load_stage(s & 3, s + 4);
    }

#pragma unroll
    for (int mt = 0; mt < 4; mt++) {
        int row0 = bm + wm * 64 + mt * 16 + (lane >> 2);
#pragma unroll
        for (int nt = 0; nt < 4; nt++) {
            int col = bn + wn * 32 + nt * 8 + (lane & 3) * 2;
            float2 bv = *(const float2*)&bias[col];
            if (row0 < M) {
                float2 o0 = make_float2(d[mt][nt][0] + bv.x, d[mt][nt][1] + bv.y);
                *(float2*)&C[(size_t)row0 * EMBED + col] = o0;
            }
            if (row0 + 8 < M) {
                float2 o1 = make_float2(d[mt][nt][2] + bv.x, d[mt][nt][3] + bv.y);
                *(float2*)&C[(size_t)(row0 + 8) * EMBED + col] = o1;
            }
        }
    }
}

// ---------------------------------------------------------------------------
// Register-blocked fused attention: block = 64 t-rows x one (b,h).
// Output written directly as fp16 hi/lo (feeds the O-projection GEMM).
// ---------------------------------------------------------------------------
#define KS_STR 81
#define VS_STR 84
__global__ __launch_bounds__(256)
void attn_kernel(const float* __restrict__ q, const float* __restrict__ k,
                 const float* __restrict__ v,
                 unsigned short* __restrict__ ohi,
                 unsigned short* __restrict__ olo) {
    extern __shared__ float sm[];
    float* vs = sm;                        // 77*84 (16B-mult rows)
    float* qs = vs + SEQ_S * VS_STR;       // 64*80
    float* sc = qs + 64 * 80;              // 64*80
    float* ks = sc + 64 * 80;              // 77*81 (scalar access only)

    const int b = blockIdx.z;
    const int h = blockIdx.y;
    const int t0g = blockIdx.x * 64;
    const int tid = threadIdx.x;
    const int w = tid >> 5;
    const int lane = tid & 31;

    // ---- vectorized staging ----
    for (int i = tid; i < SEQ_S * 20; i += 256) {
        int s = i / 20, c = i - s * 20;
        size_t gi = ((size_t)(b * SEQ_S + s)) * EMBED + h * 80 + c * 4;
        float4 k4 = *(const float4*)&k[gi];
        float4 v4 = *(const float4*)&v[gi];
        ks[s * KS_STR + c * 4 + 0] = k4.x;
        ks[s * KS_STR + c * 4 + 1] = k4.y;
        ks[s * KS_STR + c * 4 + 2] = k4.z;
        ks[s * KS_STR + c * 4 + 3] = k4.w;
        *(float4*)&vs[s * VS_STR + c * 4] = v4;
    }
    for (int i = tid; i < 64 * 20; i += 256) {
        int t = i / 20, c = i - t * 20;
        *(float4*)&qs[t * 80 + c * 4] =
            *(const float4*)&q[((size_t)(b * SEQ_T + t0g + t)) * EMBED + h * 80 + c * 4];
    }
    __syncthreads();

    const float scale = 0.11180339887498949f;  // 1/sqrt(80)
    {
        const int t0 = w * 8;
        const int s2ok = (lane < SEQ_S - 64);
        const int s2 = s2ok ? (lane + 64) : 0;
        float acc[8][3];
#pragma unroll
        for (int i = 0; i < 8; i++)
#pragma unroll
            for (int j = 0; j < 3; j++) acc[i][j] = 0.f;

        for (int d4 = 0; d4 < 20; d4++) {
            float4 q4[8];
#pragma unroll
            for (int i = 0; i < 8; i++)
                q4[i] = *(const float4*)&qs[(t0 + i) * 80 + d4 * 4];
            float k0[4], k1[4], k2[4];
#pragma unroll
            for (int c = 0; c < 4; c++) {
                k0[c] = ks[lane * KS_STR + d4 * 4 + c];
                k1[c] = ks[(lane + 32) * KS_STR + d4 * 4 + c];
                k2[c] = ks[s2 * KS_STR + d4 * 4 + c];
            }
#pragma unroll
            for (int i = 0; i < 8; i++) {
                acc[i][0] += q4[i].x * k0[0] + q4[i].y * k0[1] + q4[i].z * k0[2] + q4[i].w * k0[3];
                acc[i][1] += q4[i].x * k1[0] + q4[i].y * k1[1] + q4[i].z * k1[2] + q4[i].w * k1[3];
                acc[i][2] += q4[i].x * k2[0] + q4[i].y * k2[1] + q4[i].z * k2[2] + q4[i].w * k2[3];
            }
        }
#pragma unroll
        for (int i = 0; i < 8; i++) {
            sc[(t0 + i) * 80 + lane] = acc[i][0] * scale;
            sc[(t0 + i) * 80 + lane + 32] = acc[i][1] * scale;
            if (s2ok) sc[(t0 + i) * 80 + lane + 64] = acc[i][2] * scale;
        }
    }
    __syncthreads();

    {
        const int l = lane;
#pragma unroll
        for (int i = 0; i < 8; i++) {
            int r = w * 8 + i;
            float v0 = sc[r * 80 + l];
            float v1 = sc[r * 80 + 32 + l];
            float v2 = (l < 13) ? sc[r * 80 + 64 + l] : -1e30f;
            float m = fmaxf(v0, fmaxf(v1, v2));
#pragma unroll
            for (int off = 16; off; off >>= 1) m = fmaxf(m, __shfl_xor_sync(0xFFFFFFFFu, m, off));
            float e0 = __expf(v0 - m);
            float e1 = __expf(v1 - m);
            float e2 = (l < 13) ? __expf(v2 - m) : 0.f;
            float su = e0 + e1 + e2;
#pragma unroll
            for (int off = 16; off; off >>= 1) su += __shfl_xor_sync(0xFFFFFFFFu, su, off);
            float inv = 1.f / su;
            sc[r * 80 + l] = e0 * inv;
            sc[r * 80 + 32 + l] = e1 * inv;
            if (l < 13) sc[r * 80 + 64 + l] = e2 * inv;
        }
    }
    __syncthreads();

    {
        const int tl = w * 8 + (lane & 7);
        const int g = lane >> 3;
        float4 acc4[5];
#pragma unroll
        for (int j = 0; j < 5; j++) acc4[j] = make_float4(0.f, 0.f, 0.f, 0.f);

#pragma unroll 7
        for (int s = 0; s < SEQ_S; s++) {
            float p = sc[tl * 80 + s];
#pragma unroll
            for (int j = 0; j < 5; j++) {
                float4 v4 = *(const float4*)&vs[s * VS_STR + (g * 5 + j) * 4];
                acc4[j].x += p * v4.x;
                acc4[j].y += p * v4.y;
                acc4[j].z += p * v4.z;
                acc4[j].w += p * v4.w;
            }
        }
        size_t obase = ((size_t)(b * SEQ_T + t0g + tl)) * EMBED + h * 80;
#pragma unroll
        for (int j = 0; j < 5; j++) {
            float r0, r1, r2, r3;
            ushort4 hv, lv;
            hv.x = f16_hi(acc4[j].x, r0);
            hv.y = f16_hi(acc4[j].y, r1);
            hv.z = f16_hi(acc4[j].z, r2);
            hv.w = f16_hi(acc4[j].w, r3);
            lv.x = f16_of(r0); lv.y = f16_of(r1);
            lv.z = f16_of(r2); lv.w = f16_of(r3);
            *(ushort4*)&ohi[obase + (g * 5 + j) * 4] = hv;
            *(ushort4*)&olo[obase + (g * 5 + j) * 4] = lv;
        }
    }
}

// ---------------------------------------------------------------------------
extern "C" void kernel_launch(void* const* d_in, const int* in_sizes, int n_in,
                              void* d_out, int out_size) {
    const float* x  = (const float*)d_in[0];
    const float* y  = (const float*)d_in[1];
    const float* Wq = (const float*)d_in[2];
    const float* bq = (const float*)d_in[3];
    const float* Wk = (const float*)d_in[4];
    const float* bk = (const float*)d_in[5];
    const float* Wv = (const float*)d_in[6];
    const float* bv = (const float*)d_in[7];
    const float* Wo = (const float*)d_in[8];
    const float* bo = (const float*)d_in[9];
    float* out = (float*)d_out;

    float *qb, *kb, *vb;
    cudaGetSymbolAddress((void**)&qb, g_q);
    cudaGetSymbolAddress((void**)&kb, g_k);
    cudaGetSymbolAddress((void**)&vb, g_v);
    unsigned short *xhi, *xlo, *yhi, *ylo, *wthi, *wtlo;
    cudaGetSymbolAddress((void**)&xhi, g_xhi);
    cudaGetSymbolAddress((void**)&xlo, g_xlo);
    cudaGetSymbolAddress((void**)&yhi, g_yhi);
    cudaGetSymbolAddress((void**)&ylo, g_ylo);
    cudaGetSymbolAddress((void**)&wthi, g_wthi);
    cudaGetSymbolAddress((void**)&wtlo, g_wtlo);

    const int smem_attn = (SEQ_S * VS_STR + 64 * 80 * 2 + SEQ_S * KS_STR) * (int)sizeof(float);
    cudaFuncSetAttribute(attn_kernel, cudaFuncAttributeMaxDynamicSharedMemorySize, smem_attn);
    const int smem_m3 = 3 * (int)SLOT3;  // 122880
    cudaFuncSetAttribute(gemm_mma3, cudaFuncAttributeMaxDynamicSharedMemorySize, smem_m3);
    const int smem_m2 = 4 * (int)SLOT2;  // 122880
    cudaFuncSetAttribute(gemm_mma2, cudaFuncAttributeMaxDynamicSharedMemorySize, smem_m2);

    const int NX = BATCH * SEQ_T * EMBED;      // 21.0M
    const int NY = BATCH * SEQ_S * CROSS;      // 473k
    const int MKV = BATCH * SEQ_S;             // 616

    // --- Q projection (fp16 2-term) ---
    split_fp32_v<<<(NX / 8 + 255) / 256, 256>>>((const float4*)x, (uint4*)xhi, (uint4*)xlo, NX / 8);
    wsplit_tr<<<dim3(EMBED / 32, EMBED / 32), dim3(32, 8)>>>(Wq, wthi, wtlo, EMBED);
    {
        dim3 grid(EMBED / 128, (BATCH * SEQ_T) / 128);
        gemm_mma2<<<grid, 256, smem_m2>>>(xhi, xlo, wthi, bq, qb, BATCH * SEQ_T, EMBED);
    }

    // --- K/V projections (fp16 3-term, high precision for softmax inputs) ---
    split_fp32_v<<<(NY / 8 + 255) / 256, 256>>>((const float4*)y, (uint4*)yhi, (uint4*)ylo, NY / 8);
    {
        dim3 grid(EMBED / 128, (MKV + 127) / 128);
        wsplit_tr<<<dim3(EMBED / 32, CROSS / 32), dim3(32, 8)>>>(Wk, wthi, wtlo, CROSS);
        gemm_mma3<<<grid, 256, smem_m3>>>(yhi, ylo, wthi, wtlo, bk, kb, MKV, CROSS);
        wsplit_tr<<<dim3(EMBED / 32, CROSS / 32), dim3(32, 8)>>>(Wv, wthi, wtlo, CROSS);
        gemm_mma3<<<grid, 256, smem_m3>>>(yhi, ylo, wthi, wtlo, bv, vb, MKV, CROSS);
    }

    // --- attention (writes fp16 hi/lo directly) ---
    {
        dim3 grid(SEQ_T / 64, N_HEADS, BATCH);
        attn_kernel<<<grid, 256, smem_attn>>>(qb, kb, vb, xhi, xlo);
    }

    // --- O projection (fp16 2-term) ---
    wsplit_tr<<<dim3(EMBED / 32, EMBED / 32), dim3(32, 8)>>>(Wo, wthi, wtlo, EMBED);
    {
        dim3 grid(EMBED / 128, (BATCH * SEQ_T) / 128);
        gemm_mma2<<<grid, 256, smem_m2>>>(xhi, xlo, wthi, bo, out, BATCH * SEQ_T, EMBED);
    }
}

// round 8
// speedup vs baseline: 3.8661x; 1.3809x over previous
#include <cuda_runtime.h>
#include <cuda_fp16.h>
#include <cstdint>
#include <math.h>

#define N_HEADS 8
#define EMBED 640
#define CROSS 768
#define HEAD 80
#define BATCH 8
#define SEQ_T 4096
#define SEQ_S 77

// ---------------------------------------------------------------------------
// Scratch (no cudaMalloc allowed)
// ---------------------------------------------------------------------------
__device__ float g_q[BATCH * SEQ_T * EMBED];
__device__ float g_k[BATCH * SEQ_S * EMBED];
__device__ float g_v[BATCH * SEQ_S * EMBED];
__device__ __align__(16) unsigned short g_xhi[BATCH * SEQ_T * EMBED];
__device__ __align__(16) unsigned short g_yhi[BATCH * SEQ_S * CROSS];
__device__ __align__(16) unsigned short g_ylo[BATCH * SEQ_S * CROSS];
__device__ __align__(16) unsigned short g_wthi[EMBED * CROSS];
__device__ __align__(16) unsigned short g_wtlo[EMBED * CROSS];

// ---------------------------------------------------------------------------
// PTX helpers (non-'a' features only: ldmatrix, mma.sync, cp.async)
// ---------------------------------------------------------------------------
__device__ __forceinline__ uint32_t smem_to_u32(const void* smem_ptr) {
    uint32_t addr;
    asm("{ .reg .u64 tmp; cvta.to.shared.u64 tmp, %1; cvt.u32.u64 %0, tmp; }"
        : "=r"(addr) : "l"(smem_ptr));
    return addr;
}

#define LDSM4(r, addr) \
    asm volatile("ldmatrix.sync.aligned.m8n8.x4.shared.b16 {%0,%1,%2,%3},[%4];" \
        : "=r"((r)[0]), "=r"((r)[1]), "=r"((r)[2]), "=r"((r)[3]) : "r"(addr))

#define MMAF16(d, a, b) \
    asm volatile("mma.sync.aligned.m16n8k16.row.col.f32.f16.f16.f32 " \
        "{%0,%1,%2,%3},{%4,%5,%6,%7},{%8,%9},{%0,%1,%2,%3};" \
        : "+f"((d)[0]), "+f"((d)[1]), "+f"((d)[2]), "+f"((d)[3]) \
        : "r"((a)[0]), "r"((a)[1]), "r"((a)[2]), "r"((a)[3]), \
          "r"((b)[0]), "r"((b)[1]))

#define CP16(sp, gp) \
    asm volatile("cp.async.cg.shared.global [%0],[%1],16;" :: "r"(sp), "l"(gp))
#define CP_COMMIT() asm volatile("cp.async.commit_group;")
#define CP_WAIT3()  asm volatile("cp.async.wait_group 3;")
#define CP_WAIT2()  asm volatile("cp.async.wait_group 2;")
#define CP_WAIT1()  asm volatile("cp.async.wait_group 1;")
#define CP_WAIT0()  asm volatile("cp.async.wait_group 0;")

__device__ __forceinline__ unsigned short f16_hi(float f, float& rem) {
    __half h = __float2half_rn(f);
    rem = f - __half2float(h);
    return *(unsigned short*)&h;
}
__device__ __forceinline__ unsigned short f16_of(float f) {
    __half h = __float2half_rn(f);
    return *(unsigned short*)&h;
}

// ---------------------------------------------------------------------------
// Vectorized FP32 -> fp16 convert (hi only): 8 elements per thread
// ---------------------------------------------------------------------------
__global__ void conv_fp16_v(const float4* __restrict__ in,
                            uint4* __restrict__ hi, int n8) {
    int i = blockIdx.x * blockDim.x + threadIdx.x;
    if (i >= n8) return;
    float4 a = in[2 * i];
    float4 b = in[2 * i + 1];
    uint4 hv;
    hv.x = (uint32_t)f16_of(a.x) | ((uint32_t)f16_of(a.y) << 16);
    hv.y = (uint32_t)f16_of(a.z) | ((uint32_t)f16_of(a.w) << 16);
    hv.z = (uint32_t)f16_of(b.x) | ((uint32_t)f16_of(b.y) << 16);
    hv.w = (uint32_t)f16_of(b.z) | ((uint32_t)f16_of(b.w) << 16);
    hi[i] = hv;
}

// Vectorized FP32 -> fp16 hi/lo split: 8 elements per thread (K/V inputs)
__global__ void split_fp32_v(const float4* __restrict__ in,
                             uint4* __restrict__ hi,
                             uint4* __restrict__ lo, int n8) {
    int i = blockIdx.x * blockDim.x + threadIdx.x;
    if (i >= n8) return;
    float4 a = in[2 * i];
    float4 b = in[2 * i + 1];
    float r[8];
    unsigned short h[8];
    h[0] = f16_hi(a.x, r[0]); h[1] = f16_hi(a.y, r[1]);
    h[2] = f16_hi(a.z, r[2]); h[3] = f16_hi(a.w, r[3]);
    h[4] = f16_hi(b.x, r[4]); h[5] = f16_hi(b.y, r[5]);
    h[6] = f16_hi(b.z, r[6]); h[7] = f16_hi(b.w, r[7]);
    uint4 hv, lv;
    hv.x = (uint32_t)h[0] | ((uint32_t)h[1] << 16);
    hv.y = (uint32_t)h[2] | ((uint32_t)h[3] << 16);
    hv.z = (uint32_t)h[4] | ((uint32_t)h[5] << 16);
    hv.w = (uint32_t)h[6] | ((uint32_t)h[7] << 16);
    lv.x = (uint32_t)f16_of(r[0]) | ((uint32_t)f16_of(r[1]) << 16);
    lv.y = (uint32_t)f16_of(r[2]) | ((uint32_t)f16_of(r[3]) << 16);
    lv.z = (uint32_t)f16_of(r[4]) | ((uint32_t)f16_of(r[5]) << 16);
    lv.w = (uint32_t)f16_of(r[6]) | ((uint32_t)f16_of(r[7]) << 16);
    hi[i] = hv;
    lo[i] = lv;
}

// ---------------------------------------------------------------------------
// Coalesced transpose + convert (hi only): W[K,640] -> Wt [640,K] fp16
// ---------------------------------------------------------------------------
__global__ void wconv_tr(const float* __restrict__ W,
                         unsigned short* __restrict__ thi, int K) {
    __shared__ float tile[32][33];
    const int tx = threadIdx.x, ty = threadIdx.y;
    const int n0 = blockIdx.x * 32;
    const int k0 = blockIdx.y * 32;
#pragma unroll
    for (int i = 0; i < 32; i += 8)
        tile[ty + i][tx] = W[(size_t)(k0 + ty + i) * EMBED + n0 + tx];
    __syncthreads();
#pragma unroll
    for (int i = 0; i < 32; i += 8) {
        size_t oi = (size_t)(n0 + ty + i) * K + k0 + tx;
        thi[oi] = f16_of(tile[tx][ty + i]);
    }
}

// Transpose + hi/lo split (for Wk, Wv)
__global__ void wsplit_tr(const float* __restrict__ W,
                          unsigned short* __restrict__ thi,
                          unsigned short* __restrict__ tlo, int K) {
    __shared__ float tile[32][33];
    const int tx = threadIdx.x, ty = threadIdx.y;
    const int n0 = blockIdx.x * 32;
    const int k0 = blockIdx.y * 32;
#pragma unroll
    for (int i = 0; i < 32; i += 8)
        tile[ty + i][tx] = W[(size_t)(k0 + ty + i) * EMBED + n0 + tx];
    __syncthreads();
#pragma unroll
    for (int i = 0; i < 32; i += 8) {
        float v = tile[tx][ty + i];
        float rem;
        unsigned short h = f16_hi(v, rem);
        size_t oi = (size_t)(n0 + ty + i) * K + k0 + tx;
        thi[oi] = h;
        tlo[oi] = f16_of(rem);
    }
}

// ---------------------------------------------------------------------------
// 3-term fp16 split GEMM (high precision; K/V projections)
// ---------------------------------------------------------------------------
#define SLOT3 40960u
__global__ __launch_bounds__(256, 1)
void gemm_mma3(const unsigned short* __restrict__ Ahi,
               const unsigned short* __restrict__ Alo,
               const unsigned short* __restrict__ Bhi,
               const unsigned short* __restrict__ Blo,
               const float* __restrict__ bias, float* __restrict__ C,
               int M, int K) {
    extern __shared__ char smem[];
    const uint32_t sbase = smem_to_u32(smem);
    const int tid = threadIdx.x;
    const int lane = tid & 31;
    const int wid = tid >> 5;
    const int wm = wid >> 2;
    const int wn = wid & 3;
    const int bm = blockIdx.y * 128;
    const int bn = blockIdx.x * 128;
    const int rowU4 = K >> 3;
    const int nst = K >> 5;
    const int maxAr = (M - bm - 1 < 127) ? (M - bm - 1) : 127;

    const uint4* gA0 = (const uint4*)(Ahi + (size_t)bm * K);
    const uint4* gA1 = (const uint4*)(Alo + (size_t)bm * K);
    const uint4* gB0 = (const uint4*)(Bhi + (size_t)bn * K);
    const uint4* gB1 = (const uint4*)(Blo + (size_t)bn * K);

    float d[4][4][4];
#pragma unroll
    for (int i = 0; i < 4; i++)
#pragma unroll
        for (int j = 0; j < 4; j++)
#pragma unroll
            for (int r = 0; r < 4; r++) d[i][j][r] = 0.f;

    auto load_stage = [&](int slot, int kt) {
        uint32_t sb = sbase + (uint32_t)slot * SLOT3;
#pragma unroll
        for (int j = 0; j < 8; j++) {
            int gidx = j * 256 + tid;
            int term = gidx >> 9;
            int idx = gidx & 511;
            int r = idx >> 2;
            int c = idx & 3;
            int re = (term < 2 && r > maxAr) ? maxAr : r;
            const uint4* src = (term == 0) ? gA0 : (term == 1) ? gA1
                             : (term == 2) ? gB0 : gB1;
            const uint4* gp = src + (size_t)re * rowU4 + kt * 4 + c;
            uint32_t sp = sb + (uint32_t)term * 10240u
                        + (uint32_t)(r * 80 + c * 16);
            CP16(sp, gp);
        }
        CP_COMMIT();
    };

    auto compute_stage = [&](int slot) {
        uint32_t sb = sbase + (uint32_t)slot * SLOT3;
        const uint32_t aOff[2] = {sb, sb + 10240u};
        const uint32_t bOff[2] = {sb + 20480u, sb + 30720u};
#pragma unroll
        for (int kk = 0; kk < 2; kk++) {
            const uint32_t colB = (uint32_t)(kk * 32) + ((lane & 16) ? 16u : 0u);
            uint32_t ah[4][4], al[4][4];
#pragma unroll
            for (int mt = 0; mt < 4; mt++) {
                int row = wm * 64 + mt * 16 + (lane & 15);
                LDSM4(ah[mt], aOff[0] + (uint32_t)(row * 80) + colB);
                LDSM4(al[mt], aOff[1] + (uint32_t)(row * 80) + colB);
            }
            uint32_t bh[4][2], bl[4][2];
#pragma unroll
            for (int nt2 = 0; nt2 < 2; nt2++) {
                int row = wn * 32 + nt2 * 16 + (lane & 15);
                uint32_t r4[4];
                LDSM4(r4, bOff[0] + (uint32_t)(row * 80) + colB);
                bh[nt2 * 2 + 0][0] = r4[0]; bh[nt2 * 2 + 0][1] = r4[2];
                bh[nt2 * 2 + 1][0] = r4[1]; bh[nt2 * 2 + 1][1] = r4[3];
                LDSM4(r4, bOff[1] + (uint32_t)(row * 80) + colB);
                bl[nt2 * 2 + 0][0] = r4[0]; bl[nt2 * 2 + 0][1] = r4[2];
                bl[nt2 * 2 + 1][0] = r4[1]; bl[nt2 * 2 + 1][1] = r4[3];
            }
#pragma unroll
            for (int mt = 0; mt < 4; mt++)
#pragma unroll
                for (int nt = 0; nt < 4; nt++) {
                    MMAF16(d[mt][nt], ah[mt], bh[nt]);
                    MMAF16(d[mt][nt], ah[mt], bl[nt]);
                    MMAF16(d[mt][nt], al[mt], bh[nt]);
                }
        }
    };

    load_stage(0, 0);
    load_stage(1, 1);
    load_stage(2, 2);
    for (int s = 0; s < nst; s++) {
        if (s + 2 < nst) { CP_WAIT2(); }
        else if (s + 1 < nst) { CP_WAIT1(); }
        else { CP_WAIT0(); }
        __syncthreads();
        compute_stage(s % 3);
        __syncthreads();
        if (s + 3 < nst) load_stage(s % 3, s + 3);
    }

#pragma unroll
    for (int mt = 0; mt < 4; mt++) {
        int row0 = bm + wm * 64 + mt * 16 + (lane >> 2);
#pragma unroll
        for (int nt = 0; nt < 4; nt++) {
            int col = bn + wn * 32 + nt * 8 + (lane & 3) * 2;
            float2 bv = *(const float2*)&bias[col];
            if (row0 < M) {
                float2 o0 = make_float2(d[mt][nt][0] + bv.x, d[mt][nt][1] + bv.y);
                *(float2*)&C[(size_t)row0 * EMBED + col] = o0;
            }
            if (row0 + 8 < M) {
                float2 o1 = make_float2(d[mt][nt][2] + bv.x, d[mt][nt][3] + bv.y);
                *(float2*)&C[(size_t)(row0 + 8) * EMBED + col] = o1;
            }
        }
    }
}

// ---------------------------------------------------------------------------
// 1-term fp16 GEMM (fast path; Q and O projections): C = Ah @ Bh + bias
// CTA 128x128, BK=32, 8 warps, 4-stage cp.async pipe (2 tiles x 10KB/stage).
// ---------------------------------------------------------------------------
#define SLOT1 20480u
__global__ __launch_bounds__(256, 1)
void gemm_mma1(const unsigned short* __restrict__ Ah,
               const unsigned short* __restrict__ Bh,
               const float* __restrict__ bias, float* __restrict__ C,
               int M, int K) {
    extern __shared__ char smem[];
    const uint32_t sbase = smem_to_u32(smem);
    const int tid = threadIdx.x;
    const int lane = tid & 31;
    const int wid = tid >> 5;
    const int wm = wid >> 2;
    const int wn = wid & 3;
    const int bm = blockIdx.y * 128;
    const int bn = blockIdx.x * 128;
    const int rowU4 = K >> 3;
    const int nst = K >> 5;
    const int maxAr = (M - bm - 1 < 127) ? (M - bm - 1) : 127;

    const uint4* gA0 = (const uint4*)(Ah + (size_t)bm * K);
    const uint4* gB0 = (const uint4*)(Bh + (size_t)bn * K);

    float d[4][4][4];
#pragma unroll
    for (int i = 0; i < 4; i++)
#pragma unroll
        for (int j = 0; j < 4; j++)
#pragma unroll
            for (int r = 0; r < 4; r++) d[i][j][r] = 0.f;

    auto load_stage = [&](int slot, int kt) {
        uint32_t sb = sbase + (uint32_t)slot * SLOT1;
#pragma unroll
        for (int j = 0; j < 4; j++) {
            int gidx = j * 256 + tid;         // 0..1023
            int term = gidx >> 9;             // 0,1 : Ah, Bh
            int idx = gidx & 511;
            int r = idx >> 2;
            int c = idx & 3;
            int re = (term == 0 && r > maxAr) ? maxAr : r;
            const uint4* src = (term == 0) ? gA0 : gB0;
            const uint4* gp = src + (size_t)re * rowU4 + kt * 4 + c;
            uint32_t sp = sb + (uint32_t)term * 10240u
                        + (uint32_t)(r * 80 + c * 16);
            CP16(sp, gp);
        }
        CP_COMMIT();
    };

    auto compute_stage = [&](int slot) {
        uint32_t sb = sbase + (uint32_t)slot * SLOT1;
        const uint32_t aOff = sb;
        const uint32_t bOff = sb + 10240u;
#pragma unroll
        for (int kk = 0; kk < 2; kk++) {
            const uint32_t colB = (uint32_t)(kk * 32) + ((lane & 16) ? 16u : 0u);
            uint32_t ah[4][4];
#pragma unroll
            for (int mt = 0; mt < 4; mt++) {
                int row = wm * 64 + mt * 16 + (lane & 15);
                LDSM4(ah[mt], aOff + (uint32_t)(row * 80) + colB);
            }
            uint32_t bh[4][2];
#pragma unroll
            for (int nt2 = 0; nt2 < 2; nt2++) {
                int row = wn * 32 + nt2 * 16 + (lane & 15);
                uint32_t r4[4];
                LDSM4(r4, bOff + (uint32_t)(row * 80) + colB);
                bh[nt2 * 2 + 0][0] = r4[0]; bh[nt2 * 2 + 0][1] = r4[2];
                bh[nt2 * 2 + 1][0] = r4[1]; bh[nt2 * 2 + 1][1] = r4[3];
            }
#pragma unroll
            for (int mt = 0; mt < 4; mt++)
#pragma unroll
                for (int nt = 0; nt < 4; nt++)
                    MMAF16(d[mt][nt], ah[mt], bh[nt]);
        }
    };

    load_stage(0, 0);
    load_stage(1, 1);
    load_stage(2, 2);
    load_stage(3, 3);
    for (int s = 0; s < nst; s++) {
        if (s + 3 < nst) { CP_WAIT3(); }
        else if (s + 2 < nst) { CP_WAIT2(); }
        else if (s + 1 < nst) { CP_WAIT1(); }
        else { CP_WAIT0(); }
        __syncthreads();
        compute_stage(s & 3);
        __syncthreads();
        if (s + 4 < nst) load_stage(s & 3, s + 4);
    }

#pragma unroll
    for (int mt = 0; mt < 4; mt++) {
        int row0 = bm + wm * 64 + mt * 16 + (lane >> 2);
#pragma unroll
        for (int nt = 0; nt < 4; nt++) {
            int col = bn + wn * 32 + nt * 8 + (lane & 3) * 2;
            float2 bv = *(const float2*)&bias[col];
            if (row0 < M) {
                float2 o0 = make_float2(d[mt][nt][0] + bv.x, d[mt][nt][1] + bv.y);
                *(float2*)&C[(size_t)row0 * EMBED + col] = o0;
            }
            if (row0 + 8 < M) {
                float2 o1 = make_float2(d[mt][nt][2] + bv.x, d[mt][nt][3] + bv.y);
                *(float2*)&C[(size_t)(row0 + 8) * EMBED + col] = o1;
            }
        }
    }
}

// ---------------------------------------------------------------------------
// Register-blocked fused attention: block = 64 t-rows x one (b,h).
// Output written directly as fp16 (hi only; feeds 1-term O-projection).
// ---------------------------------------------------------------------------
#define KS_STR 81
#define VS_STR 84
__global__ __launch_bounds__(256)
void attn_kernel(const float* __restrict__ q, const float* __restrict__ k,
                 const float* __restrict__ v,
                 unsigned short* __restrict__ ohi) {
    extern __shared__ float sm[];
    float* vs = sm;                        // 77*84 (16B-mult rows)
    float* qs = vs + SEQ_S * VS_STR;       // 64*80
    float* sc = qs + 64 * 80;              // 64*80
    float* ks = sc + 64 * 80;              // 77*81 (scalar access only)

    const int b = blockIdx.z;
    const int h = blockIdx.y;
    const int t0g = blockIdx.x * 64;
    const int tid = threadIdx.x;
    const int w = tid >> 5;
    const int lane = tid & 31;

    for (int i = tid; i < SEQ_S * 20; i += 256) {
        int s = i / 20, c = i - s * 20;
        size_t gi = ((size_t)(b * SEQ_S + s)) * EMBED + h * 80 + c * 4;
        float4 k4 = *(const float4*)&k[gi];
        float4 v4 = *(const float4*)&v[gi];
        ks[s * KS_STR + c * 4 + 0] = k4.x;
        ks[s * KS_STR + c * 4 + 1] = k4.y;
        ks[s * KS_STR + c * 4 + 2] = k4.z;
        ks[s * KS_STR + c * 4 + 3] = k4.w;
        *(float4*)&vs[s * VS_STR + c * 4] = v4;
    }
    for (int i = tid; i < 64 * 20; i += 256) {
        int t = i / 20, c = i - t * 20;
        *(float4*)&qs[t * 80 + c * 4] =
            *(const float4*)&q[((size_t)(b * SEQ_T + t0g + t)) * EMBED + h * 80 + c * 4];
    }
    __syncthreads();

    const float scale = 0.11180339887498949f;  // 1/sqrt(80)
    {
        const int t0 = w * 8;
        const int s2ok = (lane < SEQ_S - 64);
        const int s2 = s2ok ? (lane + 64) : 0;
        float acc[8][3];
#pragma unroll
        for (int i = 0; i < 8; i++)
#pragma unroll
            for (int j = 0; j < 3; j++) acc[i][j] = 0.f;

        for (int d4 = 0; d4 < 20; d4++) {
            float4 q4[8];
#pragma unroll
            for (int i = 0; i < 8; i++)
                q4[i] = *(const float4*)&qs[(t0 + i) * 80 + d4 * 4];
            float k0[4], k1[4], k2[4];
#pragma unroll
            for (int c = 0; c < 4; c++) {
                k0[c] = ks[lane * KS_STR + d4 * 4 + c];
                k1[c] = ks[(lane + 32) * KS_STR + d4 * 4 + c];
                k2[c] = ks[s2 * KS_STR + d4 * 4 + c];
            }
#pragma unroll
            for (int i = 0; i < 8; i++) {
                acc[i][0] += q4[i].x * k0[0] + q4[i].y * k0[1] + q4[i].z * k0[2] + q4[i].w * k0[3];
                acc[i][1] += q4[i].x * k1[0] + q4[i].y * k1[1] + q4[i].z * k1[2] + q4[i].w * k1[3];
                acc[i][2] += q4[i].x * k2[0] + q4[i].y * k2[1] + q4[i].z * k2[2] + q4[i].w * k2[3];
            }
        }
#pragma unroll
        for (int i = 0; i < 8; i++) {
            sc[(t0 + i) * 80 + lane] = acc[i][0] * scale;
            sc[(t0 + i) * 80 + lane + 32] = acc[i][1] * scale;
            if (s2ok) sc[(t0 + i) * 80 + lane + 64] = acc[i][2] * scale;
        }
    }
    __syncthreads();

    {
        const int l = lane;
#pragma unroll
        for (int i = 0; i < 8; i++) {
            int r = w * 8 + i;
            float v0 = sc[r * 80 + l];
            float v1 = sc[r * 80 + 32 + l];
            float v2 = (l < 13) ? sc[r * 80 + 64 + l] : -1e30f;
            float m = fmaxf(v0, fmaxf(v1, v2));
#pragma unroll
            for (int off = 16; off; off >>= 1) m = fmaxf(m, __shfl_xor_sync(0xFFFFFFFFu, m, off));
            float e0 = __expf(v0 - m);
            float e1 = __expf(v1 - m);
            float e2 = (l < 13) ? __expf(v2 - m) : 0.f;
            float su = e0 + e1 + e2;
#pragma unroll
            for (int off = 16; off; off >>= 1) su += __shfl_xor_sync(0xFFFFFFFFu, su, off);
            float inv = 1.f / su;
            sc[r * 80 + l] = e0 * inv;
            sc[r * 80 + 32 + l] = e1 * inv;
            if (l < 13) sc[r * 80 + 64 + l] = e2 * inv;
        }
    }
    __syncthreads();

    {
        const int tl = w * 8 + (lane & 7);
        const int g = lane >> 3;
        float4 acc4[5];
#pragma unroll
        for (int j = 0; j < 5; j++) acc4[j] = make_float4(0.f, 0.f, 0.f, 0.f);

#pragma unroll 7
        for (int s = 0; s < SEQ_S; s++) {
            float p = sc[tl * 80 + s];
#pragma unroll
            for (int j = 0; j < 5; j++) {
                float4 v4 = *(const float4*)&vs[s * VS_STR + (g * 5 + j) * 4];
                acc4[j].x += p * v4.x;
                acc4[j].y += p * v4.y;
                acc4[j].z += p * v4.z;
                acc4[j].w += p * v4.w;
            }
        }
        size_t obase = ((size_t)(b * SEQ_T + t0g + tl)) * EMBED + h * 80;
#pragma unroll
        for (int j = 0; j < 5; j++) {
            ushort4 hv;
            hv.x = f16_of(acc4[j].x);
            hv.y = f16_of(acc4[j].y);
            hv.z = f16_of(acc4[j].z);
            hv.w = f16_of(acc4[j].w);
            *(ushort4*)&ohi[obase + (g * 5 + j) * 4] = hv;
        }
    }
}

// ---------------------------------------------------------------------------
extern "C" void kernel_launch(void* const* d_in, const int* in_sizes, int n_in,
                              void* d_out, int out_size) {
    const float* x  = (const float*)d_in[0];
    const float* y  = (const float*)d_in[1];
    const float* Wq = (const float*)d_in[2];
    const float* bq = (const float*)d_in[3];
    const float* Wk = (const float*)d_in[4];
    const float* bk = (const float*)d_in[5];
    const float* Wv = (const float*)d_in[6];
    const float* bv = (const float*)d_in[7];
    const float* Wo = (const float*)d_in[8];
    const float* bo = (const float*)d_in[9];
    float* out = (float*)d_out;

    float *qb, *kb, *vb;
    cudaGetSymbolAddress((void**)&qb, g_q);
    cudaGetSymbolAddress((void**)&kb, g_k);
    cudaGetSymbolAddress((void**)&vb, g_v);
    unsigned short *xhi, *yhi, *ylo, *wthi, *wtlo;
    cudaGetSymbolAddress((void**)&xhi, g_xhi);
    cudaGetSymbolAddress((void**)&yhi, g_yhi);
    cudaGetSymbolAddress((void**)&ylo, g_ylo);
    cudaGetSymbolAddress((void**)&wthi, g_wthi);
    cudaGetSymbolAddress((void**)&wtlo, g_wtlo);

    const int smem_attn = (SEQ_S * VS_STR + 64 * 80 * 2 + SEQ_S * KS_STR) * (int)sizeof(float);
    cudaFuncSetAttribute(attn_kernel, cudaFuncAttributeMaxDynamicSharedMemorySize, smem_attn);
    const int smem_m3 = 3 * (int)SLOT3;  // 122880
    cudaFuncSetAttribute(gemm_mma3, cudaFuncAttributeMaxDynamicSharedMemorySize, smem_m3);
    const int smem_m1 = 4 * (int)SLOT1;  // 81920
    cudaFuncSetAttribute(gemm_mma1, cudaFuncAttributeMaxDynamicSharedMemorySize, smem_m1);

    const int NX = BATCH * SEQ_T * EMBED;      // 21.0M
    const int NY = BATCH * SEQ_S * CROSS;      // 473k
    const int MKV = BATCH * SEQ_S;             // 616

    // --- Q projection (fp16 1-term) ---
    conv_fp16_v<<<(NX / 8 + 255) / 256, 256>>>((const float4*)x, (uint4*)xhi, NX / 8);
    wconv_tr<<<dim3(EMBED / 32, EMBED / 32), dim3(32, 8)>>>(Wq, wthi, EMBED);
    {
        dim3 grid(EMBED / 128, (BATCH * SEQ_T) / 128);
        gemm_mma1<<<grid, 256, smem_m1>>>(xhi, wthi, bq, qb, BATCH * SEQ_T, EMBED);
    }

    // --- K/V projections (fp16 3-term, high precision for softmax inputs) ---
    split_fp32_v<<<(NY / 8 + 255) / 256, 256>>>((const float4*)y, (uint4*)yhi, (uint4*)ylo, NY / 8);
    {
        dim3 grid(EMBED / 128, (MKV + 127) / 128);
        wsplit_tr<<<dim3(EMBED / 32, CROSS / 32), dim3(32, 8)>>>(Wk, wthi, wtlo, CROSS);
        gemm_mma3<<<grid, 256, smem_m3>>>(yhi, ylo, wthi, wtlo, bk, kb, MKV, CROSS);
        wsplit_tr<<<dim3(EMBED / 32, CROSS / 32), dim3(32, 8)>>>(Wv, wthi, wtlo, CROSS);
        gemm_mma3<<<grid, 256, smem_m3>>>(yhi, ylo, wthi, wtlo, bv, vb, MKV, CROSS);
    }

    // --- attention (writes fp16 hi directly) ---
    {
        dim3 grid(SEQ_T / 64, N_HEADS, BATCH);
        attn_kernel<<<grid, 256, smem_attn>>>(qb, kb, vb, xhi);
    }

    // --- O projection (fp16 1-term) ---
    wconv_tr<<<dim3(EMBED / 32, EMBED / 32), dim3(32, 8)>>>(Wo, wthi, EMBED);
    {
        dim3 grid(EMBED / 128, (BATCH * SEQ_T) / 128);
        gemm_mma1<<<grid, 256, smem_m1>>>(xhi, wthi, bo, out, BATCH * SEQ_T, EMBED);
    }
}

// round 10
// speedup vs baseline: 5.4352x; 1.4059x over previous
#include <cuda_runtime.h>
#include <cuda_fp16.h>
#include <cstdint>
#include <math.h>

#define N_HEADS 8
#define EMBED 640
#define CROSS 768
#define HEAD 80
#define BATCH 8
#define SEQ_T 4096
#define SEQ_S 77

// ---------------------------------------------------------------------------
// Scratch (no cudaMalloc allowed)
// ---------------------------------------------------------------------------
__device__ __align__(16) unsigned short g_xhi[BATCH * SEQ_T * EMBED];  // x fp16 / attn-out fp16
__device__ __align__(16) unsigned short g_qhi[BATCH * SEQ_T * EMBED];  // scaled q hi
__device__ __align__(16) unsigned short g_qlo[BATCH * SEQ_T * EMBED];  // scaled q lo
__device__ __align__(16) unsigned short g_khi[BATCH * SEQ_S * EMBED];
__device__ __align__(16) unsigned short g_vhi[BATCH * SEQ_S * EMBED];
__device__ __align__(16) unsigned short g_yhi[BATCH * SEQ_S * CROSS];
__device__ __align__(16) unsigned short g_ylo[BATCH * SEQ_S * CROSS];
__device__ __align__(16) unsigned short g_wthi[EMBED * CROSS];
__device__ __align__(16) unsigned short g_wtlo[EMBED * CROSS];

// ---------------------------------------------------------------------------
// PTX helpers (non-'a' features only: ldmatrix, mma.sync, cp.async)
// ---------------------------------------------------------------------------
__device__ __forceinline__ uint32_t smem_to_u32(const void* smem_ptr) {
    uint32_t addr;
    asm("{ .reg .u64 tmp; cvta.to.shared.u64 tmp, %1; cvt.u32.u64 %0, tmp; }"
        : "=r"(addr) : "l"(smem_ptr));
    return addr;
}

#define LDSM4(r, addr) \
    asm volatile("ldmatrix.sync.aligned.m8n8.x4.shared.b16 {%0,%1,%2,%3},[%4];" \
        : "=r"((r)[0]), "=r"((r)[1]), "=r"((r)[2]), "=r"((r)[3]) : "r"(addr))

#define MMAF16(d, a, b) \
    asm volatile("mma.sync.aligned.m16n8k16.row.col.f32.f16.f16.f32 " \
        "{%0,%1,%2,%3},{%4,%5,%6,%7},{%8,%9},{%0,%1,%2,%3};" \
        : "+f"((d)[0]), "+f"((d)[1]), "+f"((d)[2]), "+f"((d)[3]) \
        : "r"((a)[0]), "r"((a)[1]), "r"((a)[2]), "r"((a)[3]), \
          "r"((b)[0]), "r"((b)[1]))

#define CP16(sp, gp) \
    asm volatile("cp.async.cg.shared.global [%0],[%1],16;" :: "r"(sp), "l"(gp))
#define CP_COMMIT() asm volatile("cp.async.commit_group;")
#define CP_WAIT3()  asm volatile("cp.async.wait_group 3;")
#define CP_WAIT2()  asm volatile("cp.async.wait_group 2;")
#define CP_WAIT1()  asm volatile("cp.async.wait_group 1;")
#define CP_WAIT0()  asm volatile("cp.async.wait_group 0;")

__device__ __forceinline__ unsigned short f16_hi(float f, float& rem) {
    __half h = __float2half_rn(f);
    rem = f - __half2float(h);
    return *(unsigned short*)&h;
}
__device__ __forceinline__ unsigned short f16_of(float f) {
    __half h = __float2half_rn(f);
    return *(unsigned short*)&h;
}
// pack two fp32 -> f16x2 register: .lo = lo arg, .hi = hi arg
__device__ __forceinline__ uint32_t pack_f16x2(float lo, float hi) {
    uint32_t r;
    asm("cvt.rn.f16x2.f32 %0, %1, %2;" : "=r"(r) : "f"(hi), "f"(lo));
    return r;
}

// ---------------------------------------------------------------------------
// Vectorized FP32 -> fp16 convert (hi only): 8 elements per thread
// ---------------------------------------------------------------------------
__global__ void conv_fp16_v(const float4* __restrict__ in,
                            uint4* __restrict__ hi, int n8) {
    int i = blockIdx.x * blockDim.x + threadIdx.x;
    if (i >= n8) return;
    float4 a = in[2 * i];
    float4 b = in[2 * i + 1];
    uint4 hv;
    hv.x = (uint32_t)f16_of(a.x) | ((uint32_t)f16_of(a.y) << 16);
    hv.y = (uint32_t)f16_of(a.z) | ((uint32_t)f16_of(a.w) << 16);
    hv.z = (uint32_t)f16_of(b.x) | ((uint32_t)f16_of(b.y) << 16);
    hv.w = (uint32_t)f16_of(b.z) | ((uint32_t)f16_of(b.w) << 16);
    hi[i] = hv;
}

// Vectorized FP32 -> fp16 hi/lo split: 8 elements per thread (K/V inputs)
__global__ void split_fp32_v(const float4* __restrict__ in,
                             uint4* __restrict__ hi,
                             uint4* __restrict__ lo, int n8) {
    int i = blockIdx.x * blockDim.x + threadIdx.x;
    if (i >= n8) return;
    float4 a = in[2 * i];
    float4 b = in[2 * i + 1];
    float r[8];
    unsigned short h[8];
    h[0] = f16_hi(a.x, r[0]); h[1] = f16_hi(a.y, r[1]);
    h[2] = f16_hi(a.z, r[2]); h[3] = f16_hi(a.w, r[3]);
    h[4] = f16_hi(b.x, r[4]); h[5] = f16_hi(b.y, r[5]);
    h[6] = f16_hi(b.z, r[6]); h[7] = f16_hi(b.w, r[7]);
    uint4 hv, lv;
    hv.x = (uint32_t)h[0] | ((uint32_t)h[1] << 16);
    hv.y = (uint32_t)h[2] | ((uint32_t)h[3] << 16);
    hv.z = (uint32_t)h[4] | ((uint32_t)h[5] << 16);
    hv.w = (uint32_t)h[6] | ((uint32_t)h[7] << 16);
    lv.x = (uint32_t)f16_of(r[0]) | ((uint32_t)f16_of(r[1]) << 16);
    lv.y = (uint32_t)f16_of(r[2]) | ((uint32_t)f16_of(r[3]) << 16);
    lv.z = (uint32_t)f16_of(r[4]) | ((uint32_t)f16_of(r[5]) << 16);
    lv.w = (uint32_t)f16_of(r[6]) | ((uint32_t)f16_of(r[7]) << 16);
    hi[i] = hv;
    lo[i] = lv;
}

// ---------------------------------------------------------------------------
// Coalesced transpose + convert (hi only): W[K,640] -> Wt [640,K] fp16
// ---------------------------------------------------------------------------
__global__ void wconv_tr(const float* __restrict__ W,
                         unsigned short* __restrict__ thi, int K) {
    __shared__ float tile[32][33];
    const int tx = threadIdx.x, ty = threadIdx.y;
    const int n0 = blockIdx.x * 32;
    const int k0 = blockIdx.y * 32;
#pragma unroll
    for (int i = 0; i < 32; i += 8)
        tile[ty + i][tx] = W[(size_t)(k0 + ty + i) * EMBED + n0 + tx];
    __syncthreads();
#pragma unroll
    for (int i = 0; i < 32; i += 8) {
        size_t oi = (size_t)(n0 + ty + i) * K + k0 + tx;
        thi[oi] = f16_of(tile[tx][ty + i]);
    }
}

// Transpose + hi/lo split (for Wk, Wv)
__global__ void wsplit_tr(const float* __restrict__ W,
                          unsigned short* __restrict__ thi,
                          unsigned short* __restrict__ tlo, int K) {
    __shared__ float tile[32][33];
    const int tx = threadIdx.x, ty = threadIdx.y;
    const int n0 = blockIdx.x * 32;
    const int k0 = blockIdx.y * 32;
#pragma unroll
    for (int i = 0; i < 32; i += 8)
        tile[ty + i][tx] = W[(size_t)(k0 + ty + i) * EMBED + n0 + tx];
    __syncthreads();
#pragma unroll
    for (int i = 0; i < 32; i += 8) {
        float v = tile[tx][ty + i];
        float rem;
        unsigned short h = f16_hi(v, rem);
        size_t oi = (size_t)(n0 + ty + i) * K + k0 + tx;
        thi[oi] = h;
        tlo[oi] = f16_of(rem);
    }
}

// ---------------------------------------------------------------------------
// 3-term fp16 split GEMM -> fp16 output (K/V projections)
// ---------------------------------------------------------------------------
#define SLOT3 40960u
__global__ __launch_bounds__(256, 1)
void gemm_mma3(const unsigned short* __restrict__ Ahi,
               const unsigned short* __restrict__ Alo,
               const unsigned short* __restrict__ Bhi,
               const unsigned short* __restrict__ Blo,
               const float* __restrict__ bias,
               unsigned short* __restrict__ C16,
               int M, int K) {
    extern __shared__ char smem[];
    const uint32_t sbase = smem_to_u32(smem);
    const int tid = threadIdx.x;
    const int lane = tid & 31;
    const int wid = tid >> 5;
    const int wm = wid >> 2;
    const int wn = wid & 3;
    const int bm = blockIdx.y * 128;
    const int bn = blockIdx.x * 128;
    const int rowU4 = K >> 3;
    const int nst = K >> 5;
    const int maxAr = (M - bm - 1 < 127) ? (M - bm - 1) : 127;

    const uint4* gA0 = (const uint4*)(Ahi + (size_t)bm * K);
    const uint4* gA1 = (const uint4*)(Alo + (size_t)bm * K);
    const uint4* gB0 = (const uint4*)(Bhi + (size_t)bn * K);
    const uint4* gB1 = (const uint4*)(Blo + (size_t)bn * K);

    float d[4][4][4];
#pragma unroll
    for (int i = 0; i < 4; i++)
#pragma unroll
        for (int j = 0; j < 4; j++)
#pragma unroll
            for (int r = 0; r < 4; r++) d[i][j][r] = 0.f;

    auto load_stage = [&](int slot, int kt) {
        uint32_t sb = sbase + (uint32_t)slot * SLOT3;
#pragma unroll
        for (int j = 0; j < 8; j++) {
            int gidx = j * 256 + tid;
            int term = gidx >> 9;
            int idx = gidx & 511;
            int r = idx >> 2;
            int c = idx & 3;
            int re = (term < 2 && r > maxAr) ? maxAr : r;
            const uint4* src = (term == 0) ? gA0 : (term == 1) ? gA1
                             : (term == 2) ? gB0 : gB1;
            const uint4* gp = src + (size_t)re * rowU4 + kt * 4 + c;
            uint32_t sp = sb + (uint32_t)term * 10240u
                        + (uint32_t)(r * 80 + c * 16);
            CP16(sp, gp);
        }
        CP_COMMIT();
    };

    auto compute_stage = [&](int slot) {
        uint32_t sb = sbase + (uint32_t)slot * SLOT3;
        const uint32_t aOff[2] = {sb, sb + 10240u};
        const uint32_t bOff[2] = {sb + 20480u, sb + 30720u};
#pragma unroll
        for (int kk = 0; kk < 2; kk++) {
            const uint32_t colB = (uint32_t)(kk * 32) + ((lane & 16) ? 16u : 0u);
            uint32_t ah[4][4], al[4][4];
#pragma unroll
            for (int mt = 0; mt < 4; mt++) {
                int row = wm * 64 + mt * 16 + (lane & 15);
                LDSM4(ah[mt], aOff[0] + (uint32_t)(row * 80) + colB);
                LDSM4(al[mt], aOff[1] + (uint32_t)(row * 80) + colB);
            }
            uint32_t bh[4][2], bl[4][2];
#pragma unroll
            for (int nt2 = 0; nt2 < 2; nt2++) {
                int row = wn * 32 + nt2 * 16 + (lane & 15);
                uint32_t r4[4];
                LDSM4(r4, bOff[0] + (uint32_t)(row * 80) + colB);
                bh[nt2 * 2 + 0][0] = r4[0]; bh[nt2 * 2 + 0][1] = r4[2];
                bh[nt2 * 2 + 1][0] = r4[1]; bh[nt2 * 2 + 1][1] = r4[3];
                LDSM4(r4, bOff[1] + (uint32_t)(row * 80) + colB);
                bl[nt2 * 2 + 0][0] = r4[0]; bl[nt2 * 2 + 0][1] = r4[2];
                bl[nt2 * 2 + 1][0] = r4[1]; bl[nt2 * 2 + 1][1] = r4[3];
            }
#pragma unroll
            for (int mt = 0; mt < 4; mt++)
#pragma unroll
                for (int nt = 0; nt < 4; nt++) {
                    MMAF16(d[mt][nt], ah[mt], bh[nt]);
                    MMAF16(d[mt][nt], ah[mt], bl[nt]);
                    MMAF16(d[mt][nt], al[mt], bh[nt]);
                }
        }
    };

    load_stage(0, 0);
    load_stage(1, 1);
    load_stage(2, 2);
    for (int s = 0; s < nst; s++) {
        if (s + 2 < nst) { CP_WAIT2(); }
        else if (s + 1 < nst) { CP_WAIT1(); }
        else { CP_WAIT0(); }
        __syncthreads();
        compute_stage(s % 3);
        __syncthreads();
        if (s + 3 < nst) load_stage(s % 3, s + 3);
    }

#pragma unroll
    for (int mt = 0; mt < 4; mt++) {
        int row0 = bm + wm * 64 + mt * 16 + (lane >> 2);
#pragma unroll
        for (int nt = 0; nt < 4; nt++) {
            int col = bn + wn * 32 + nt * 8 + (lane & 3) * 2;
            float2 bv = *(const float2*)&bias[col];
            if (row0 < M) {
                uint32_t p = (uint32_t)f16_of(d[mt][nt][0] + bv.x)
                           | ((uint32_t)f16_of(d[mt][nt][1] + bv.y) << 16);
                *(uint32_t*)&C16[(size_t)row0 * EMBED + col] = p;
            }
            if (row0 + 8 < M) {
                uint32_t p = (uint32_t)f16_of(d[mt][nt][2] + bv.x)
                           | ((uint32_t)f16_of(d[mt][nt][3] + bv.y) << 16);
                *(uint32_t*)&C16[(size_t)(row0 + 8) * EMBED + col] = p;
            }
        }
    }
}

// ---------------------------------------------------------------------------
// 1-term fp16 GEMM core (shared by fp32-out and fp16-hi/lo-out variants)
// CTA 128x128, BK=32, 8 warps, 4-stage cp.async pipe.
// ---------------------------------------------------------------------------
#define SLOT1 20480u
template <int OUT16>
__device__ __forceinline__ void gemm1_body(
    const unsigned short* __restrict__ Ah,
    const unsigned short* __restrict__ Bh,
    const float* __restrict__ bias, float* __restrict__ C,
    unsigned short* __restrict__ Chi, unsigned short* __restrict__ Clo,
    float oscale, int M, int K, char* smem) {
    const uint32_t sbase = smem_to_u32(smem);
    const int tid = threadIdx.x;
    const int lane = tid & 31;
    const int wid = tid >> 5;
    const int wm = wid >> 2;
    const int wn = wid & 3;
    const int bm = blockIdx.y * 128;
    const int bn = blockIdx.x * 128;
    const int rowU4 = K >> 3;
    const int nst = K >> 5;

    const uint4* gA0 = (const uint4*)(Ah + (size_t)bm * K);
    const uint4* gB0 = (const uint4*)(Bh + (size_t)bn * K);

    float d[4][4][4];
#pragma unroll
    for (int i = 0; i < 4; i++)
#pragma unroll
        for (int j = 0; j < 4; j++)
#pragma unroll
            for (int r = 0; r < 4; r++) d[i][j][r] = 0.f;

    auto load_stage = [&](int slot, int kt) {
        uint32_t sb = sbase + (uint32_t)slot * SLOT1;
#pragma unroll
        for (int j = 0; j < 4; j++) {
            int gidx = j * 256 + tid;
            int term = gidx >> 9;
            int idx = gidx & 511;
            int r = idx >> 2;
            int c = idx & 3;
            const uint4* src = (term == 0) ? gA0 : gB0;
            const uint4* gp = src + (size_t)r * rowU4 + kt * 4 + c;
            uint32_t sp = sb + (uint32_t)term * 10240u
                        + (uint32_t)(r * 80 + c * 16);
            CP16(sp, gp);
        }
        CP_COMMIT();
    };

    auto compute_stage = [&](int slot) {
        uint32_t sb = sbase + (uint32_t)slot * SLOT1;
        const uint32_t aOff = sb;
        const uint32_t bOff = sb + 10240u;
#pragma unroll
        for (int kk = 0; kk < 2; kk++) {
            const uint32_t colB = (uint32_t)(kk * 32) + ((lane & 16) ? 16u : 0u);
            uint32_t ah[4][4];
#pragma unroll
            for (int mt = 0; mt < 4; mt++) {
                int row = wm * 64 + mt * 16 + (lane & 15);
                LDSM4(ah[mt], aOff + (uint32_t)(row * 80) + colB);
            }
            uint32_t bh[4][2];
#pragma unroll
            for (int nt2 = 0; nt2 < 2; nt2++) {
                int row = wn * 32 + nt2 * 16 + (lane & 15);
                uint32_t r4[4];
                LDSM4(r4, bOff + (uint32_t)(row * 80) + colB);
                bh[nt2 * 2 + 0][0] = r4[0]; bh[nt2 * 2 + 0][1] = r4[2];
                bh[nt2 * 2 + 1][0] = r4[1]; bh[nt2 * 2 + 1][1] = r4[3];
            }
#pragma unroll
            for (int mt = 0; mt < 4; mt++)
#pragma unroll
                for (int nt = 0; nt < 4; nt++)
                    MMAF16(d[mt][nt], ah[mt], bh[nt]);
        }
    };

    load_stage(0, 0);
    load_stage(1, 1);
    load_stage(2, 2);
    load_stage(3, 3);
    for (int s = 0; s < nst; s++) {
        if (s + 3 < nst) { CP_WAIT3(); }
        else if (s + 2 < nst) { CP_WAIT2(); }
        else if (s + 1 < nst) { CP_WAIT1(); }
        else { CP_WAIT0(); }
        __syncthreads();
        compute_stage(s & 3);
        __syncthreads();
        if (s + 4 < nst) load_stage(s & 3, s + 4);
    }

#pragma unroll
    for (int mt = 0; mt < 4; mt++) {
        int row0 = bm + wm * 64 + mt * 16 + (lane >> 2);
#pragma unroll
        for (int nt = 0; nt < 4; nt++) {
            int col = bn + wn * 32 + nt * 8 + (lane & 3) * 2;
            float2 bv = *(const float2*)&bias[col];
#pragma unroll
            for (int half = 0; half < 2; half++) {
                int row = row0 + half * 8;
                float v0 = (d[mt][nt][half * 2 + 0] + bv.x) * oscale;
                float v1 = (d[mt][nt][half * 2 + 1] + bv.y) * oscale;
                if (OUT16) {
                    float r0, r1;
                    unsigned short h0 = f16_hi(v0, r0);
                    unsigned short h1 = f16_hi(v1, r1);
                    *(uint32_t*)&Chi[(size_t)row * EMBED + col] =
                        (uint32_t)h0 | ((uint32_t)h1 << 16);
                    *(uint32_t*)&Clo[(size_t)row * EMBED + col] =
                        (uint32_t)f16_of(r0) | ((uint32_t)f16_of(r1) << 16);
                } else {
                    *(float2*)&C[(size_t)row * EMBED + col] = make_float2(v0, v1);
                }
            }
        }
    }
}

// O projection: fp32 output
__global__ __launch_bounds__(256, 1)
void gemm_mma1(const unsigned short* __restrict__ Ah,
               const unsigned short* __restrict__ Bh,
               const float* __restrict__ bias, float* __restrict__ C,
               int M, int K) {
    extern __shared__ char smem[];
    gemm1_body<0>(Ah, Bh, bias, C, nullptr, nullptr, 1.0f, M, K, smem);
}

// Q projection: scaled fp16 hi/lo output
__global__ __launch_bounds__(256, 1)
void gemm_mma1q(const unsigned short* __restrict__ Ah,
                const unsigned short* __restrict__ Bh,
                const float* __restrict__ bias,
                unsigned short* __restrict__ Chi,
                unsigned short* __restrict__ Clo,
                int M, int K) {
    extern __shared__ char smem[];
    gemm1_body<1>(Ah, Bh, bias, nullptr, Chi, Clo,
                  0.11180339887498949f, M, K, smem);
}

// ---------------------------------------------------------------------------
// Tensor-core attention: block = 128 t-rows x one (b,h), 8 warps x 16 rows.
// QK: 2-term q(hi/lo) x k(hi); softmax in C-fragments; P repacked in-register
// to A-fragments; PV vs V^T in smem. Output fp16 (feeds O-proj).
// smem halves, row stride 88 (conflict-free ldmatrix).
// ---------------------------------------------------------------------------
#define AT_STR 88
__global__ __launch_bounds__(256)
void attn_mma(const unsigned short* __restrict__ qhi,
              const unsigned short* __restrict__ qlo,
              const unsigned short* __restrict__ khi,
              const unsigned short* __restrict__ vhi,
              unsigned short* __restrict__ ohi) {
    extern __shared__ unsigned short smh[];
    unsigned short* sqh = smh;                    // 128*88
    unsigned short* sql = sqh + 128 * AT_STR;     // 128*88
    unsigned short* skh = sql + 128 * AT_STR;     // 80*88
    unsigned short* svt = skh + 80 * AT_STR;      // 80*88 (d rows, s cols)

    const int b = blockIdx.z;
    const int h = blockIdx.y;
    const int t0 = blockIdx.x * 128;
    const int tid = threadIdx.x;
    const int w = tid >> 5;
    const int lane = tid & 31;

    // ---- zero pads (FIXED: both loops execute for all needed entries) ----
    for (int i = tid; i < 3 * AT_STR; i += 256)   // skh rows 77..79, all cols
        skh[77 * AT_STR + i] = 0;
    for (int i = tid; i < 240; i += 256) {        // svt cols 77..79, all 80 d-rows
        svt[(i / 3) * AT_STR + 77 + (i % 3)] = 0;
    }

    // ---- staging ----
    for (int i = tid; i < 1280; i += 256) {       // q hi/lo: 128 rows x 10 uint4
        int t = i / 10, c = i - t * 10;
        size_t gi = ((size_t)(b * SEQ_T + t0 + t)) * 80 + h * 10 + c;
        *(uint4*)&sqh[t * AT_STR + c * 8] = ((const uint4*)qhi)[gi];
        *(uint4*)&sql[t * AT_STR + c * 8] = ((const uint4*)qlo)[gi];
    }
    for (int i = tid; i < 770; i += 256) {        // k: 77 rows x 10 uint4
        int s = i / 10, c = i - s * 10;
        size_t gi = ((size_t)(b * SEQ_S + s)) * 80 + h * 10 + c;
        *(uint4*)&skh[s * AT_STR + c * 8] = ((const uint4*)khi)[gi];
    }
    for (int i = tid; i < SEQ_S * 80; i += 256) { // v transpose -> svt[d][s]
        int s = i / 80, dd = i - s * 80;
        svt[dd * AT_STR + s] = vhi[((size_t)(b * SEQ_S + s)) * EMBED + h * 80 + dd];
    }
    __syncthreads();

    const uint32_t sqh_b = smem_to_u32(sqh);
    const uint32_t sql_b = smem_to_u32(sql);
    const uint32_t skh_b = smem_to_u32(skh);
    const uint32_t svt_b = smem_to_u32(svt);
    const uint32_t lrow = (uint32_t)(lane & 15) * (AT_STR * 2);
    const uint32_t loff = (lane & 16) ? 16u : 0u;

    // ---- QK^T: d[10][4] fp32 fragments ----
    float d[10][4];
#pragma unroll
    for (int nt = 0; nt < 10; nt++)
#pragma unroll
        for (int c = 0; c < 4; c++) d[nt][c] = 0.f;

#pragma unroll
    for (int ks = 0; ks < 5; ks++) {
        const uint32_t ca = (uint32_t)(ks * 32) + loff;
        uint32_t ah[4], al[4];
        LDSM4(ah, sqh_b + (uint32_t)(w * 16) * (AT_STR * 2) + lrow + ca);
        LDSM4(al, sql_b + (uint32_t)(w * 16) * (AT_STR * 2) + lrow + ca);
#pragma unroll
        for (int nt2 = 0; nt2 < 5; nt2++) {
            uint32_t r4[4];
            LDSM4(r4, skh_b + (uint32_t)(nt2 * 16) * (AT_STR * 2) + lrow + ca);
            uint32_t b0[2] = {r4[0], r4[2]};
            uint32_t b1[2] = {r4[1], r4[3]};
            MMAF16(d[nt2 * 2 + 0], ah, b0);
            MMAF16(d[nt2 * 2 + 0], al, b0);
            MMAF16(d[nt2 * 2 + 1], ah, b1);
            MMAF16(d[nt2 * 2 + 1], al, b1);
        }
    }

    // ---- mask cols >= 77 (only n-tile 9: cols 72..79) ----
    {
        int colb = 72 + (lane & 3) * 2;
        if (colb >= 77)     { d[9][0] = -1e30f; d[9][2] = -1e30f; }
        if (colb + 1 >= 77) { d[9][1] = -1e30f; d[9][3] = -1e30f; }
    }

    // ---- softmax on fragments (rows: lane/4 and lane/4+8) ----
    {
        float mA = -1e30f, mB = -1e30f;
#pragma unroll
        for (int nt = 0; nt < 10; nt++) {
            mA = fmaxf(mA, fmaxf(d[nt][0], d[nt][1]));
            mB = fmaxf(mB, fmaxf(d[nt][2], d[nt][3]));
        }
        mA = fmaxf(mA, __shfl_xor_sync(0xFFFFFFFFu, mA, 1));
        mA = fmaxf(mA, __shfl_xor_sync(0xFFFFFFFFu, mA, 2));
        mB = fmaxf(mB, __shfl_xor_sync(0xFFFFFFFFu, mB, 1));
        mB = fmaxf(mB, __shfl_xor_sync(0xFFFFFFFFu, mB, 2));
        float sA = 0.f, sB = 0.f;
#pragma unroll
        for (int nt = 0; nt < 10; nt++) {
            d[nt][0] = __expf(d[nt][0] - mA); sA += d[nt][0];
            d[nt][1] = __expf(d[nt][1] - mA); sA += d[nt][1];
            d[nt][2] = __expf(d[nt][2] - mB); sB += d[nt][2];
            d[nt][3] = __expf(d[nt][3] - mB); sB += d[nt][3];
        }
        sA += __shfl_xor_sync(0xFFFFFFFFu, sA, 1);
        sA += __shfl_xor_sync(0xFFFFFFFFu, sA, 2);
        sB += __shfl_xor_sync(0xFFFFFFFFu, sB, 1);
        sB += __shfl_xor_sync(0xFFFFFFFFu, sB, 2);
        float rA = 1.f / sA, rB = 1.f / sB;
#pragma unroll
        for (int nt = 0; nt < 10; nt++) {
            d[nt][0] *= rA; d[nt][1] *= rA;
            d[nt][2] *= rB; d[nt][3] *= rB;
        }
    }

    // ---- repack P (C-fragments) to A-fragments, fp16 ----
    uint32_t pa[5][4];
#pragma unroll
    for (int kp = 0; kp < 5; kp++) {
        pa[kp][0] = pack_f16x2(d[2 * kp][0],     d[2 * kp][1]);
        pa[kp][1] = pack_f16x2(d[2 * kp][2],     d[2 * kp][3]);
        pa[kp][2] = pack_f16x2(d[2 * kp + 1][0], d[2 * kp + 1][1]);
        pa[kp][3] = pack_f16x2(d[2 * kp + 1][2], d[2 * kp + 1][3]);
    }

    // ---- PV: o[10][4] over V^T ----
    float o[10][4];
#pragma unroll
    for (int nt = 0; nt < 10; nt++)
#pragma unroll
        for (int c = 0; c < 4; c++) o[nt][c] = 0.f;

#pragma unroll
    for (int kp = 0; kp < 5; kp++) {
        const uint32_t ca = (uint32_t)(kp * 32) + loff;
#pragma unroll
        for (int nt2 = 0; nt2 < 5; nt2++) {
            uint32_t r4[4];
            LDSM4(r4, svt_b + (uint32_t)(nt2 * 16) * (AT_STR * 2) + lrow + ca);
            uint32_t b0[2] = {r4[0], r4[2]};
            uint32_t b1[2] = {r4[1], r4[3]};
            MMAF16(o[nt2 * 2 + 0], pa[kp], b0);
            MMAF16(o[nt2 * 2 + 1], pa[kp], b1);
        }
    }

    // ---- epilogue: fp16 out ----
    {
        const size_t rbase = (size_t)(b * SEQ_T + t0 + w * 16 + (lane >> 2));
        const int col = h * 80 + (lane & 3) * 2;
#pragma unroll
        for (int nt = 0; nt < 10; nt++) {
            *(uint32_t*)&ohi[rbase * EMBED + col + nt * 8] =
                pack_f16x2(o[nt][0], o[nt][1]);
            *(uint32_t*)&ohi[(rbase + 8) * EMBED + col + nt * 8] =
                pack_f16x2(o[nt][2], o[nt][3]);
        }
    }
}

// ---------------------------------------------------------------------------
extern "C" void kernel_launch(void* const* d_in, const int* in_sizes, int n_in,
                              void* d_out, int out_size) {
    const float* x  = (const float*)d_in[0];
    const float* y  = (const float*)d_in[1];
    const float* Wq = (const float*)d_in[2];
    const float* bq = (const float*)d_in[3];
    const float* Wk = (const float*)d_in[4];
    const float* bk = (const float*)d_in[5];
    const float* Wv = (const float*)d_in[6];
    const float* bv = (const float*)d_in[7];
    const float* Wo = (const float*)d_in[8];
    const float* bo = (const float*)d_in[9];
    float* out = (float*)d_out;

    unsigned short *xhi, *qhi, *qlo, *khi, *vhi, *yhi, *ylo, *wthi, *wtlo;
    cudaGetSymbolAddress((void**)&xhi, g_xhi);
    cudaGetSymbolAddress((void**)&qhi, g_qhi);
    cudaGetSymbolAddress((void**)&qlo, g_qlo);
    cudaGetSymbolAddress((void**)&khi, g_khi);
    cudaGetSymbolAddress((void**)&vhi, g_vhi);
    cudaGetSymbolAddress((void**)&yhi, g_yhi);
    cudaGetSymbolAddress((void**)&ylo, g_ylo);
    cudaGetSymbolAddress((void**)&wthi, g_wthi);
    cudaGetSymbolAddress((void**)&wtlo, g_wtlo);

    const int smem_attn = (128 * AT_STR * 2 + 80 * AT_STR * 2) * 2;  // 73216 B
    cudaFuncSetAttribute(attn_mma, cudaFuncAttributeMaxDynamicSharedMemorySize, smem_attn);
    const int smem_m3 = 3 * (int)SLOT3;  // 122880
    cudaFuncSetAttribute(gemm_mma3, cudaFuncAttributeMaxDynamicSharedMemorySize, smem_m3);
    const int smem_m1 = 4 * (int)SLOT1;  // 81920
    cudaFuncSetAttribute(gemm_mma1, cudaFuncAttributeMaxDynamicSharedMemorySize, smem_m1);
    cudaFuncSetAttribute(gemm_mma1q, cudaFuncAttributeMaxDynamicSharedMemorySize, smem_m1);

    const int NX = BATCH * SEQ_T * EMBED;      // 21.0M
    const int NY = BATCH * SEQ_S * CROSS;      // 473k
    const int MKV = BATCH * SEQ_S;             // 616

    // --- Q projection: fp16 1-term, outputs scaled q hi/lo fp16 ---
    conv_fp16_v<<<(NX / 8 + 255) / 256, 256>>>((const float4*)x, (uint4*)xhi, NX / 8);
    wconv_tr<<<dim3(EMBED / 32, EMBED / 32), dim3(32, 8)>>>(Wq, wthi, EMBED);
    {
        dim3 grid(EMBED / 128, (BATCH * SEQ_T) / 128);
        gemm_mma1q<<<grid, 256, smem_m1>>>(xhi, wthi, bq, qhi, qlo, BATCH * SEQ_T, EMBED);
    }

    // --- K/V projections: fp16 3-term (exact), fp16 outputs ---
    split_fp32_v<<<(NY / 8 + 255) / 256, 256>>>((const float4*)y, (uint4*)yhi, (uint4*)ylo, NY / 8);
    {
        dim3 grid(EMBED / 128, (MKV + 127) / 128);
        wsplit_tr<<<dim3(EMBED / 32, CROSS / 32), dim3(32, 8)>>>(Wk, wthi, wtlo, CROSS);
        gemm_mma3<<<grid, 256, smem_m3>>>(yhi, ylo, wthi, wtlo, bk, khi, MKV, CROSS);
        wsplit_tr<<<dim3(EMBED / 32, CROSS / 32), dim3(32, 8)>>>(Wv, wthi, wtlo, CROSS);
        gemm_mma3<<<grid, 256, smem_m3>>>(yhi, ylo, wthi, wtlo, bv, vhi, MKV, CROSS);
    }

    // --- attention on tensor cores (writes fp16 into xhi; x dead by now) ---
    {
        dim3 grid(SEQ_T / 128, N_HEADS, BATCH);
        attn_mma<<<grid, 256, smem_attn>>>(qhi, qlo, khi, vhi, xhi);
    }

    // --- O projection: fp16 1-term, fp32 output ---
    wconv_tr<<<dim3(EMBED / 32, EMBED / 32), dim3(32, 8)>>>(Wo, wthi, EMBED);
    {
        dim3 grid(EMBED / 128, (BATCH * SEQ_T) / 128);
        gemm_mma1<<<grid, 256, smem_m1>>>(xhi, wthi, bo, out, BATCH * SEQ_T, EMBED);
    }
}

// round 11
// speedup vs baseline: 5.7494x; 1.0578x over previous
#include <cuda_runtime.h>
#include <cuda_fp16.h>
#include <cstdint>
#include <math.h>

#define N_HEADS 8
#define EMBED 640
#define CROSS 768
#define HEAD 80
#define BATCH 8
#define SEQ_T 4096
#define SEQ_S 77

// ---------------------------------------------------------------------------
// Scratch (no cudaMalloc allowed)
// ---------------------------------------------------------------------------
__device__ __align__(16) unsigned short g_xhi[BATCH * SEQ_T * EMBED];  // x fp16 / attn-out fp16
__device__ __align__(16) unsigned short g_qhi[BATCH * SEQ_T * EMBED];  // scaled q hi
__device__ __align__(16) unsigned short g_qlo[BATCH * SEQ_T * EMBED];  // scaled q lo
__device__ __align__(16) unsigned short g_khi[BATCH * SEQ_S * EMBED];
__device__ __align__(16) unsigned short g_vhi[BATCH * SEQ_S * EMBED];
__device__ __align__(16) unsigned short g_yhi[BATCH * SEQ_S * CROSS];
__device__ __align__(16) unsigned short g_ylo[BATCH * SEQ_S * CROSS];
__device__ __align__(16) unsigned short g_wthi[EMBED * CROSS];
__device__ __align__(16) unsigned short g_wtlo[EMBED * CROSS];

// ---------------------------------------------------------------------------
// PTX helpers (non-'a' features only: ldmatrix, mma.sync, cp.async)
// ---------------------------------------------------------------------------
__device__ __forceinline__ uint32_t smem_to_u32(const void* smem_ptr) {
    uint32_t addr;
    asm("{ .reg .u64 tmp; cvta.to.shared.u64 tmp, %1; cvt.u32.u64 %0, tmp; }"
        : "=r"(addr) : "l"(smem_ptr));
    return addr;
}

#define LDSM4(r, addr) \
    asm volatile("ldmatrix.sync.aligned.m8n8.x4.shared.b16 {%0,%1,%2,%3},[%4];" \
        : "=r"((r)[0]), "=r"((r)[1]), "=r"((r)[2]), "=r"((r)[3]) : "r"(addr))

#define MMAF16(d, a, b) \
    asm volatile("mma.sync.aligned.m16n8k16.row.col.f32.f16.f16.f32 " \
        "{%0,%1,%2,%3},{%4,%5,%6,%7},{%8,%9},{%0,%1,%2,%3};" \
        : "+f"((d)[0]), "+f"((d)[1]), "+f"((d)[2]), "+f"((d)[3]) \
        : "r"((a)[0]), "r"((a)[1]), "r"((a)[2]), "r"((a)[3]), \
          "r"((b)[0]), "r"((b)[1]))

#define CP16(sp, gp) \
    asm volatile("cp.async.cg.shared.global [%0],[%1],16;" :: "r"(sp), "l"(gp))
#define CP_COMMIT() asm volatile("cp.async.commit_group;")
#define CP_WAIT2()  asm volatile("cp.async.wait_group 2;")
#define CP_WAIT1()  asm volatile("cp.async.wait_group 1;")
#define CP_WAIT0()  asm volatile("cp.async.wait_group 0;")

__device__ __forceinline__ unsigned short f16_hi(float f, float& rem) {
    __half h = __float2half_rn(f);
    rem = f - __half2float(h);
    return *(unsigned short*)&h;
}
__device__ __forceinline__ unsigned short f16_of(float f) {
    __half h = __float2half_rn(f);
    return *(unsigned short*)&h;
}
// pack two fp32 -> f16x2 register: .lo = lo arg, .hi = hi arg
__device__ __forceinline__ uint32_t pack_f16x2(float lo, float hi) {
    uint32_t r;
    asm("cvt.rn.f16x2.f32 %0, %1, %2;" : "=r"(r) : "f"(hi), "f"(lo));
    return r;
}

// ---------------------------------------------------------------------------
// Vectorized FP32 -> fp16 convert (hi only): 8 elements per thread
// ---------------------------------------------------------------------------
__global__ void conv_fp16_v(const float4* __restrict__ in,
                            uint4* __restrict__ hi, int n8) {
    int i = blockIdx.x * blockDim.x + threadIdx.x;
    if (i >= n8) return;
    float4 a = in[2 * i];
    float4 b = in[2 * i + 1];
    uint4 hv;
    hv.x = (uint32_t)f16_of(a.x) | ((uint32_t)f16_of(a.y) << 16);
    hv.y = (uint32_t)f16_of(a.z) | ((uint32_t)f16_of(a.w) << 16);
    hv.z = (uint32_t)f16_of(b.x) | ((uint32_t)f16_of(b.y) << 16);
    hv.w = (uint32_t)f16_of(b.z) | ((uint32_t)f16_of(b.w) << 16);
    hi[i] = hv;
}

// Vectorized FP32 -> fp16 hi/lo split: 8 elements per thread (K/V inputs)
__global__ void split_fp32_v(const float4* __restrict__ in,
                             uint4* __restrict__ hi,
                             uint4* __restrict__ lo, int n8) {
    int i = blockIdx.x * blockDim.x + threadIdx.x;
    if (i >= n8) return;
    float4 a = in[2 * i];
    float4 b = in[2 * i + 1];
    float r[8];
    unsigned short h[8];
    h[0] = f16_hi(a.x, r[0]); h[1] = f16_hi(a.y, r[1]);
    h[2] = f16_hi(a.z, r[2]); h[3] = f16_hi(a.w, r[3]);
    h[4] = f16_hi(b.x, r[4]); h[5] = f16_hi(b.y, r[5]);
    h[6] = f16_hi(b.z, r[6]); h[7] = f16_hi(b.w, r[7]);
    uint4 hv, lv;
    hv.x = (uint32_t)h[0] | ((uint32_t)h[1] << 16);
    hv.y = (uint32_t)h[2] | ((uint32_t)h[3] << 16);
    hv.z = (uint32_t)h[4] | ((uint32_t)h[5] << 16);
    hv.w = (uint32_t)h[6] | ((uint32_t)h[7] << 16);
    lv.x = (uint32_t)f16_of(r[0]) | ((uint32_t)f16_of(r[1]) << 16);
    lv.y = (uint32_t)f16_of(r[2]) | ((uint32_t)f16_of(r[3]) << 16);
    lv.z = (uint32_t)f16_of(r[4]) | ((uint32_t)f16_of(r[5]) << 16);
    lv.w = (uint32_t)f16_of(r[6]) | ((uint32_t)f16_of(r[7]) << 16);
    hi[i] = hv;
    lo[i] = lv;
}

// ---------------------------------------------------------------------------
// Coalesced transpose + convert (hi only): W[K,640] -> Wt [640,K] fp16
// ---------------------------------------------------------------------------
__global__ void wconv_tr(const float* __restrict__ W,
                         unsigned short* __restrict__ thi, int K) {
    __shared__ float tile[32][33];
    const int tx = threadIdx.x, ty = threadIdx.y;
    const int n0 = blockIdx.x * 32;
    const int k0 = blockIdx.y * 32;
#pragma unroll
    for (int i = 0; i < 32; i += 8)
        tile[ty + i][tx] = W[(size_t)(k0 + ty + i) * EMBED + n0 + tx];
    __syncthreads();
#pragma unroll
    for (int i = 0; i < 32; i += 8) {
        size_t oi = (size_t)(n0 + ty + i) * K + k0 + tx;
        thi[oi] = f16_of(tile[tx][ty + i]);
    }
}

// Transpose + hi/lo split (for Wk, Wv)
__global__ void wsplit_tr(const float* __restrict__ W,
                          unsigned short* __restrict__ thi,
                          unsigned short* __restrict__ tlo, int K) {
    __shared__ float tile[32][33];
    const int tx = threadIdx.x, ty = threadIdx.y;
    const int n0 = blockIdx.x * 32;
    const int k0 = blockIdx.y * 32;
#pragma unroll
    for (int i = 0; i < 32; i += 8)
        tile[ty + i][tx] = W[(size_t)(k0 + ty + i) * EMBED + n0 + tx];
    __syncthreads();
#pragma unroll
    for (int i = 0; i < 32; i += 8) {
        float v = tile[tx][ty + i];
        float rem;
        unsigned short h = f16_hi(v, rem);
        size_t oi = (size_t)(n0 + ty + i) * K + k0 + tx;
        thi[oi] = h;
        tlo[oi] = f16_of(rem);
    }
}

// ---------------------------------------------------------------------------
// 3-term fp16 split GEMM -> fp16 output (K/V projections)
// 3 slots, 2 preloads, single sync per stage.
// ---------------------------------------------------------------------------
#define SLOT3 40960u
__global__ __launch_bounds__(256, 1)
void gemm_mma3(const unsigned short* __restrict__ Ahi,
               const unsigned short* __restrict__ Alo,
               const unsigned short* __restrict__ Bhi,
               const unsigned short* __restrict__ Blo,
               const float* __restrict__ bias,
               unsigned short* __restrict__ C16,
               int M, int K) {
    extern __shared__ char smem[];
    const uint32_t sbase = smem_to_u32(smem);
    const int tid = threadIdx.x;
    const int lane = tid & 31;
    const int wid = tid >> 5;
    const int wm = wid >> 2;
    const int wn = wid & 3;
    const int bm = blockIdx.y * 128;
    const int bn = blockIdx.x * 128;
    const int rowU4 = K >> 3;
    const int nst = K >> 5;
    const int maxAr = (M - bm - 1 < 127) ? (M - bm - 1) : 127;

    const uint4* gA0 = (const uint4*)(Ahi + (size_t)bm * K);
    const uint4* gA1 = (const uint4*)(Alo + (size_t)bm * K);
    const uint4* gB0 = (const uint4*)(Bhi + (size_t)bn * K);
    const uint4* gB1 = (const uint4*)(Blo + (size_t)bn * K);

    float d[4][4][4];
#pragma unroll
    for (int i = 0; i < 4; i++)
#pragma unroll
        for (int j = 0; j < 4; j++)
#pragma unroll
            for (int r = 0; r < 4; r++) d[i][j][r] = 0.f;

    auto load_stage = [&](int slot, int kt) {
        uint32_t sb = sbase + (uint32_t)slot * SLOT3;
#pragma unroll
        for (int j = 0; j < 8; j++) {
            int gidx = j * 256 + tid;
            int term = gidx >> 9;
            int idx = gidx & 511;
            int r = idx >> 2;
            int c = idx & 3;
            int re = (term < 2 && r > maxAr) ? maxAr : r;
            const uint4* src = (term == 0) ? gA0 : (term == 1) ? gA1
                             : (term == 2) ? gB0 : gB1;
            const uint4* gp = src + (size_t)re * rowU4 + kt * 4 + c;
            uint32_t sp = sb + (uint32_t)term * 10240u
                        + (uint32_t)(r * 80 + c * 16);
            CP16(sp, gp);
        }
        CP_COMMIT();
    };

    auto compute_stage = [&](int slot) {
        uint32_t sb = sbase + (uint32_t)slot * SLOT3;
        const uint32_t aOff[2] = {sb, sb + 10240u};
        const uint32_t bOff[2] = {sb + 20480u, sb + 30720u};
#pragma unroll
        for (int kk = 0; kk < 2; kk++) {
            const uint32_t colB = (uint32_t)(kk * 32) + ((lane & 16) ? 16u : 0u);
            uint32_t ah[4][4], al[4][4];
#pragma unroll
            for (int mt = 0; mt < 4; mt++) {
                int row = wm * 64 + mt * 16 + (lane & 15);
                LDSM4(ah[mt], aOff[0] + (uint32_t)(row * 80) + colB);
                LDSM4(al[mt], aOff[1] + (uint32_t)(row * 80) + colB);
            }
            uint32_t bh[4][2], bl[4][2];
#pragma unroll
            for (int nt2 = 0; nt2 < 2; nt2++) {
                int row = wn * 32 + nt2 * 16 + (lane & 15);
                uint32_t r4[4];
                LDSM4(r4, bOff[0] + (uint32_t)(row * 80) + colB);
                bh[nt2 * 2 + 0][0] = r4[0]; bh[nt2 * 2 + 0][1] = r4[2];
                bh[nt2 * 2 + 1][0] = r4[1]; bh[nt2 * 2 + 1][1] = r4[3];
                LDSM4(r4, bOff[1] + (uint32_t)(row * 80) + colB);
                bl[nt2 * 2 + 0][0] = r4[0]; bl[nt2 * 2 + 0][1] = r4[2];
                bl[nt2 * 2 + 1][0] = r4[1]; bl[nt2 * 2 + 1][1] = r4[3];
            }
#pragma unroll
            for (int mt = 0; mt < 4; mt++)
#pragma unroll
                for (int nt = 0; nt < 4; nt++) {
                    MMAF16(d[mt][nt], ah[mt], bh[nt]);
                    MMAF16(d[mt][nt], ah[mt], bl[nt]);
                    MMAF16(d[mt][nt], al[mt], bh[nt]);
                }
        }
    };

    load_stage(0, 0);
    load_stage(1, 1);
    for (int s = 0; s < nst; s++) {
        if (s + 1 < nst) { CP_WAIT1(); } else { CP_WAIT0(); }
        __syncthreads();
        if (s + 2 < nst) load_stage((s + 2) % 3, s + 2);
        compute_stage(s % 3);
    }

#pragma unroll
    for (int mt = 0; mt < 4; mt++) {
        int row0 = bm + wm * 64 + mt * 16 + (lane >> 2);
#pragma unroll
        for (int nt = 0; nt < 4; nt++) {
            int col = bn + wn * 32 + nt * 8 + (lane & 3) * 2;
            float2 bv = *(const float2*)&bias[col];
            if (row0 < M) {
                uint32_t p = (uint32_t)f16_of(d[mt][nt][0] + bv.x)
                           | ((uint32_t)f16_of(d[mt][nt][1] + bv.y) << 16);
                *(uint32_t*)&C16[(size_t)row0 * EMBED + col] = p;
            }
            if (row0 + 8 < M) {
                uint32_t p = (uint32_t)f16_of(d[mt][nt][2] + bv.x)
                           | ((uint32_t)f16_of(d[mt][nt][3] + bv.y) << 16);
                *(uint32_t*)&C16[(size_t)(row0 + 8) * EMBED + col] = p;
            }
        }
    }
}

// ---------------------------------------------------------------------------
// 1-term fp16 GEMM core: 4 slots, 3 preloads, single sync per stage,
// occupancy 2 (smem 4x20KB = 80KB; 2 CTAs/SM fit in 228KB).
// ---------------------------------------------------------------------------
#define SLOT1 20480u
template <int OUT16>
__device__ __forceinline__ void gemm1_body(
    const unsigned short* __restrict__ Ah,
    const unsigned short* __restrict__ Bh,
    const float* __restrict__ bias, float* __restrict__ C,
    unsigned short* __restrict__ Chi, unsigned short* __restrict__ Clo,
    float oscale, int M, int K, char* smem) {
    const uint32_t sbase = smem_to_u32(smem);
    const int tid = threadIdx.x;
    const int lane = tid & 31;
    const int wid = tid >> 5;
    const int wm = wid >> 2;
    const int wn = wid & 3;
    const int bm = blockIdx.y * 128;
    const int bn = blockIdx.x * 128;
    const int rowU4 = K >> 3;
    const int nst = K >> 5;

    const uint4* gA0 = (const uint4*)(Ah + (size_t)bm * K);
    const uint4* gB0 = (const uint4*)(Bh + (size_t)bn * K);

    float d[4][4][4];
#pragma unroll
    for (int i = 0; i < 4; i++)
#pragma unroll
        for (int j = 0; j < 4; j++)
#pragma unroll
            for (int r = 0; r < 4; r++) d[i][j][r] = 0.f;

    auto load_stage = [&](int slot, int kt) {
        uint32_t sb = sbase + (uint32_t)slot * SLOT1;
#pragma unroll
        for (int j = 0; j < 4; j++) {
            int gidx = j * 256 + tid;
            int term = gidx >> 9;
            int idx = gidx & 511;
            int r = idx >> 2;
            int c = idx & 3;
            const uint4* src = (term == 0) ? gA0 : gB0;
            const uint4* gp = src + (size_t)r * rowU4 + kt * 4 + c;
            uint32_t sp = sb + (uint32_t)term * 10240u
                        + (uint32_t)(r * 80 + c * 16);
            CP16(sp, gp);
        }
        CP_COMMIT();
    };

    auto compute_stage = [&](int slot) {
        uint32_t sb = sbase + (uint32_t)slot * SLOT1;
        const uint32_t aOff = sb;
        const uint32_t bOff = sb + 10240u;
#pragma unroll
        for (int kk = 0; kk < 2; kk++) {
            const uint32_t colB = (uint32_t)(kk * 32) + ((lane & 16) ? 16u : 0u);
            uint32_t ah[4][4];
#pragma unroll
            for (int mt = 0; mt < 4; mt++) {
                int row = wm * 64 + mt * 16 + (lane & 15);
                LDSM4(ah[mt], aOff + (uint32_t)(row * 80) + colB);
            }
            uint32_t bh[4][2];
#pragma unroll
            for (int nt2 = 0; nt2 < 2; nt2++) {
                int row = wn * 32 + nt2 * 16 + (lane & 15);
                uint32_t r4[4];
                LDSM4(r4, bOff + (uint32_t)(row * 80) + colB);
                bh[nt2 * 2 + 0][0] = r4[0]; bh[nt2 * 2 + 0][1] = r4[2];
                bh[nt2 * 2 + 1][0] = r4[1]; bh[nt2 * 2 + 1][1] = r4[3];
            }
#pragma unroll
            for (int mt = 0; mt < 4; mt++)
#pragma unroll
                for (int nt = 0; nt < 4; nt++)
                    MMAF16(d[mt][nt], ah[mt], bh[nt]);
        }
    };

    // 3 preloads into 4 slots; one sync per stage.
    load_stage(0, 0);
    load_stage(1, 1);
    load_stage(2, 2);
    for (int s = 0; s < nst; s++) {
        if (s + 2 < nst) { CP_WAIT2(); }
        else if (s + 1 < nst) { CP_WAIT1(); }
        else { CP_WAIT0(); }
        __syncthreads();
        if (s + 3 < nst) load_stage((s + 3) & 3, s + 3);
        compute_stage(s & 3);
    }

#pragma unroll
    for (int mt = 0; mt < 4; mt++) {
        int row0 = bm + wm * 64 + mt * 16 + (lane >> 2);
#pragma unroll
        for (int nt = 0; nt < 4; nt++) {
            int col = bn + wn * 32 + nt * 8 + (lane & 3) * 2;
            float2 bv = *(const float2*)&bias[col];
#pragma unroll
            for (int half = 0; half < 2; half++) {
                int row = row0 + half * 8;
                float v0 = (d[mt][nt][half * 2 + 0] + bv.x) * oscale;
                float v1 = (d[mt][nt][half * 2 + 1] + bv.y) * oscale;
                if (OUT16) {
                    float r0, r1;
                    unsigned short h0 = f16_hi(v0, r0);
                    unsigned short h1 = f16_hi(v1, r1);
                    *(uint32_t*)&Chi[(size_t)row * EMBED + col] =
                        (uint32_t)h0 | ((uint32_t)h1 << 16);
                    *(uint32_t*)&Clo[(size_t)row * EMBED + col] =
                        (uint32_t)f16_of(r0) | ((uint32_t)f16_of(r1) << 16);
                } else {
                    *(float2*)&C[(size_t)row * EMBED + col] = make_float2(v0, v1);
                }
            }
        }
    }
}

// O projection: fp32 output
__global__ __launch_bounds__(256, 2)
void gemm_mma1(const unsigned short* __restrict__ Ah,
               const unsigned short* __restrict__ Bh,
               const float* __restrict__ bias, float* __restrict__ C,
               int M, int K) {
    extern __shared__ char smem[];
    gemm1_body<0>(Ah, Bh, bias, C, nullptr, nullptr, 1.0f, M, K, smem);
}

// Q projection: scaled fp16 hi/lo output
__global__ __launch_bounds__(256, 2)
void gemm_mma1q(const unsigned short* __restrict__ Ah,
                const unsigned short* __restrict__ Bh,
                const float* __restrict__ bias,
                unsigned short* __restrict__ Chi,
                unsigned short* __restrict__ Clo,
                int M, int K) {
    extern __shared__ char smem[];
    gemm1_body<1>(Ah, Bh, bias, nullptr, Chi, Clo,
                  0.11180339887498949f, M, K, smem);
}

// ---------------------------------------------------------------------------
// Tensor-core attention: block = 128 t-rows x one (b,h), 8 warps x 16 rows.
// QK: 2-term q(hi/lo) x k(hi); softmax in C-fragments; P repacked in-register
// to A-fragments; PV vs V^T in smem. Output fp16 (feeds O-proj).
// ---------------------------------------------------------------------------
#define AT_STR 88
__global__ __launch_bounds__(256)
void attn_mma(const unsigned short* __restrict__ qhi,
              const unsigned short* __restrict__ qlo,
              const unsigned short* __restrict__ khi,
              const unsigned short* __restrict__ vhi,
              unsigned short* __restrict__ ohi) {
    extern __shared__ unsigned short smh[];
    unsigned short* sqh = smh;                    // 128*88
    unsigned short* sql = sqh + 128 * AT_STR;     // 128*88
    unsigned short* skh = sql + 128 * AT_STR;     // 80*88
    unsigned short* svt = skh + 80 * AT_STR;      // 80*88 (d rows, s cols)

    const int b = blockIdx.z;
    const int h = blockIdx.y;
    const int t0 = blockIdx.x * 128;
    const int tid = threadIdx.x;
    const int w = tid >> 5;
    const int lane = tid & 31;

    // ---- zero pads ----
    for (int i = tid; i < 3 * AT_STR; i += 256)
        skh[77 * AT_STR + i] = 0;
    for (int i = tid; i < 240; i += 256)
        svt[(i / 3) * AT_STR + 77 + (i % 3)] = 0;

    // ---- staging ----
    for (int i = tid; i < 1280; i += 256) {
        int t = i / 10, c = i - t * 10;
        size_t gi = ((size_t)(b * SEQ_T + t0 + t)) * 80 + h * 10 + c;
        *(uint4*)&sqh[t * AT_STR + c * 8] = ((const uint4*)qhi)[gi];
        *(uint4*)&sql[t * AT_STR + c * 8] = ((const uint4*)qlo)[gi];
    }
    for (int i = tid; i < 770; i += 256) {
        int s = i / 10, c = i - s * 10;
        size_t gi = ((size_t)(b * SEQ_S + s)) * 80 + h * 10 + c;
        *(uint4*)&skh[s * AT_STR + c * 8] = ((const uint4*)khi)[gi];
    }
    for (int i = tid; i < SEQ_S * 80; i += 256) {
        int s = i / 80, dd = i - s * 80;
        svt[dd * AT_STR + s] = vhi[((size_t)(b * SEQ_S + s)) * EMBED + h * 80 + dd];
    }
    __syncthreads();

    const uint32_t sqh_b = smem_to_u32(sqh);
    const uint32_t sql_b = smem_to_u32(sql);
    const uint32_t skh_b = smem_to_u32(skh);
    const uint32_t svt_b = smem_to_u32(svt);
    const uint32_t lrow = (uint32_t)(lane & 15) * (AT_STR * 2);
    const uint32_t loff = (lane & 16) ? 16u : 0u;

    // ---- QK^T ----
    float d[10][4];
#pragma unroll
    for (int nt = 0; nt < 10; nt++)
#pragma unroll
        for (int c = 0; c < 4; c++) d[nt][c] = 0.f;

#pragma unroll
    for (int ks = 0; ks < 5; ks++) {
        const uint32_t ca = (uint32_t)(ks * 32) + loff;
        uint32_t ah[4], al[4];
        LDSM4(ah, sqh_b + (uint32_t)(w * 16) * (AT_STR * 2) + lrow + ca);
        LDSM4(al, sql_b + (uint32_t)(w * 16) * (AT_STR * 2) + lrow + ca);
#pragma unroll
        for (int nt2 = 0; nt2 < 5; nt2++) {
            uint32_t r4[4];
            LDSM4(r4, skh_b + (uint32_t)(nt2 * 16) * (AT_STR * 2) + lrow + ca);
            uint32_t b0[2] = {r4[0], r4[2]};
            uint32_t b1[2] = {r4[1], r4[3]};
            MMAF16(d[nt2 * 2 + 0], ah, b0);
            MMAF16(d[nt2 * 2 + 0], al, b0);
            MMAF16(d[nt2 * 2 + 1], ah, b1);
            MMAF16(d[nt2 * 2 + 1], al, b1);
        }
    }

    // ---- mask cols >= 77 ----
    {
        int colb = 72 + (lane & 3) * 2;
        if (colb >= 77)     { d[9][0] = -1e30f; d[9][2] = -1e30f; }
        if (colb + 1 >= 77) { d[9][1] = -1e30f; d[9][3] = -1e30f; }
    }

    // ---- softmax on fragments ----
    {
        float mA = -1e30f, mB = -1e30f;
#pragma unroll
        for (int nt = 0; nt < 10; nt++) {
            mA = fmaxf(mA, fmaxf(d[nt][0], d[nt][1]));
            mB = fmaxf(mB, fmaxf(d[nt][2], d[nt][3]));
        }
        mA = fmaxf(mA, __shfl_xor_sync(0xFFFFFFFFu, mA, 1));
        mA = fmaxf(mA, __shfl_xor_sync(0xFFFFFFFFu, mA, 2));
        mB = fmaxf(mB, __shfl_xor_sync(0xFFFFFFFFu, mB, 1));
        mB = fmaxf(mB, __shfl_xor_sync(0xFFFFFFFFu, mB, 2));
        float sA = 0.f, sB = 0.f;
#pragma unroll
        for (int nt = 0; nt < 10; nt++) {
            d[nt][0] = __expf(d[nt][0] - mA); sA += d[nt][0];
            d[nt][1] = __expf(d[nt][1] - mA); sA += d[nt][1];
            d[nt][2] = __expf(d[nt][2] - mB); sB += d[nt][2];
            d[nt][3] = __expf(d[nt][3] - mB); sB += d[nt][3];
        }
        sA += __shfl_xor_sync(0xFFFFFFFFu, sA, 1);
        sA += __shfl_xor_sync(0xFFFFFFFFu, sA, 2);
        sB += __shfl_xor_sync(0xFFFFFFFFu, sB, 1);
        sB += __shfl_xor_sync(0xFFFFFFFFu, sB, 2);
        float rA = 1.f / sA, rB = 1.f / sB;
#pragma unroll
        for (int nt = 0; nt < 10; nt++) {
            d[nt][0] *= rA; d[nt][1] *= rA;
            d[nt][2] *= rB; d[nt][3] *= rB;
        }
    }

    // ---- repack P to A-fragments ----
    uint32_t pa[5][4];
#pragma unroll
    for (int kp = 0; kp < 5; kp++) {
        pa[kp][0] = pack_f16x2(d[2 * kp][0],     d[2 * kp][1]);
        pa[kp][1] = pack_f16x2(d[2 * kp][2],     d[2 * kp][3]);
        pa[kp][2] = pack_f16x2(d[2 * kp + 1][0], d[2 * kp + 1][1]);
        pa[kp][3] = pack_f16x2(d[2 * kp + 1][2], d[2 * kp + 1][3]);
    }

    // ---- PV over V^T ----
    float o[10][4];
#pragma unroll
    for (int nt = 0; nt < 10; nt++)
#pragma unroll
        for (int c = 0; c < 4; c++) o[nt][c] = 0.f;

#pragma unroll
    for (int kp = 0; kp < 5; kp++) {
        const uint32_t ca = (uint32_t)(kp * 32) + loff;
#pragma unroll
        for (int nt2 = 0; nt2 < 5; nt2++) {
            uint32_t r4[4];
            LDSM4(r4, svt_b + (uint32_t)(nt2 * 16) * (AT_STR * 2) + lrow + ca);
            uint32_t b0[2] = {r4[0], r4[2]};
            uint32_t b1[2] = {r4[1], r4[3]};
            MMAF16(o[nt2 * 2 + 0], pa[kp], b0);
            MMAF16(o[nt2 * 2 + 1], pa[kp], b1);
        }
    }

    // ---- epilogue ----
    {
        const size_t rbase = (size_t)(b * SEQ_T + t0 + w * 16 + (lane >> 2));
        const int col = h * 80 + (lane & 3) * 2;
#pragma unroll
        for (int nt = 0; nt < 10; nt++) {
            *(uint32_t*)&ohi[rbase * EMBED + col + nt * 8] =
                pack_f16x2(o[nt][0], o[nt][1]);
            *(uint32_t*)&ohi[(rbase + 8) * EMBED + col + nt * 8] =
                pack_f16x2(o[nt][2], o[nt][3]);
        }
    }
}

// ---------------------------------------------------------------------------
extern "C" void kernel_launch(void* const* d_in, const int* in_sizes, int n_in,
                              void* d_out, int out_size) {
    const float* x  = (const float*)d_in[0];
    const float* y  = (const float*)d_in[1];
    const float* Wq = (const float*)d_in[2];
    const float* bq = (const float*)d_in[3];
    const float* Wk = (const float*)d_in[4];
    const float* bk = (const float*)d_in[5];
    const float* Wv = (const float*)d_in[6];
    const float* bv = (const float*)d_in[7];
    const float* Wo = (const float*)d_in[8];
    const float* bo = (const float*)d_in[9];
    float* out = (float*)d_out;

    unsigned short *xhi, *qhi, *qlo, *khi, *vhi, *yhi, *ylo, *wthi, *wtlo;
    cudaGetSymbolAddress((void**)&xhi, g_xhi);
    cudaGetSymbolAddress((void**)&qhi, g_qhi);
    cudaGetSymbolAddress((void**)&qlo, g_qlo);
    cudaGetSymbolAddress((void**)&khi, g_khi);
    cudaGetSymbolAddress((void**)&vhi, g_vhi);
    cudaGetSymbolAddress((void**)&yhi, g_yhi);
    cudaGetSymbolAddress((void**)&ylo, g_ylo);
    cudaGetSymbolAddress((void**)&wthi, g_wthi);
    cudaGetSymbolAddress((void**)&wtlo, g_wtlo);

    const int smem_attn = (128 * AT_STR * 2 + 80 * AT_STR * 2) * 2;  // 73216 B
    cudaFuncSetAttribute(attn_mma, cudaFuncAttributeMaxDynamicSharedMemorySize, smem_attn);
    const int smem_m3 = 3 * (int)SLOT3;  // 122880
    cudaFuncSetAttribute(gemm_mma3, cudaFuncAttributeMaxDynamicSharedMemorySize, smem_m3);
    const int smem_m1 = 4 * (int)SLOT1;  // 81920
    cudaFuncSetAttribute(gemm_mma1, cudaFuncAttributeMaxDynamicSharedMemorySize, smem_m1);
    cudaFuncSetAttribute(gemm_mma1q, cudaFuncAttributeMaxDynamicSharedMemorySize, smem_m1);

    const int NX = BATCH * SEQ_T * EMBED;      // 21.0M
    const int NY = BATCH * SEQ_S * CROSS;      // 473k
    const int MKV = BATCH * SEQ_S;             // 616

    // --- Q projection: fp16 1-term, outputs scaled q hi/lo fp16 ---
    conv_fp16_v<<<(NX / 8 + 255) / 256, 256>>>((const float4*)x, (uint4*)xhi, NX / 8);
    wconv_tr<<<dim3(EMBED / 32, EMBED / 32), dim3(32, 8)>>>(Wq, wthi, EMBED);
    {
        dim3 grid(EMBED / 128, (BATCH * SEQ_T) / 128);
        gemm_mma1q<<<grid, 256, smem_m1>>>(xhi, wthi, bq, qhi, qlo, BATCH * SEQ_T, EMBED);
    }

    // --- K/V projections: fp16 3-term (exact), fp16 outputs ---
    split_fp32_v<<<(NY / 8 + 255) / 256, 256>>>((const float4*)y, (uint4*)yhi, (uint4*)ylo, NY / 8);
    {
        dim3 grid(EMBED / 128, (MKV + 127) / 128);
        wsplit_tr<<<dim3(EMBED / 32, CROSS / 32), dim3(32, 8)>>>(Wk, wthi, wtlo, CROSS);
        gemm_mma3<<<grid, 256, smem_m3>>>(yhi, ylo, wthi, wtlo, bk, khi, MKV, CROSS);
        wsplit_tr<<<dim3(EMBED / 32, CROSS / 32), dim3(32, 8)>>>(Wv, wthi, wtlo, CROSS);
        gemm_mma3<<<grid, 256, smem_m3>>>(yhi, ylo, wthi, wtlo, bv, vhi, MKV, CROSS);
    }

    // --- attention on tensor cores (writes fp16 into xhi; x dead by now) ---
    {
        dim3 grid(SEQ_T / 128, N_HEADS, BATCH);
        attn_mma<<<grid, 256, smem_attn>>>(qhi, qlo, khi, vhi, xhi);
    }

    // --- O projection: fp16 1-term, fp32 output ---
    wconv_tr<<<dim3(EMBED / 32, EMBED / 32), dim3(32, 8)>>>(Wo, wthi, EMBED);
    {
        dim3 grid(EMBED / 128, (BATCH * SEQ_T) / 128);
        gemm_mma1<<<grid, 256, smem_m1>>>(xhi, wthi, bo, out, BATCH * SEQ_T, EMBED);
    }
}

// round 12
// speedup vs baseline: 5.9513x; 1.0351x over previous
#include <cuda_runtime.h>
#include <cuda_fp16.h>
#include <cstdint>
#include <math.h>

#define N_HEADS 8
#define EMBED 640
#define CROSS 768
#define HEAD 80
#define BATCH 8
#define SEQ_T 4096
#define SEQ_S 77

// ---------------------------------------------------------------------------
// Scratch (no cudaMalloc allowed)
// ---------------------------------------------------------------------------
__device__ __align__(16) unsigned short g_xhi[BATCH * SEQ_T * EMBED];  // x fp16 / attn-out fp16
__device__ __align__(16) unsigned short g_qhi[BATCH * SEQ_T * EMBED];  // scaled q hi
__device__ __align__(16) unsigned short g_qlo[BATCH * SEQ_T * EMBED];  // scaled q lo
__device__ __align__(16) unsigned short g_khi[BATCH * SEQ_S * EMBED];
__device__ __align__(16) unsigned short g_vhi[BATCH * SEQ_S * EMBED];
__device__ __align__(16) unsigned short g_yhi[BATCH * SEQ_S * CROSS];
__device__ __align__(16) unsigned short g_ylo[BATCH * SEQ_S * CROSS];
__device__ __align__(16) unsigned short g_wthi[EMBED * CROSS];
__device__ __align__(16) unsigned short g_wtlo[EMBED * CROSS];
__device__ __align__(16) unsigned short g_w2hi[EMBED * CROSS];
__device__ __align__(16) unsigned short g_w2lo[EMBED * CROSS];

// ---------------------------------------------------------------------------
// PTX helpers (non-'a' features only: ldmatrix, mma.sync, cp.async)
// ---------------------------------------------------------------------------
__device__ __forceinline__ uint32_t smem_to_u32(const void* smem_ptr) {
    uint32_t addr;
    asm("{ .reg .u64 tmp; cvta.to.shared.u64 tmp, %1; cvt.u32.u64 %0, tmp; }"
        : "=r"(addr) : "l"(smem_ptr));
    return addr;
}

#define LDSM4(r, addr) \
    asm volatile("ldmatrix.sync.aligned.m8n8.x4.shared.b16 {%0,%1,%2,%3},[%4];" \
        : "=r"((r)[0]), "=r"((r)[1]), "=r"((r)[2]), "=r"((r)[3]) : "r"(addr))

#define MMAF16(d, a, b) \
    asm volatile("mma.sync.aligned.m16n8k16.row.col.f32.f16.f16.f32 " \
        "{%0,%1,%2,%3},{%4,%5,%6,%7},{%8,%9},{%0,%1,%2,%3};" \
        : "+f"((d)[0]), "+f"((d)[1]), "+f"((d)[2]), "+f"((d)[3]) \
        : "r"((a)[0]), "r"((a)[1]), "r"((a)[2]), "r"((a)[3]), \
          "r"((b)[0]), "r"((b)[1]))

#define CP16(sp, gp) \
    asm volatile("cp.async.cg.shared.global [%0],[%1],16;" :: "r"(sp), "l"(gp))
#define CP_COMMIT() asm volatile("cp.async.commit_group;")
#define CP_WAIT2()  asm volatile("cp.async.wait_group 2;")
#define CP_WAIT1()  asm volatile("cp.async.wait_group 1;")
#define CP_WAIT0()  asm volatile("cp.async.wait_group 0;")

__device__ __forceinline__ unsigned short f16_hi(float f, float& rem) {
    __half h = __float2half_rn(f);
    rem = f - __half2float(h);
    return *(unsigned short*)&h;
}
__device__ __forceinline__ unsigned short f16_of(float f) {
    __half h = __float2half_rn(f);
    return *(unsigned short*)&h;
}
__device__ __forceinline__ uint32_t pack_f16x2(float lo, float hi) {
    uint32_t r;
    asm("cvt.rn.f16x2.f32 %0, %1, %2;" : "=r"(r) : "f"(hi), "f"(lo));
    return r;
}

// ---------------------------------------------------------------------------
// Vectorized FP32 -> fp16 convert (hi only): 8 elements per thread
// ---------------------------------------------------------------------------
__global__ void conv_fp16_v(const float4* __restrict__ in,
                            uint4* __restrict__ hi, int n8) {
    int i = blockIdx.x * blockDim.x + threadIdx.x;
    if (i >= n8) return;
    float4 a = in[2 * i];
    float4 b = in[2 * i + 1];
    uint4 hv;
    hv.x = (uint32_t)f16_of(a.x) | ((uint32_t)f16_of(a.y) << 16);
    hv.y = (uint32_t)f16_of(a.z) | ((uint32_t)f16_of(a.w) << 16);
    hv.z = (uint32_t)f16_of(b.x) | ((uint32_t)f16_of(b.y) << 16);
    hv.w = (uint32_t)f16_of(b.z) | ((uint32_t)f16_of(b.w) << 16);
    hi[i] = hv;
}

// Vectorized FP32 -> fp16 hi/lo split: 8 elements per thread (K/V inputs)
__global__ void split_fp32_v(const float4* __restrict__ in,
                             uint4* __restrict__ hi,
                             uint4* __restrict__ lo, int n8) {
    int i = blockIdx.x * blockDim.x + threadIdx.x;
    if (i >= n8) return;
    float4 a = in[2 * i];
    float4 b = in[2 * i + 1];
    float r[8];
    unsigned short h[8];
    h[0] = f16_hi(a.x, r[0]); h[1] = f16_hi(a.y, r[1]);
    h[2] = f16_hi(a.z, r[2]); h[3] = f16_hi(a.w, r[3]);
    h[4] = f16_hi(b.x, r[4]); h[5] = f16_hi(b.y, r[5]);
    h[6] = f16_hi(b.z, r[6]); h[7] = f16_hi(b.w, r[7]);
    uint4 hv, lv;
    hv.x = (uint32_t)h[0] | ((uint32_t)h[1] << 16);
    hv.y = (uint32_t)h[2] | ((uint32_t)h[3] << 16);
    hv.z = (uint32_t)h[4] | ((uint32_t)h[5] << 16);
    hv.w = (uint32_t)h[6] | ((uint32_t)h[7] << 16);
    lv.x = (uint32_t)f16_of(r[0]) | ((uint32_t)f16_of(r[1]) << 16);
    lv.y = (uint32_t)f16_of(r[2]) | ((uint32_t)f16_of(r[3]) << 16);
    lv.z = (uint32_t)f16_of(r[4]) | ((uint32_t)f16_of(r[5]) << 16);
    lv.w = (uint32_t)f16_of(r[6]) | ((uint32_t)f16_of(r[7]) << 16);
    hi[i] = hv;
    lo[i] = lv;
}

// ---------------------------------------------------------------------------
// Coalesced transpose + convert (hi only): W[K,640] -> Wt [640,K] fp16
// ---------------------------------------------------------------------------
__global__ void wconv_tr(const float* __restrict__ W,
                         unsigned short* __restrict__ thi, int K) {
    __shared__ float tile[32][33];
    const int tx = threadIdx.x, ty = threadIdx.y;
    const int n0 = blockIdx.x * 32;
    const int k0 = blockIdx.y * 32;
#pragma unroll
    for (int i = 0; i < 32; i += 8)
        tile[ty + i][tx] = W[(size_t)(k0 + ty + i) * EMBED + n0 + tx];
    __syncthreads();
#pragma unroll
    for (int i = 0; i < 32; i += 8) {
        size_t oi = (size_t)(n0 + ty + i) * K + k0 + tx;
        thi[oi] = f16_of(tile[tx][ty + i]);
    }
}

// Transpose + hi/lo split for TWO weights in one launch (z selects Wk / Wv)
__global__ void wsplit_tr2(const float* __restrict__ Wa,
                           const float* __restrict__ Wb,
                           unsigned short* __restrict__ ahi,
                           unsigned short* __restrict__ alo,
                           unsigned short* __restrict__ bhi,
                           unsigned short* __restrict__ blo, int K) {
    __shared__ float tile[32][33];
    const int tx = threadIdx.x, ty = threadIdx.y;
    const int n0 = blockIdx.x * 32;
    const int k0 = blockIdx.y * 32;
    const float* W = blockIdx.z ? Wb : Wa;
    unsigned short* thi = blockIdx.z ? bhi : ahi;
    unsigned short* tlo = blockIdx.z ? blo : alo;
#pragma unroll
    for (int i = 0; i < 32; i += 8)
        tile[ty + i][tx] = W[(size_t)(k0 + ty + i) * EMBED + n0 + tx];
    __syncthreads();
#pragma unroll
    for (int i = 0; i < 32; i += 8) {
        float v = tile[tx][ty + i];
        float rem;
        unsigned short h = f16_hi(v, rem);
        size_t oi = (size_t)(n0 + ty + i) * K + k0 + tx;
        thi[oi] = h;
        tlo[oi] = f16_of(rem);
    }
}

// ---------------------------------------------------------------------------
// Fused K+V projections: 3-term fp16 split GEMM, grid.z selects weight set.
// 3 slots, 2 preloads, single sync per stage.
// ---------------------------------------------------------------------------
#define SLOT3 40960u
__global__ __launch_bounds__(256, 1)
void gemm_mma3kv(const unsigned short* __restrict__ Ahi,
                 const unsigned short* __restrict__ Alo,
                 const unsigned short* __restrict__ Bhi0,
                 const unsigned short* __restrict__ Blo0,
                 const unsigned short* __restrict__ Bhi1,
                 const unsigned short* __restrict__ Blo1,
                 const float* __restrict__ bias0,
                 const float* __restrict__ bias1,
                 unsigned short* __restrict__ C0,
                 unsigned short* __restrict__ C1,
                 int M, int K) {
    extern __shared__ char smem[];
    const uint32_t sbase = smem_to_u32(smem);
    const int tid = threadIdx.x;
    const int lane = tid & 31;
    const int wid = tid >> 5;
    const int wm = wid >> 2;
    const int wn = wid & 3;
    const int bm = blockIdx.y * 128;
    const int bn = blockIdx.x * 128;
    const int rowU4 = K >> 3;
    const int nst = K >> 5;
    const int maxAr = (M - bm - 1 < 127) ? (M - bm - 1) : 127;

    const unsigned short* Bhi = blockIdx.z ? Bhi1 : Bhi0;
    const unsigned short* Blo = blockIdx.z ? Blo1 : Blo0;
    const float* bias = blockIdx.z ? bias1 : bias0;
    unsigned short* C16 = blockIdx.z ? C1 : C0;

    const uint4* gA0 = (const uint4*)(Ahi + (size_t)bm * K);
    const uint4* gA1 = (const uint4*)(Alo + (size_t)bm * K);
    const uint4* gB0 = (const uint4*)(Bhi + (size_t)bn * K);
    const uint4* gB1 = (const uint4*)(Blo + (size_t)bn * K);

    float d[4][4][4];
#pragma unroll
    for (int i = 0; i < 4; i++)
#pragma unroll
        for (int j = 0; j < 4; j++)
#pragma unroll
            for (int r = 0; r < 4; r++) d[i][j][r] = 0.f;

    auto load_stage = [&](int slot, int kt) {
        uint32_t sb = sbase + (uint32_t)slot * SLOT3;
#pragma unroll
        for (int j = 0; j < 8; j++) {
            int gidx = j * 256 + tid;
            int term = gidx >> 9;
            int idx = gidx & 511;
            int r = idx >> 2;
            int c = idx & 3;
            int re = (term < 2 && r > maxAr) ? maxAr : r;
            const uint4* src = (term == 0) ? gA0 : (term == 1) ? gA1
                             : (term == 2) ? gB0 : gB1;
            const uint4* gp = src + (size_t)re * rowU4 + kt * 4 + c;
            uint32_t sp = sb + (uint32_t)term * 10240u
                        + (uint32_t)(r * 80 + c * 16);
            CP16(sp, gp);
        }
        CP_COMMIT();
    };

    auto compute_stage = [&](int slot) {
        uint32_t sb = sbase + (uint32_t)slot * SLOT3;
        const uint32_t aOff[2] = {sb, sb + 10240u};
        const uint32_t bOff[2] = {sb + 20480u, sb + 30720u};
#pragma unroll
        for (int kk = 0; kk < 2; kk++) {
            const uint32_t colB = (uint32_t)(kk * 32) + ((lane & 16) ? 16u : 0u);
            uint32_t ah[4][4], al[4][4];
#pragma unroll
            for (int mt = 0; mt < 4; mt++) {
                int row = wm * 64 + mt * 16 + (lane & 15);
                LDSM4(ah[mt], aOff[0] + (uint32_t)(row * 80) + colB);
                LDSM4(al[mt], aOff[1] + (uint32_t)(row * 80) + colB);
            }
            uint32_t bh[4][2], bl[4][2];
#pragma unroll
            for (int nt2 = 0; nt2 < 2; nt2++) {
                int row = wn * 32 + nt2 * 16 + (lane & 15);
                uint32_t r4[4];
                LDSM4(r4, bOff[0] + (uint32_t)(row * 80) + colB);
                bh[nt2 * 2 + 0][0] = r4[0]; bh[nt2 * 2 + 0][1] = r4[2];
                bh[nt2 * 2 + 1][0] = r4[1]; bh[nt2 * 2 + 1][1] = r4[3];
                LDSM4(r4, bOff[1] + (uint32_t)(row * 80) + colB);
                bl[nt2 * 2 + 0][0] = r4[0]; bl[nt2 * 2 + 0][1] = r4[2];
                bl[nt2 * 2 + 1][0] = r4[1]; bl[nt2 * 2 + 1][1] = r4[3];
            }
#pragma unroll
            for (int mt = 0; mt < 4; mt++)
#pragma unroll
                for (int nt = 0; nt < 4; nt++) {
                    MMAF16(d[mt][nt], ah[mt], bh[nt]);
                    MMAF16(d[mt][nt], ah[mt], bl[nt]);
                    MMAF16(d[mt][nt], al[mt], bh[nt]);
                }
        }
    };

    load_stage(0, 0);
    load_stage(1, 1);
    for (int s = 0; s < nst; s++) {
        if (s + 1 < nst) { CP_WAIT1(); } else { CP_WAIT0(); }
        __syncthreads();
        if (s + 2 < nst) load_stage((s + 2) % 3, s + 2);
        compute_stage(s % 3);
    }

#pragma unroll
    for (int mt = 0; mt < 4; mt++) {
        int row0 = bm + wm * 64 + mt * 16 + (lane >> 2);
#pragma unroll
        for (int nt = 0; nt < 4; nt++) {
            int col = bn + wn * 32 + nt * 8 + (lane & 3) * 2;
            float2 bv = *(const float2*)&bias[col];
            if (row0 < M) {
                uint32_t p = (uint32_t)f16_of(d[mt][nt][0] + bv.x)
                           | ((uint32_t)f16_of(d[mt][nt][1] + bv.y) << 16);
                *(uint32_t*)&C16[(size_t)row0 * EMBED + col] = p;
            }
            if (row0 + 8 < M) {
                uint32_t p = (uint32_t)f16_of(d[mt][nt][2] + bv.x)
                           | ((uint32_t)f16_of(d[mt][nt][3] + bv.y) << 16);
                *(uint32_t*)&C16[(size_t)(row0 + 8) * EMBED + col] = p;
            }
        }
    }
}

// ---------------------------------------------------------------------------
// 1-term fp16 GEMM core: 4 slots, 3 preloads, single sync per stage, occ 2.
// ---------------------------------------------------------------------------
#define SLOT1 20480u
template <int OUT16>
__device__ __forceinline__ void gemm1_body(
    const unsigned short* __restrict__ Ah,
    const unsigned short* __restrict__ Bh,
    const float* __restrict__ bias, float* __restrict__ C,
    unsigned short* __restrict__ Chi, unsigned short* __restrict__ Clo,
    float oscale, int M, int K, char* smem) {
    const uint32_t sbase = smem_to_u32(smem);
    const int tid = threadIdx.x;
    const int lane = tid & 31;
    const int wid = tid >> 5;
    const int wm = wid >> 2;
    const int wn = wid & 3;
    const int bm = blockIdx.y * 128;
    const int bn = blockIdx.x * 128;
    const int rowU4 = K >> 3;
    const int nst = K >> 5;

    const uint4* gA0 = (const uint4*)(Ah + (size_t)bm * K);
    const uint4* gB0 = (const uint4*)(Bh + (size_t)bn * K);

    float d[4][4][4];
#pragma unroll
    for (int i = 0; i < 4; i++)
#pragma unroll
        for (int j = 0; j < 4; j++)
#pragma unroll
            for (int r = 0; r < 4; r++) d[i][j][r] = 0.f;

    auto load_stage = [&](int slot, int kt) {
        uint32_t sb = sbase + (uint32_t)slot * SLOT1;
#pragma unroll
        for (int j = 0; j < 4; j++) {
            int gidx = j * 256 + tid;
            int term = gidx >> 9;
            int idx = gidx & 511;
            int r = idx >> 2;
            int c = idx & 3;
            const uint4* src = (term == 0) ? gA0 : gB0;
            const uint4* gp = src + (size_t)r * rowU4 + kt * 4 + c;
            uint32_t sp = sb + (uint32_t)term * 10240u
                        + (uint32_t)(r * 80 + c * 16);
            CP16(sp, gp);
        }
        CP_COMMIT();
    };

    auto compute_stage = [&](int slot) {
        uint32_t sb = sbase + (uint32_t)slot * SLOT1;
        const uint32_t aOff = sb;
        const uint32_t bOff = sb + 10240u;
#pragma unroll
        for (int kk = 0; kk < 2; kk++) {
            const uint32_t colB = (uint32_t)(kk * 32) + ((lane & 16) ? 16u : 0u);
            uint32_t ah[4][4];
#pragma unroll
            for (int mt = 0; mt < 4; mt++) {
                int row = wm * 64 + mt * 16 + (lane & 15);
                LDSM4(ah[mt], aOff + (uint32_t)(row * 80) + colB);
            }
            uint32_t bh[4][2];
#pragma unroll
            for (int nt2 = 0; nt2 < 2; nt2++) {
                int row = wn * 32 + nt2 * 16 + (lane & 15);
                uint32_t r4[4];
                LDSM4(r4, bOff + (uint32_t)(row * 80) + colB);
                bh[nt2 * 2 + 0][0] = r4[0]; bh[nt2 * 2 + 0][1] = r4[2];
                bh[nt2 * 2 + 1][0] = r4[1]; bh[nt2 * 2 + 1][1] = r4[3];
            }
#pragma unroll
            for (int mt = 0; mt < 4; mt++)
#pragma unroll
                for (int nt = 0; nt < 4; nt++)
                    MMAF16(d[mt][nt], ah[mt], bh[nt]);
        }
    };

    load_stage(0, 0);
    load_stage(1, 1);
    load_stage(2, 2);
    for (int s = 0; s < nst; s++) {
        if (s + 2 < nst) { CP_WAIT2(); }
        else if (s + 1 < nst) { CP_WAIT1(); }
        else { CP_WAIT0(); }
        __syncthreads();
        if (s + 3 < nst) load_stage((s + 3) & 3, s + 3);
        compute_stage(s & 3);
    }

#pragma unroll
    for (int mt = 0; mt < 4; mt++) {
        int row0 = bm + wm * 64 + mt * 16 + (lane >> 2);
#pragma unroll
        for (int nt = 0; nt < 4; nt++) {
            int col = bn + wn * 32 + nt * 8 + (lane & 3) * 2;
            float2 bv = *(const float2*)&bias[col];
#pragma unroll
            for (int half = 0; half < 2; half++) {
                int row = row0 + half * 8;
                float v0 = (d[mt][nt][half * 2 + 0] + bv.x) * oscale;
                float v1 = (d[mt][nt][half * 2 + 1] + bv.y) * oscale;
                if (OUT16) {
                    float r0, r1;
                    unsigned short h0 = f16_hi(v0, r0);
                    unsigned short h1 = f16_hi(v1, r1);
                    *(uint32_t*)&Chi[(size_t)row * EMBED + col] =
                        (uint32_t)h0 | ((uint32_t)h1 << 16);
                    *(uint32_t*)&Clo[(size_t)row * EMBED + col] =
                        (uint32_t)f16_of(r0) | ((uint32_t)f16_of(r1) << 16);
                } else {
                    *(float2*)&C[(size_t)row * EMBED + col] = make_float2(v0, v1);
                }
            }
        }
    }
}

// O projection: fp32 output
__global__ __launch_bounds__(256, 2)
void gemm_mma1(const unsigned short* __restrict__ Ah,
               const unsigned short* __restrict__ Bh,
               const float* __restrict__ bias, float* __restrict__ C,
               int M, int K) {
    extern __shared__ char smem[];
    gemm1_body<0>(Ah, Bh, bias, C, nullptr, nullptr, 1.0f, M, K, smem);
}

// Q projection: scaled fp16 hi/lo output
__global__ __launch_bounds__(256, 2)
void gemm_mma1q(const unsigned short* __restrict__ Ah,
                const unsigned short* __restrict__ Bh,
                const float* __restrict__ bias,
                unsigned short* __restrict__ Chi,
                unsigned short* __restrict__ Clo,
                int M, int K) {
    extern __shared__ char smem[];
    gemm1_body<1>(Ah, Bh, bias, nullptr, Chi, Clo,
                  0.11180339887498949f, M, K, smem);
}

// ---------------------------------------------------------------------------
// Tensor-core attention: block = 64 t-rows x one (b,h), 4 warps x 16 rows.
// Smaller blocks -> ~3 CTAs/SM for latency hiding through the serial phases.
// ---------------------------------------------------------------------------
#define AT_STR 88
#define AT_T 128
__global__ __launch_bounds__(AT_T)
void attn_mma(const unsigned short* __restrict__ qhi,
              const unsigned short* __restrict__ qlo,
              const unsigned short* __restrict__ khi,
              const unsigned short* __restrict__ vhi,
              unsigned short* __restrict__ ohi) {
    extern __shared__ unsigned short smh[];
    unsigned short* sqh = smh;                    // 64*88
    unsigned short* sql = sqh + 64 * AT_STR;      // 64*88
    unsigned short* skh = sql + 64 * AT_STR;      // 80*88
    unsigned short* svt = skh + 80 * AT_STR;      // 80*88 (d rows, s cols)

    const int b = blockIdx.z;
    const int h = blockIdx.y;
    const int t0 = blockIdx.x * 64;
    const int tid = threadIdx.x;
    const int w = tid >> 5;
    const int lane = tid & 31;

    // ---- zero pads ----
    for (int i = tid; i < 3 * AT_STR; i += AT_T)
        skh[77 * AT_STR + i] = 0;
    for (int i = tid; i < 240; i += AT_T)
        svt[(i / 3) * AT_STR + 77 + (i % 3)] = 0;

    // ---- staging ----
    for (int i = tid; i < 640; i += AT_T) {       // q hi/lo: 64 rows x 10 uint4
        int t = i / 10, c = i - t * 10;
        size_t gi = ((size_t)(b * SEQ_T + t0 + t)) * 80 + h * 10 + c;
        *(uint4*)&sqh[t * AT_STR + c * 8] = ((const uint4*)qhi)[gi];
        *(uint4*)&sql[t * AT_STR + c * 8] = ((const uint4*)qlo)[gi];
    }
    for (int i = tid; i < 770; i += AT_T) {       // k: 77 rows x 10 uint4
        int s = i / 10, c = i - s * 10;
        size_t gi = ((size_t)(b * SEQ_S + s)) * 80 + h * 10 + c;
        *(uint4*)&skh[s * AT_STR + c * 8] = ((const uint4*)khi)[gi];
    }
    for (int i = tid; i < SEQ_S * 80; i += AT_T) { // v transpose -> svt[d][s]
        int s = i / 80, dd = i - s * 80;
        svt[dd * AT_STR + s] = vhi[((size_t)(b * SEQ_S + s)) * EMBED + h * 80 + dd];
    }
    __syncthreads();

    const uint32_t sqh_b = smem_to_u32(sqh);
    const uint32_t sql_b = smem_to_u32(sql);
    const uint32_t skh_b = smem_to_u32(skh);
    const uint32_t svt_b = smem_to_u32(svt);
    const uint32_t lrow = (uint32_t)(lane & 15) * (AT_STR * 2);
    const uint32_t loff = (lane & 16) ? 16u : 0u;

    // ---- QK^T ----
    float d[10][4];
#pragma unroll
    for (int nt = 0; nt < 10; nt++)
#pragma unroll
        for (int c = 0; c < 4; c++) d[nt][c] = 0.f;

#pragma unroll
    for (int ks = 0; ks < 5; ks++) {
        const uint32_t ca = (uint32_t)(ks * 32) + loff;
        uint32_t ah[4], al[4];
        LDSM4(ah, sqh_b + (uint32_t)(w * 16) * (AT_STR * 2) + lrow + ca);
        LDSM4(al, sql_b + (uint32_t)(w * 16) * (AT_STR * 2) + lrow + ca);
#pragma unroll
        for (int nt2 = 0; nt2 < 5; nt2++) {
            uint32_t r4[4];
            LDSM4(r4, skh_b + (uint32_t)(nt2 * 16) * (AT_STR * 2) + lrow + ca);
            uint32_t b0[2] = {r4[0], r4[2]};
            uint32_t b1[2] = {r4[1], r4[3]};
            MMAF16(d[nt2 * 2 + 0], ah, b0);
            MMAF16(d[nt2 * 2 + 0], al, b0);
            MMAF16(d[nt2 * 2 + 1], ah, b1);
            MMAF16(d[nt2 * 2 + 1], al, b1);
        }
    }

    // ---- mask cols >= 77 ----
    {
        int colb = 72 + (lane & 3) * 2;
        if (colb >= 77)     { d[9][0] = -1e30f; d[9][2] = -1e30f; }
        if (colb + 1 >= 77) { d[9][1] = -1e30f; d[9][3] = -1e30f; }
    }

    // ---- softmax on fragments ----
    {
        float mA = -1e30f, mB = -1e30f;
#pragma unroll
        for (int nt = 0; nt < 10; nt++) {
            mA = fmaxf(mA, fmaxf(d[nt][0], d[nt][1]));
            mB = fmaxf(mB, fmaxf(d[nt][2], d[nt][3]));
        }
        mA = fmaxf(mA, __shfl_xor_sync(0xFFFFFFFFu, mA, 1));
        mA = fmaxf(mA, __shfl_xor_sync(0xFFFFFFFFu, mA, 2));
        mB = fmaxf(mB, __shfl_xor_sync(0xFFFFFFFFu, mB, 1));
        mB = fmaxf(mB, __shfl_xor_sync(0xFFFFFFFFu, mB, 2));
        float sA = 0.f, sB = 0.f;
#pragma unroll
        for (int nt = 0; nt < 10; nt++) {
            d[nt][0] = __expf(d[nt][0] - mA); sA += d[nt][0];
            d[nt][1] = __expf(d[nt][1] - mA); sA += d[nt][1];
            d[nt][2] = __expf(d[nt][2] - mB); sB += d[nt][2];
            d[nt][3] = __expf(d[nt][3] - mB); sB += d[nt][3];
        }
        sA += __shfl_xor_sync(0xFFFFFFFFu, sA, 1);
        sA += __shfl_xor_sync(0xFFFFFFFFu, sA, 2);
        sB += __shfl_xor_sync(0xFFFFFFFFu, sB, 1);
        sB += __shfl_xor_sync(0xFFFFFFFFu, sB, 2);
        float rA = 1.f / sA, rB = 1.f / sB;
#pragma unroll
        for (int nt = 0; nt < 10; nt++) {
            d[nt][0] *= rA; d[nt][1] *= rA;
            d[nt][2] *= rB; d[nt][3] *= rB;
        }
    }

    // ---- repack P to A-fragments ----
    uint32_t pa[5][4];
#pragma unroll
    for (int kp = 0; kp < 5; kp++) {
        pa[kp][0] = pack_f16x2(d[2 * kp][0],     d[2 * kp][1]);
        pa[kp][1] = pack_f16x2(d[2 * kp][2],     d[2 * kp][3]);
        pa[kp][2] = pack_f16x2(d[2 * kp + 1][0], d[2 * kp + 1][1]);
        pa[kp][3] = pack_f16x2(d[2 * kp + 1][2], d[2 * kp + 1][3]);
    }

    // ---- PV over V^T ----
    float o[10][4];
#pragma unroll
    for (int nt = 0; nt < 10; nt++)
#pragma unroll
        for (int c = 0; c < 4; c++) o[nt][c] = 0.f;

#pragma unroll
    for (int kp = 0; kp < 5; kp++) {
        const uint32_t ca = (uint32_t)(kp * 32) + loff;
#pragma unroll
        for (int nt2 = 0; nt2 < 5; nt2++) {
            uint32_t r4[4];
            LDSM4(r4, svt_b + (uint32_t)(nt2 * 16) * (AT_STR * 2) + lrow + ca);
            uint32_t b0[2] = {r4[0], r4[2]};
            uint32_t b1[2] = {r4[1], r4[3]};
            MMAF16(o[nt2 * 2 + 0], pa[kp], b0);
            MMAF16(o[nt2 * 2 + 1], pa[kp], b1);
        }
    }

    // ---- epilogue ----
    {
        const size_t rbase = (size_t)(b * SEQ_T + t0 + w * 16 + (lane >> 2));
        const int col = h * 80 + (lane & 3) * 2;
#pragma unroll
        for (int nt = 0; nt < 10; nt++) {
            *(uint32_t*)&ohi[rbase * EMBED + col + nt * 8] =
                pack_f16x2(o[nt][0], o[nt][1]);
            *(uint32_t*)&ohi[(rbase + 8) * EMBED + col + nt * 8] =
                pack_f16x2(o[nt][2], o[nt][3]);
        }
    }
}

// ---------------------------------------------------------------------------
extern "C" void kernel_launch(void* const* d_in, const int* in_sizes, int n_in,
                              void* d_out, int out_size) {
    const float* x  = (const float*)d_in[0];
    const float* y  = (const float*)d_in[1];
    const float* Wq = (const float*)d_in[2];
    const float* bq = (const float*)d_in[3];
    const float* Wk = (const float*)d_in[4];
    const float* bk = (const float*)d_in[5];
    const float* Wv = (const float*)d_in[6];
    const float* bv = (const float*)d_in[7];
    const float* Wo = (const float*)d_in[8];
    const float* bo = (const float*)d_in[9];
    float* out = (float*)d_out;

    unsigned short *xhi, *qhi, *qlo, *khi, *vhi, *yhi, *ylo;
    unsigned short *wthi, *wtlo, *w2hi, *w2lo;
    cudaGetSymbolAddress((void**)&xhi, g_xhi);
    cudaGetSymbolAddress((void**)&qhi, g_qhi);
    cudaGetSymbolAddress((void**)&qlo, g_qlo);
    cudaGetSymbolAddress((void**)&khi, g_khi);
    cudaGetSymbolAddress((void**)&vhi, g_vhi);
    cudaGetSymbolAddress((void**)&yhi, g_yhi);
    cudaGetSymbolAddress((void**)&ylo, g_ylo);
    cudaGetSymbolAddress((void**)&wthi, g_wthi);
    cudaGetSymbolAddress((void**)&wtlo, g_wtlo);
    cudaGetSymbolAddress((void**)&w2hi, g_w2hi);
    cudaGetSymbolAddress((void**)&w2lo, g_w2lo);

    const int smem_attn = (64 * AT_STR * 2 + 80 * AT_STR * 2) * 2;  // 50688 B
    cudaFuncSetAttribute(attn_mma, cudaFuncAttributeMaxDynamicSharedMemorySize, smem_attn);
    const int smem_m3 = 3 * (int)SLOT3;  // 122880
    cudaFuncSetAttribute(gemm_mma3kv, cudaFuncAttributeMaxDynamicSharedMemorySize, smem_m3);
    const int smem_m1 = 4 * (int)SLOT1;  // 81920
    cudaFuncSetAttribute(gemm_mma1, cudaFuncAttributeMaxDynamicSharedMemorySize, smem_m1);
    cudaFuncSetAttribute(gemm_mma1q, cudaFuncAttributeMaxDynamicSharedMemorySize, smem_m1);

    const int NX = BATCH * SEQ_T * EMBED;      // 21.0M
    const int NY = BATCH * SEQ_S * CROSS;      // 473k
    const int MKV = BATCH * SEQ_S;             // 616

    // --- Q projection: fp16 1-term, outputs scaled q hi/lo fp16 ---
    conv_fp16_v<<<(NX / 8 + 255) / 256, 256>>>((const float4*)x, (uint4*)xhi, NX / 8);
    wconv_tr<<<dim3(EMBED / 32, EMBED / 32), dim3(32, 8)>>>(Wq, wthi, EMBED);
    {
        dim3 grid(EMBED / 128, (BATCH * SEQ_T) / 128);
        gemm_mma1q<<<grid, 256, smem_m1>>>(xhi, wthi, bq, qhi, qlo, BATCH * SEQ_T, EMBED);
    }

    // --- K/V projections fused: one transpose launch, one GEMM launch ---
    split_fp32_v<<<(NY / 8 + 255) / 256, 256>>>((const float4*)y, (uint4*)yhi, (uint4*)ylo, NY / 8);
    wsplit_tr2<<<dim3(EMBED / 32, CROSS / 32, 2), dim3(32, 8)>>>(
        Wk, Wv, wthi, wtlo, w2hi, w2lo, CROSS);
    {
        dim3 grid(EMBED / 128, (MKV + 127) / 128, 2);
        gemm_mma3kv<<<grid, 256, smem_m3>>>(yhi, ylo, wthi, wtlo, w2hi, w2lo,
                                            bk, bv, khi, vhi, MKV, CROSS);
    }

    // --- attention on tensor cores (writes fp16 into xhi; x dead by now) ---
    {
        dim3 grid(SEQ_T / 64, N_HEADS, BATCH);
        attn_mma<<<grid, AT_T, smem_attn>>>(qhi, qlo, khi, vhi, xhi);
    }

    // --- O projection: fp16 1-term, fp32 output ---
    wconv_tr<<<dim3(EMBED / 32, EMBED / 32), dim3(32, 8)>>>(Wo, wthi, EMBED);
    {
        dim3 grid(EMBED / 128, (BATCH * SEQ_T) / 128);
        gemm_mma1<<<grid, 256, smem_m1>>>(xhi, wthi, bo, out, BATCH * SEQ_T, EMBED);
    }
}

// round 13
// speedup vs baseline: 6.0320x; 1.0136x over previous
#include <cuda_runtime.h>
#include <cuda_fp16.h>
#include <cstdint>
#include <math.h>

#define N_HEADS 8
#define EMBED 640
#define CROSS 768
#define HEAD 80
#define BATCH 8
#define SEQ_T 4096
#define SEQ_S 77

// ---------------------------------------------------------------------------
// Scratch (no cudaMalloc allowed)
// ---------------------------------------------------------------------------
__device__ __align__(16) unsigned short g_xhi[BATCH * SEQ_T * EMBED];  // x fp16 / attn-out fp16
__device__ __align__(16) unsigned short g_qhi[BATCH * SEQ_T * EMBED];  // scaled q hi
__device__ __align__(16) unsigned short g_qlo[BATCH * SEQ_T * EMBED];  // scaled q lo
__device__ __align__(16) unsigned short g_khi[BATCH * SEQ_S * EMBED];
__device__ __align__(16) unsigned short g_vhi[BATCH * SEQ_S * EMBED];
__device__ __align__(16) unsigned short g_yhi[BATCH * SEQ_S * CROSS];
__device__ __align__(16) unsigned short g_ylo[BATCH * SEQ_S * CROSS];
__device__ __align__(16) unsigned short g_wq[EMBED * EMBED];
__device__ __align__(16) unsigned short g_wo[EMBED * EMBED];
__device__ __align__(16) unsigned short g_wkhi[EMBED * CROSS];
__device__ __align__(16) unsigned short g_wklo[EMBED * CROSS];
__device__ __align__(16) unsigned short g_wvhi[EMBED * CROSS];
__device__ __align__(16) unsigned short g_wvlo[EMBED * CROSS];

// ---------------------------------------------------------------------------
// PTX helpers (non-'a' features only: ldmatrix, mma.sync, cp.async)
// ---------------------------------------------------------------------------
__device__ __forceinline__ uint32_t smem_to_u32(const void* smem_ptr) {
    uint32_t addr;
    asm("{ .reg .u64 tmp; cvta.to.shared.u64 tmp, %1; cvt.u32.u64 %0, tmp; }"
        : "=r"(addr) : "l"(smem_ptr));
    return addr;
}

#define LDSM4(r, addr) \
    asm volatile("ldmatrix.sync.aligned.m8n8.x4.shared.b16 {%0,%1,%2,%3},[%4];" \
        : "=r"((r)[0]), "=r"((r)[1]), "=r"((r)[2]), "=r"((r)[3]) : "r"(addr))

#define MMAF16(d, a, b) \
    asm volatile("mma.sync.aligned.m16n8k16.row.col.f32.f16.f16.f32 " \
        "{%0,%1,%2,%3},{%4,%5,%6,%7},{%8,%9},{%0,%1,%2,%3};" \
        : "+f"((d)[0]), "+f"((d)[1]), "+f"((d)[2]), "+f"((d)[3]) \
        : "r"((a)[0]), "r"((a)[1]), "r"((a)[2]), "r"((a)[3]), \
          "r"((b)[0]), "r"((b)[1]))

#define CP16(sp, gp) \
    asm volatile("cp.async.cg.shared.global [%0],[%1],16;" :: "r"(sp), "l"(gp))
#define CP_COMMIT() asm volatile("cp.async.commit_group;")
#define CP_WAIT2()  asm volatile("cp.async.wait_group 2;")
#define CP_WAIT1()  asm volatile("cp.async.wait_group 1;")
#define CP_WAIT0()  asm volatile("cp.async.wait_group 0;")

__device__ __forceinline__ unsigned short f16_hi(float f, float& rem) {
    __half h = __float2half_rn(f);
    rem = f - __half2float(h);
    return *(unsigned short*)&h;
}
__device__ __forceinline__ unsigned short f16_of(float f) {
    __half h = __float2half_rn(f);
    return *(unsigned short*)&h;
}
__device__ __forceinline__ uint32_t pack_f16x2(float lo, float hi) {
    uint32_t r;
    asm("cvt.rn.f16x2.f32 %0, %1, %2;" : "=r"(r) : "f"(hi), "f"(lo));
    return r;
}

// ---------------------------------------------------------------------------
// Fused preprocessing: one launch does
//   [0, 10240)        : x fp32 -> fp16 (hi only), 8 elems/thread
//   [10240, 10471)    : y fp32 -> fp16 hi/lo split
//   [10471, 10871)    : Wq transpose+convert (hi)      -> g_wq
//   [10871, 11831)    : Wk/Wv transpose+split (hi/lo)  -> g_wk*, g_wv*
//   [11831, 12231)    : Wo transpose+convert (hi)      -> g_wo
// ---------------------------------------------------------------------------
#define PREP_XB   10240
#define PREP_YB   231
#define PREP_WQB  400   // 20 n-tiles x 20 k-tiles
#define PREP_WKVB 960   // 20 x 24 x 2
#define PREP_WOB  400
__global__ void prep_all(const float4* __restrict__ x4,
                         const float4* __restrict__ y4,
                         const float* __restrict__ Wq,
                         const float* __restrict__ Wk,
                         const float* __restrict__ Wv,
                         const float* __restrict__ Wo,
                         uint4* __restrict__ xhi,
                         uint4* __restrict__ yhi, uint4* __restrict__ ylo,
                         unsigned short* __restrict__ wq,
                         unsigned short* __restrict__ wkhi, unsigned short* __restrict__ wklo,
                         unsigned short* __restrict__ wvhi, unsigned short* __restrict__ wvlo,
                         unsigned short* __restrict__ wo) {
    __shared__ float tile[32][33];
    const int blk = blockIdx.x;
    const int tid = threadIdx.x;

    if (blk < PREP_XB) {
        // x convert (hi only)
        int i = blk * 256 + tid;
        float4 a = x4[2 * i];
        float4 b = x4[2 * i + 1];
        uint4 hv;
        hv.x = (uint32_t)f16_of(a.x) | ((uint32_t)f16_of(a.y) << 16);
        hv.y = (uint32_t)f16_of(a.z) | ((uint32_t)f16_of(a.w) << 16);
        hv.z = (uint32_t)f16_of(b.x) | ((uint32_t)f16_of(b.y) << 16);
        hv.w = (uint32_t)f16_of(b.z) | ((uint32_t)f16_of(b.w) << 16);
        xhi[i] = hv;
        return;
    }
    if (blk < PREP_XB + PREP_YB) {
        // y hi/lo split
        int i = (blk - PREP_XB) * 256 + tid;
        float4 a = y4[2 * i];
        float4 b = y4[2 * i + 1];
        float r[8];
        unsigned short h[8];
        h[0] = f16_hi(a.x, r[0]); h[1] = f16_hi(a.y, r[1]);
        h[2] = f16_hi(a.z, r[2]); h[3] = f16_hi(a.w, r[3]);
        h[4] = f16_hi(b.x, r[4]); h[5] = f16_hi(b.y, r[5]);
        h[6] = f16_hi(b.z, r[6]); h[7] = f16_hi(b.w, r[7]);
        uint4 hv, lv;
        hv.x = (uint32_t)h[0] | ((uint32_t)h[1] << 16);
        hv.y = (uint32_t)h[2] | ((uint32_t)h[3] << 16);
        hv.z = (uint32_t)h[4] | ((uint32_t)h[5] << 16);
        hv.w = (uint32_t)h[6] | ((uint32_t)h[7] << 16);
        lv.x = (uint32_t)f16_of(r[0]) | ((uint32_t)f16_of(r[1]) << 16);
        lv.y = (uint32_t)f16_of(r[2]) | ((uint32_t)f16_of(r[3]) << 16);
        lv.z = (uint32_t)f16_of(r[4]) | ((uint32_t)f16_of(r[5]) << 16);
        lv.w = (uint32_t)f16_of(r[6]) | ((uint32_t)f16_of(r[7]) << 16);
        yhi[i] = hv;
        ylo[i] = lv;
        return;
    }

    // transpose paths: flat 256 threads -> (tx, ty)
    const int tx = tid & 31;
    const int ty = tid >> 5;

    const float* W;
    unsigned short *thi, *tlo = nullptr;
    int K, t;
    if (blk < PREP_XB + PREP_YB + PREP_WQB) {
        t = blk - (PREP_XB + PREP_YB);
        W = Wq; thi = wq; K = EMBED;
    } else if (blk < PREP_XB + PREP_YB + PREP_WQB + PREP_WKVB) {
        t = blk - (PREP_XB + PREP_YB + PREP_WQB);
        int z = t / 480;
        t = t % 480;
        W = z ? Wv : Wk;
        thi = z ? wvhi : wkhi;
        tlo = z ? wvlo : wklo;
        K = CROSS;
    } else {
        t = blk - (PREP_XB + PREP_YB + PREP_WQB + PREP_WKVB);
        W = Wo; thi = wo; K = EMBED;
    }
    const int n0 = (t % 20) * 32;        // EMBED/32 = 20 n-tiles
    const int k0 = (t / 20) * 32;
#pragma unroll
    for (int i = 0; i < 32; i += 8)
        tile[ty + i][tx] = W[(size_t)(k0 + ty + i) * EMBED + n0 + tx];
    __syncthreads();
#pragma unroll
    for (int i = 0; i < 32; i += 8) {
        float v = tile[tx][ty + i];
        size_t oi = (size_t)(n0 + ty + i) * K + k0 + tx;
        if (tlo) {
            float rem;
            unsigned short h = f16_hi(v, rem);
            thi[oi] = h;
            tlo[oi] = f16_of(rem);
        } else {
            thi[oi] = f16_of(v);
        }
    }
}

// ---------------------------------------------------------------------------
// Fused K+V projections: 3-term fp16 split GEMM, grid.z selects weight set.
// 3 slots, 2 preloads, single sync per stage.
// ---------------------------------------------------------------------------
#define SLOT3 40960u
__global__ __launch_bounds__(256, 1)
void gemm_mma3kv(const unsigned short* __restrict__ Ahi,
                 const unsigned short* __restrict__ Alo,
                 const unsigned short* __restrict__ Bhi0,
                 const unsigned short* __restrict__ Blo0,
                 const unsigned short* __restrict__ Bhi1,
                 const unsigned short* __restrict__ Blo1,
                 const float* __restrict__ bias0,
                 const float* __restrict__ bias1,
                 unsigned short* __restrict__ C0,
                 unsigned short* __restrict__ C1,
                 int M, int K) {
    extern __shared__ char smem[];
    const uint32_t sbase = smem_to_u32(smem);
    const int tid = threadIdx.x;
    const int lane = tid & 31;
    const int wid = tid >> 5;
    const int wm = wid >> 2;
    const int wn = wid & 3;
    const int bm = blockIdx.y * 128;
    const int bn = blockIdx.x * 128;
    const int rowU4 = K >> 3;
    const int nst = K >> 5;
    const int maxAr = (M - bm - 1 < 127) ? (M - bm - 1) : 127;

    const unsigned short* Bhi = blockIdx.z ? Bhi1 : Bhi0;
    const unsigned short* Blo = blockIdx.z ? Blo1 : Blo0;
    const float* bias = blockIdx.z ? bias1 : bias0;
    unsigned short* C16 = blockIdx.z ? C1 : C0;

    const uint4* gA0 = (const uint4*)(Ahi + (size_t)bm * K);
    const uint4* gA1 = (const uint4*)(Alo + (size_t)bm * K);
    const uint4* gB0 = (const uint4*)(Bhi + (size_t)bn * K);
    const uint4* gB1 = (const uint4*)(Blo + (size_t)bn * K);

    float d[4][4][4];
#pragma unroll
    for (int i = 0; i < 4; i++)
#pragma unroll
        for (int j = 0; j < 4; j++)
#pragma unroll
            for (int r = 0; r < 4; r++) d[i][j][r] = 0.f;

    auto load_stage = [&](int slot, int kt) {
        uint32_t sb = sbase + (uint32_t)slot * SLOT3;
#pragma unroll
        for (int j = 0; j < 8; j++) {
            int gidx = j * 256 + tid;
            int term = gidx >> 9;
            int idx = gidx & 511;
            int r = idx >> 2;
            int c = idx & 3;
            int re = (term < 2 && r > maxAr) ? maxAr : r;
            const uint4* src = (term == 0) ? gA0 : (term == 1) ? gA1
                             : (term == 2) ? gB0 : gB1;
            const uint4* gp = src + (size_t)re * rowU4 + kt * 4 + c;
            uint32_t sp = sb + (uint32_t)term * 10240u
                        + (uint32_t)(r * 80 + c * 16);
            CP16(sp, gp);
        }
        CP_COMMIT();
    };

    auto compute_stage = [&](int slot) {
        uint32_t sb = sbase + (uint32_t)slot * SLOT3;
        const uint32_t aOff[2] = {sb, sb + 10240u};
        const uint32_t bOff[2] = {sb + 20480u, sb + 30720u};
#pragma unroll
        for (int kk = 0; kk < 2; kk++) {
            const uint32_t colB = (uint32_t)(kk * 32) + ((lane & 16) ? 16u : 0u);
            uint32_t ah[4][4], al[4][4];
#pragma unroll
            for (int mt = 0; mt < 4; mt++) {
                int row = wm * 64 + mt * 16 + (lane & 15);
                LDSM4(ah[mt], aOff[0] + (uint32_t)(row * 80) + colB);
                LDSM4(al[mt], aOff[1] + (uint32_t)(row * 80) + colB);
            }
            uint32_t bh[4][2], bl[4][2];
#pragma unroll
            for (int nt2 = 0; nt2 < 2; nt2++) {
                int row = wn * 32 + nt2 * 16 + (lane & 15);
                uint32_t r4[4];
                LDSM4(r4, bOff[0] + (uint32_t)(row * 80) + colB);
                bh[nt2 * 2 + 0][0] = r4[0]; bh[nt2 * 2 + 0][1] = r4[2];
                bh[nt2 * 2 + 1][0] = r4[1]; bh[nt2 * 2 + 1][1] = r4[3];
                LDSM4(r4, bOff[1] + (uint32_t)(row * 80) + colB);
                bl[nt2 * 2 + 0][0] = r4[0]; bl[nt2 * 2 + 0][1] = r4[2];
                bl[nt2 * 2 + 1][0] = r4[1]; bl[nt2 * 2 + 1][1] = r4[3];
            }
#pragma unroll
            for (int mt = 0; mt < 4; mt++)
#pragma unroll
                for (int nt = 0; nt < 4; nt++) {
                    MMAF16(d[mt][nt], ah[mt], bh[nt]);
                    MMAF16(d[mt][nt], ah[mt], bl[nt]);
                    MMAF16(d[mt][nt], al[mt], bh[nt]);
                }
        }
    };

    load_stage(0, 0);
    load_stage(1, 1);
    for (int s = 0; s < nst; s++) {
        if (s + 1 < nst) { CP_WAIT1(); } else { CP_WAIT0(); }
        __syncthreads();
        if (s + 2 < nst) load_stage((s + 2) % 3, s + 2);
        compute_stage(s % 3);
    }

#pragma unroll
    for (int mt = 0; mt < 4; mt++) {
        int row0 = bm + wm * 64 + mt * 16 + (lane >> 2);
#pragma unroll
        for (int nt = 0; nt < 4; nt++) {
            int col = bn + wn * 32 + nt * 8 + (lane & 3) * 2;
            float2 bv = *(const float2*)&bias[col];
            if (row0 < M) {
                uint32_t p = (uint32_t)f16_of(d[mt][nt][0] + bv.x)
                           | ((uint32_t)f16_of(d[mt][nt][1] + bv.y) << 16);
                *(uint32_t*)&C16[(size_t)row0 * EMBED + col] = p;
            }
            if (row0 + 8 < M) {
                uint32_t p = (uint32_t)f16_of(d[mt][nt][2] + bv.x)
                           | ((uint32_t)f16_of(d[mt][nt][3] + bv.y) << 16);
                *(uint32_t*)&C16[(size_t)(row0 + 8) * EMBED + col] = p;
            }
        }
    }
}

// ---------------------------------------------------------------------------
// 1-term fp16 GEMM core: 4 slots, 3 preloads, single sync per stage, occ 2.
// ---------------------------------------------------------------------------
#define SLOT1 20480u
template <int OUT16>
__device__ __forceinline__ void gemm1_body(
    const unsigned short* __restrict__ Ah,
    const unsigned short* __restrict__ Bh,
    const float* __restrict__ bias, float* __restrict__ C,
    unsigned short* __restrict__ Chi, unsigned short* __restrict__ Clo,
    float oscale, int M, int K, char* smem) {
    const uint32_t sbase = smem_to_u32(smem);
    const int tid = threadIdx.x;
    const int lane = tid & 31;
    const int wid = tid >> 5;
    const int wm = wid >> 2;
    const int wn = wid & 3;
    const int bm = blockIdx.y * 128;
    const int bn = blockIdx.x * 128;
    const int rowU4 = K >> 3;
    const int nst = K >> 5;

    const uint4* gA0 = (const uint4*)(Ah + (size_t)bm * K);
    const uint4* gB0 = (const uint4*)(Bh + (size_t)bn * K);

    float d[4][4][4];
#pragma unroll
    for (int i = 0; i < 4; i++)
#pragma unroll
        for (int j = 0; j < 4; j++)
#pragma unroll
            for (int r = 0; r < 4; r++) d[i][j][r] = 0.f;

    auto load_stage = [&](int slot, int kt) {
        uint32_t sb = sbase + (uint32_t)slot * SLOT1;
#pragma unroll
        for (int j = 0; j < 4; j++) {
            int gidx = j * 256 + tid;
            int term = gidx >> 9;
            int idx = gidx & 511;
            int r = idx >> 2;
            int c = idx & 3;
            const uint4* src = (term == 0) ? gA0 : gB0;
            const uint4* gp = src + (size_t)r * rowU4 + kt * 4 + c;
            uint32_t sp = sb + (uint32_t)term * 10240u
                        + (uint32_t)(r * 80 + c * 16);
            CP16(sp, gp);
        }
        CP_COMMIT();
    };

    auto compute_stage = [&](int slot) {
        uint32_t sb = sbase + (uint32_t)slot * SLOT1;
        const uint32_t aOff = sb;
        const uint32_t bOff = sb + 10240u;
#pragma unroll
        for (int kk = 0; kk < 2; kk++) {
            const uint32_t colB = (uint32_t)(kk * 32) + ((lane & 16) ? 16u : 0u);
            uint32_t ah[4][4];
#pragma unroll
            for (int mt = 0; mt < 4; mt++) {
                int row = wm * 64 + mt * 16 + (lane & 15);
                LDSM4(ah[mt], aOff + (uint32_t)(row * 80) + colB);
            }
            uint32_t bh[4][2];
#pragma unroll
            for (int nt2 = 0; nt2 < 2; nt2++) {
                int row = wn * 32 + nt2 * 16 + (lane & 15);
                uint32_t r4[4];
                LDSM4(r4, bOff + (uint32_t)(row * 80) + colB);
                bh[nt2 * 2 + 0][0] = r4[0]; bh[nt2 * 2 + 0][1] = r4[2];
                bh[nt2 * 2 + 1][0] = r4[1]; bh[nt2 * 2 + 1][1] = r4[3];
            }
#pragma unroll
            for (int mt = 0; mt < 4; mt++)
#pragma unroll
                for (int nt = 0; nt < 4; nt++)
                    MMAF16(d[mt][nt], ah[mt], bh[nt]);
        }
    };

    load_stage(0, 0);
    load_stage(1, 1);
    load_stage(2, 2);
    for (int s = 0; s < nst; s++) {
        if (s + 2 < nst) { CP_WAIT2(); }
        else if (s + 1 < nst) { CP_WAIT1(); }
        else { CP_WAIT0(); }
        __syncthreads();
        if (s + 3 < nst) load_stage((s + 3) & 3, s + 3);
        compute_stage(s & 3);
    }

#pragma unroll
    for (int mt = 0; mt < 4; mt++) {
        int row0 = bm + wm * 64 + mt * 16 + (lane >> 2);
#pragma unroll
        for (int nt = 0; nt < 4; nt++) {
            int col = bn + wn * 32 + nt * 8 + (lane & 3) * 2;
            float2 bv = *(const float2*)&bias[col];
#pragma unroll
            for (int half = 0; half < 2; half++) {
                int row = row0 + half * 8;
                float v0 = (d[mt][nt][half * 2 + 0] + bv.x) * oscale;
                float v1 = (d[mt][nt][half * 2 + 1] + bv.y) * oscale;
                if (OUT16) {
                    float r0, r1;
                    unsigned short h0 = f16_hi(v0, r0);
                    unsigned short h1 = f16_hi(v1, r1);
                    *(uint32_t*)&Chi[(size_t)row * EMBED + col] =
                        (uint32_t)h0 | ((uint32_t)h1 << 16);
                    *(uint32_t*)&Clo[(size_t)row * EMBED + col] =
                        (uint32_t)f16_of(r0) | ((uint32_t)f16_of(r1) << 16);
                } else {
                    *(float2*)&C[(size_t)row * EMBED + col] = make_float2(v0, v1);
                }
            }
        }
    }
}

// O projection: fp32 output
__global__ __launch_bounds__(256, 2)
void gemm_mma1(const unsigned short* __restrict__ Ah,
               const unsigned short* __restrict__ Bh,
               const float* __restrict__ bias, float* __restrict__ C,
               int M, int K) {
    extern __shared__ char smem[];
    gemm1_body<0>(Ah, Bh, bias, C, nullptr, nullptr, 1.0f, M, K, smem);
}

// Q projection: scaled fp16 hi/lo output
__global__ __launch_bounds__(256, 2)
void gemm_mma1q(const unsigned short* __restrict__ Ah,
                const unsigned short* __restrict__ Bh,
                const float* __restrict__ bias,
                unsigned short* __restrict__ Chi,
                unsigned short* __restrict__ Clo,
                int M, int K) {
    extern __shared__ char smem[];
    gemm1_body<1>(Ah, Bh, bias, nullptr, Chi, Clo,
                  0.11180339887498949f, M, K, smem);
}

// ---------------------------------------------------------------------------
// Tensor-core attention: block = 64 t-rows x one (b,h), 4 warps x 16 rows.
// ---------------------------------------------------------------------------
#define AT_STR 88
#define AT_T 128
__global__ __launch_bounds__(AT_T)
void attn_mma(const unsigned short* __restrict__ qhi,
              const unsigned short* __restrict__ qlo,
              const unsigned short* __restrict__ khi,
              const unsigned short* __restrict__ vhi,
              unsigned short* __restrict__ ohi) {
    extern __shared__ unsigned short smh[];
    unsigned short* sqh = smh;                    // 64*88
    unsigned short* sql = sqh + 64 * AT_STR;      // 64*88
    unsigned short* skh = sql + 64 * AT_STR;      // 80*88
    unsigned short* svt = skh + 80 * AT_STR;      // 80*88 (d rows, s cols)

    const int b = blockIdx.z;
    const int h = blockIdx.y;
    const int t0 = blockIdx.x * 64;
    const int tid = threadIdx.x;
    const int w = tid >> 5;
    const int lane = tid & 31;

    for (int i = tid; i < 3 * AT_STR; i += AT_T)
        skh[77 * AT_STR + i] = 0;
    for (int i = tid; i < 240; i += AT_T)
        svt[(i / 3) * AT_STR + 77 + (i % 3)] = 0;

    for (int i = tid; i < 640; i += AT_T) {
        int t = i / 10, c = i - t * 10;
        size_t gi = ((size_t)(b * SEQ_T + t0 + t)) * 80 + h * 10 + c;
        *(uint4*)&sqh[t * AT_STR + c * 8] = ((const uint4*)qhi)[gi];
        *(uint4*)&sql[t * AT_STR + c * 8] = ((const uint4*)qlo)[gi];
    }
    for (int i = tid; i < 770; i += AT_T) {
        int s = i / 10, c = i - s * 10;
        size_t gi = ((size_t)(b * SEQ_S + s)) * 80 + h * 10 + c;
        *(uint4*)&skh[s * AT_STR + c * 8] = ((const uint4*)khi)[gi];
    }
    for (int i = tid; i < SEQ_S * 80; i += AT_T) {
        int s = i / 80, dd = i - s * 80;
        svt[dd * AT_STR + s] = vhi[((size_t)(b * SEQ_S + s)) * EMBED + h * 80 + dd];
    }
    __syncthreads();

    const uint32_t sqh_b = smem_to_u32(sqh);
    const uint32_t sql_b = smem_to_u32(sql);
    const uint32_t skh_b = smem_to_u32(skh);
    const uint32_t svt_b = smem_to_u32(svt);
    const uint32_t lrow = (uint32_t)(lane & 15) * (AT_STR * 2);
    const uint32_t loff = (lane & 16) ? 16u : 0u;

    float d[10][4];
#pragma unroll
    for (int nt = 0; nt < 10; nt++)
#pragma unroll
        for (int c = 0; c < 4; c++) d[nt][c] = 0.f;

#pragma unroll
    for (int ks = 0; ks < 5; ks++) {
        const uint32_t ca = (uint32_t)(ks * 32) + loff;
        uint32_t ah[4], al[4];
        LDSM4(ah, sqh_b + (uint32_t)(w * 16) * (AT_STR * 2) + lrow + ca);
        LDSM4(al, sql_b + (uint32_t)(w * 16) * (AT_STR * 2) + lrow + ca);
#pragma unroll
        for (int nt2 = 0; nt2 < 5; nt2++) {
            uint32_t r4[4];
            LDSM4(r4, skh_b + (uint32_t)(nt2 * 16) * (AT_STR * 2) + lrow + ca);
            uint32_t b0[2] = {r4[0], r4[2]};
            uint32_t b1[2] = {r4[1], r4[3]};
            MMAF16(d[nt2 * 2 + 0], ah, b0);
            MMAF16(d[nt2 * 2 + 0], al, b0);
            MMAF16(d[nt2 * 2 + 1], ah, b1);
            MMAF16(d[nt2 * 2 + 1], al, b1);
        }
    }

    {
        int colb = 72 + (lane & 3) * 2;
        if (colb >= 77)     { d[9][0] = -1e30f; d[9][2] = -1e30f; }
        if (colb + 1 >= 77) { d[9][1] = -1e30f; d[9][3] = -1e30f; }
    }

    {
        float mA = -1e30f, mB = -1e30f;
#pragma unroll
        for (int nt = 0; nt < 10; nt++) {
            mA = fmaxf(mA, fmaxf(d[nt][0], d[nt][1]));
            mB = fmaxf(mB, fmaxf(d[nt][2], d[nt][3]));
        }
        mA = fmaxf(mA, __shfl_xor_sync(0xFFFFFFFFu, mA, 1));
        mA = fmaxf(mA, __shfl_xor_sync(0xFFFFFFFFu, mA, 2));
        mB = fmaxf(mB, __shfl_xor_sync(0xFFFFFFFFu, mB, 1));
        mB = fmaxf(mB, __shfl_xor_sync(0xFFFFFFFFu, mB, 2));
        float sA = 0.f, sB = 0.f;
#pragma unroll
        for (int nt = 0; nt < 10; nt++) {
            d[nt][0] = __expf(d[nt][0] - mA); sA += d[nt][0];
            d[nt][1] = __expf(d[nt][1] - mA); sA += d[nt][1];
            d[nt][2] = __expf(d[nt][2] - mB); sB += d[nt][2];
            d[nt][3] = __expf(d[nt][3] - mB); sB += d[nt][3];
        }
        sA += __shfl_xor_sync(0xFFFFFFFFu, sA, 1);
        sA += __shfl_xor_sync(0xFFFFFFFFu, sA, 2);
        sB += __shfl_xor_sync(0xFFFFFFFFu, sB, 1);
        sB += __shfl_xor_sync(0xFFFFFFFFu, sB, 2);
        float rA = 1.f / sA, rB = 1.f / sB;
#pragma unroll
        for (int nt = 0; nt < 10; nt++) {
            d[nt][0] *= rA; d[nt][1] *= rA;
            d[nt][2] *= rB; d[nt][3] *= rB;
        }
    }

    uint32_t pa[5][4];
#pragma unroll
    for (int kp = 0; kp < 5; kp++) {
        pa[kp][0] = pack_f16x2(d[2 * kp][0],     d[2 * kp][1]);
        pa[kp][1] = pack_f16x2(d[2 * kp][2],     d[2 * kp][3]);
        pa[kp][2] = pack_f16x2(d[2 * kp + 1][0], d[2 * kp + 1][1]);
        pa[kp][3] = pack_f16x2(d[2 * kp + 1][2], d[2 * kp + 1][3]);
    }

    float o[10][4];
#pragma unroll
    for (int nt = 0; nt < 10; nt++)
#pragma unroll
        for (int c = 0; c < 4; c++) o[nt][c] = 0.f;

#pragma unroll
    for (int kp = 0; kp < 5; kp++) {
        const uint32_t ca = (uint32_t)(kp * 32) + loff;
#pragma unroll
        for (int nt2 = 0; nt2 < 5; nt2++) {
            uint32_t r4[4];
            LDSM4(r4, svt_b + (uint32_t)(nt2 * 16) * (AT_STR * 2) + lrow + ca);
            uint32_t b0[2] = {r4[0], r4[2]};
            uint32_t b1[2] = {r4[1], r4[3]};
            MMAF16(o[nt2 * 2 + 0], pa[kp], b0);
            MMAF16(o[nt2 * 2 + 1], pa[kp], b1);
        }
    }

    {
        const size_t rbase = (size_t)(b * SEQ_T + t0 + w * 16 + (lane >> 2));
        const int col = h * 80 + (lane & 3) * 2;
#pragma unroll
        for (int nt = 0; nt < 10; nt++) {
            *(uint32_t*)&ohi[rbase * EMBED + col + nt * 8] =
                pack_f16x2(o[nt][0], o[nt][1]);
            *(uint32_t*)&ohi[(rbase + 8) * EMBED + col + nt * 8] =
                pack_f16x2(o[nt][2], o[nt][3]);
        }
    }
}

// ---------------------------------------------------------------------------
extern "C" void kernel_launch(void* const* d_in, const int* in_sizes, int n_in,
                              void* d_out, int out_size) {
    const float* x  = (const float*)d_in[0];
    const float* y  = (const float*)d_in[1];
    const float* Wq = (const float*)d_in[2];
    const float* bq = (const float*)d_in[3];
    const float* Wk = (const float*)d_in[4];
    const float* bk = (const float*)d_in[5];
    const float* Wv = (const float*)d_in[6];
    const float* bv = (const float*)d_in[7];
    const float* Wo = (const float*)d_in[8];
    const float* bo = (const float*)d_in[9];
    float* out = (float*)d_out;

    unsigned short *xhi, *qhi, *qlo, *khi, *vhi, *yhi, *ylo;
    unsigned short *wq, *wo, *wkhi, *wklo, *wvhi, *wvlo;
    cudaGetSymbolAddress((void**)&xhi, g_xhi);
    cudaGetSymbolAddress((void**)&qhi, g_qhi);
    cudaGetSymbolAddress((void**)&qlo, g_qlo);
    cudaGetSymbolAddress((void**)&khi, g_khi);
    cudaGetSymbolAddress((void**)&vhi, g_vhi);
    cudaGetSymbolAddress((void**)&yhi, g_yhi);
    cudaGetSymbolAddress((void**)&ylo, g_ylo);
    cudaGetSymbolAddress((void**)&wq, g_wq);
    cudaGetSymbolAddress((void**)&wo, g_wo);
    cudaGetSymbolAddress((void**)&wkhi, g_wkhi);
    cudaGetSymbolAddress((void**)&wklo, g_wklo);
    cudaGetSymbolAddress((void**)&wvhi, g_wvhi);
    cudaGetSymbolAddress((void**)&wvlo, g_wvlo);

    const int smem_attn = (64 * AT_STR * 2 + 80 * AT_STR * 2) * 2;  // 50688 B
    cudaFuncSetAttribute(attn_mma, cudaFuncAttributeMaxDynamicSharedMemorySize, smem_attn);
    const int smem_m3 = 3 * (int)SLOT3;  // 122880
    cudaFuncSetAttribute(gemm_mma3kv, cudaFuncAttributeMaxDynamicSharedMemorySize, smem_m3);
    const int smem_m1 = 4 * (int)SLOT1;  // 81920
    cudaFuncSetAttribute(gemm_mma1, cudaFuncAttributeMaxDynamicSharedMemorySize, smem_m1);
    cudaFuncSetAttribute(gemm_mma1q, cudaFuncAttributeMaxDynamicSharedMemorySize, smem_m1);

    const int MKV = BATCH * SEQ_S;             // 616

    // --- 1. fused preprocessing (x conv, y split, all weight transposes) ---
    {
        int nblk = PREP_XB + PREP_YB + PREP_WQB + PREP_WKVB + PREP_WOB;  // 12231
        prep_all<<<nblk, 256>>>((const float4*)x, (const float4*)y,
                                Wq, Wk, Wv, Wo,
                                (uint4*)xhi, (uint4*)yhi, (uint4*)ylo,
                                wq, wkhi, wklo, wvhi, wvlo, wo);
    }

    // --- 2. Q projection: fp16 1-term, outputs scaled q hi/lo fp16 ---
    {
        dim3 grid(EMBED / 128, (BATCH * SEQ_T) / 128);
        gemm_mma1q<<<grid, 256, smem_m1>>>(xhi, wq, bq, qhi, qlo, BATCH * SEQ_T, EMBED);
    }

    // --- 3. K/V projections fused ---
    {
        dim3 grid(EMBED / 128, (MKV + 127) / 128, 2);
        gemm_mma3kv<<<grid, 256, smem_m3>>>(yhi, ylo, wkhi, wklo, wvhi, wvlo,
                                            bk, bv, khi, vhi, MKV, CROSS);
    }

    // --- 4. attention on tensor cores (writes fp16 into xhi; x dead by now) ---
    {
        dim3 grid(SEQ_T / 64, N_HEADS, BATCH);
        attn_mma<<<grid, AT_T, smem_attn>>>(qhi, qlo, khi, vhi, xhi);
    }

    // --- 5. O projection: fp16 1-term, fp32 output ---
    {
        dim3 grid(EMBED / 128, (BATCH * SEQ_T) / 128);
        gemm_mma1<<<grid, 256, smem_m1>>>(xhi, wo, bo, out, BATCH * SEQ_T, EMBED);
    }
}

// round 14
// speedup vs baseline: 6.2898x; 1.0427x over previous
#include <cuda_runtime.h>
#include <cuda_fp16.h>
#include <cstdint>
#include <math.h>

#define N_HEADS 8
#define EMBED 640
#define CROSS 768
#define HEAD 80
#define BATCH 8
#define SEQ_T 4096
#define SEQ_S 77

// ---------------------------------------------------------------------------
// Scratch (no cudaMalloc allowed)
// ---------------------------------------------------------------------------
__device__ __align__(16) unsigned short g_xhi[BATCH * SEQ_T * EMBED];  // x fp16 / attn-out fp16
__device__ __align__(16) unsigned short g_qhi[BATCH * SEQ_T * EMBED];  // scaled q hi
__device__ __align__(16) unsigned short g_qlo[BATCH * SEQ_T * EMBED];  // scaled q lo
__device__ __align__(16) unsigned short g_khi[BATCH * SEQ_S * EMBED];
// V stored transposed: [b][h][d][s], s-stride 80. Pads (s>=77) stay zero
// forever: zero-initialized device global, epilogue never writes s>=77.
__device__ __align__(16) unsigned short g_vt[BATCH * N_HEADS * 80 * 80];
__device__ __align__(16) unsigned short g_yhi[BATCH * SEQ_S * CROSS];
__device__ __align__(16) unsigned short g_ylo[BATCH * SEQ_S * CROSS];
__device__ __align__(16) unsigned short g_wq[EMBED * EMBED];
__device__ __align__(16) unsigned short g_wo[EMBED * EMBED];
__device__ __align__(16) unsigned short g_wkhi[EMBED * CROSS];
__device__ __align__(16) unsigned short g_wklo[EMBED * CROSS];
__device__ __align__(16) unsigned short g_wvhi[EMBED * CROSS];
__device__ __align__(16) unsigned short g_wvlo[EMBED * CROSS];

// ---------------------------------------------------------------------------
// PTX helpers (non-'a' features only: ldmatrix, mma.sync, cp.async)
// ---------------------------------------------------------------------------
__device__ __forceinline__ uint32_t smem_to_u32(const void* smem_ptr) {
    uint32_t addr;
    asm("{ .reg .u64 tmp; cvta.to.shared.u64 tmp, %1; cvt.u32.u64 %0, tmp; }"
        : "=r"(addr) : "l"(smem_ptr));
    return addr;
}

#define LDSM4(r, addr) \
    asm volatile("ldmatrix.sync.aligned.m8n8.x4.shared.b16 {%0,%1,%2,%3},[%4];" \
        : "=r"((r)[0]), "=r"((r)[1]), "=r"((r)[2]), "=r"((r)[3]) : "r"(addr))

#define MMAF16(d, a, b) \
    asm volatile("mma.sync.aligned.m16n8k16.row.col.f32.f16.f16.f32 " \
        "{%0,%1,%2,%3},{%4,%5,%6,%7},{%8,%9},{%0,%1,%2,%3};" \
        : "+f"((d)[0]), "+f"((d)[1]), "+f"((d)[2]), "+f"((d)[3]) \
        : "r"((a)[0]), "r"((a)[1]), "r"((a)[2]), "r"((a)[3]), \
          "r"((b)[0]), "r"((b)[1]))

#define CP16(sp, gp) \
    asm volatile("cp.async.cg.shared.global [%0],[%1],16;" :: "r"(sp), "l"(gp))
#define CP_COMMIT() asm volatile("cp.async.commit_group;")
#define CP_WAIT2()  asm volatile("cp.async.wait_group 2;")
#define CP_WAIT1()  asm volatile("cp.async.wait_group 1;")
#define CP_WAIT0()  asm volatile("cp.async.wait_group 0;")

__device__ __forceinline__ unsigned short f16_hi(float f, float& rem) {
    __half h = __float2half_rn(f);
    rem = f - __half2float(h);
    return *(unsigned short*)&h;
}
__device__ __forceinline__ unsigned short f16_of(float f) {
    __half h = __float2half_rn(f);
    return *(unsigned short*)&h;
}
__device__ __forceinline__ uint32_t pack_f16x2(float lo, float hi) {
    uint32_t r;
    asm("cvt.rn.f16x2.f32 %0, %1, %2;" : "=r"(r) : "f"(hi), "f"(lo));
    return r;
}

// ---------------------------------------------------------------------------
// Fused preprocessing (x conv | y split | Wq tr | Wk/Wv tr+split | Wo tr)
// ---------------------------------------------------------------------------
#define PREP_XB   10240
#define PREP_YB   231
#define PREP_WQB  400
#define PREP_WKVB 960
#define PREP_WOB  400
__global__ void prep_all(const float4* __restrict__ x4,
                         const float4* __restrict__ y4,
                         const float* __restrict__ Wq,
                         const float* __restrict__ Wk,
                         const float* __restrict__ Wv,
                         const float* __restrict__ Wo,
                         uint4* __restrict__ xhi,
                         uint4* __restrict__ yhi, uint4* __restrict__ ylo,
                         unsigned short* __restrict__ wq,
                         unsigned short* __restrict__ wkhi, unsigned short* __restrict__ wklo,
                         unsigned short* __restrict__ wvhi, unsigned short* __restrict__ wvlo,
                         unsigned short* __restrict__ wo) {
    __shared__ float tile[32][33];
    const int blk = blockIdx.x;
    const int tid = threadIdx.x;

    if (blk < PREP_XB) {
        int i = blk * 256 + tid;
        float4 a = x4[2 * i];
        float4 b = x4[2 * i + 1];
        uint4 hv;
        hv.x = (uint32_t)f16_of(a.x) | ((uint32_t)f16_of(a.y) << 16);
        hv.y = (uint32_t)f16_of(a.z) | ((uint32_t)f16_of(a.w) << 16);
        hv.z = (uint32_t)f16_of(b.x) | ((uint32_t)f16_of(b.y) << 16);
        hv.w = (uint32_t)f16_of(b.z) | ((uint32_t)f16_of(b.w) << 16);
        xhi[i] = hv;
        return;
    }
    if (blk < PREP_XB + PREP_YB) {
        int i = (blk - PREP_XB) * 256 + tid;
        float4 a = y4[2 * i];
        float4 b = y4[2 * i + 1];
        float r[8];
        unsigned short h[8];
        h[0] = f16_hi(a.x, r[0]); h[1] = f16_hi(a.y, r[1]);
        h[2] = f16_hi(a.z, r[2]); h[3] = f16_hi(a.w, r[3]);
        h[4] = f16_hi(b.x, r[4]); h[5] = f16_hi(b.y, r[5]);
        h[6] = f16_hi(b.z, r[6]); h[7] = f16_hi(b.w, r[7]);
        uint4 hv, lv;
        hv.x = (uint32_t)h[0] | ((uint32_t)h[1] << 16);
        hv.y = (uint32_t)h[2] | ((uint32_t)h[3] << 16);
        hv.z = (uint32_t)h[4] | ((uint32_t)h[5] << 16);
        hv.w = (uint32_t)h[6] | ((uint32_t)h[7] << 16);
        lv.x = (uint32_t)f16_of(r[0]) | ((uint32_t)f16_of(r[1]) << 16);
        lv.y = (uint32_t)f16_of(r[2]) | ((uint32_t)f16_of(r[3]) << 16);
        lv.z = (uint32_t)f16_of(r[4]) | ((uint32_t)f16_of(r[5]) << 16);
        lv.w = (uint32_t)f16_of(r[6]) | ((uint32_t)f16_of(r[7]) << 16);
        yhi[i] = hv;
        ylo[i] = lv;
        return;
    }

    const int tx = tid & 31;
    const int ty = tid >> 5;

    const float* W;
    unsigned short *thi, *tlo = nullptr;
    int K, t;
    if (blk < PREP_XB + PREP_YB + PREP_WQB) {
        t = blk - (PREP_XB + PREP_YB);
        W = Wq; thi = wq; K = EMBED;
    } else if (blk < PREP_XB + PREP_YB + PREP_WQB + PREP_WKVB) {
        t = blk - (PREP_XB + PREP_YB + PREP_WQB);
        int z = t / 480;
        t = t % 480;
        W = z ? Wv : Wk;
        thi = z ? wvhi : wkhi;
        tlo = z ? wvlo : wklo;
        K = CROSS;
    } else {
        t = blk - (PREP_XB + PREP_YB + PREP_WQB + PREP_WKVB);
        W = Wo; thi = wo; K = EMBED;
    }
    const int n0 = (t % 20) * 32;
    const int k0 = (t / 20) * 32;
#pragma unroll
    for (int i = 0; i < 32; i += 8)
        tile[ty + i][tx] = W[(size_t)(k0 + ty + i) * EMBED + n0 + tx];
    __syncthreads();
#pragma unroll
    for (int i = 0; i < 32; i += 8) {
        float v = tile[tx][ty + i];
        size_t oi = (size_t)(n0 + ty + i) * K + k0 + tx;
        if (tlo) {
            float rem;
            unsigned short h = f16_hi(v, rem);
            thi[oi] = h;
            tlo[oi] = f16_of(rem);
        } else {
            thi[oi] = f16_of(v);
        }
    }
}

// ---------------------------------------------------------------------------
// Fused K+V projections: 3-term fp16 split GEMM, grid.z selects weight set.
// z=0 -> K, normal layout. z=1 -> V, written TRANSPOSED to vt[b][h][d][s].
// ---------------------------------------------------------------------------
#define SLOT3 40960u
__global__ __launch_bounds__(256, 1)
void gemm_mma3kv(const unsigned short* __restrict__ Ahi,
                 const unsigned short* __restrict__ Alo,
                 const unsigned short* __restrict__ Bhi0,
                 const unsigned short* __restrict__ Blo0,
                 const unsigned short* __restrict__ Bhi1,
                 const unsigned short* __restrict__ Blo1,
                 const float* __restrict__ bias0,
                 const float* __restrict__ bias1,
                 unsigned short* __restrict__ Ck,
                 unsigned short* __restrict__ Cvt,
                 int M, int K) {
    extern __shared__ char smem[];
    const uint32_t sbase = smem_to_u32(smem);
    const int tid = threadIdx.x;
    const int lane = tid & 31;
    const int wid = tid >> 5;
    const int wm = wid >> 2;
    const int wn = wid & 3;
    const int bm = blockIdx.y * 128;
    const int bn = blockIdx.x * 128;
    const int rowU4 = K >> 3;
    const int nst = K >> 5;
    const int maxAr = (M - bm - 1 < 127) ? (M - bm - 1) : 127;
    const int isV = blockIdx.z;

    const unsigned short* Bhi = isV ? Bhi1 : Bhi0;
    const unsigned short* Blo = isV ? Blo1 : Blo0;
    const float* bias = isV ? bias1 : bias0;

    const uint4* gA0 = (const uint4*)(Ahi + (size_t)bm * K);
    const uint4* gA1 = (const uint4*)(Alo + (size_t)bm * K);
    const uint4* gB0 = (const uint4*)(Bhi + (size_t)bn * K);
    const uint4* gB1 = (const uint4*)(Blo + (size_t)bn * K);

    float d[4][4][4];
#pragma unroll
    for (int i = 0; i < 4; i++)
#pragma unroll
        for (int j = 0; j < 4; j++)
#pragma unroll
            for (int r = 0; r < 4; r++) d[i][j][r] = 0.f;

    auto load_stage = [&](int slot, int kt) {
        uint32_t sb = sbase + (uint32_t)slot * SLOT3;
#pragma unroll
        for (int j = 0; j < 8; j++) {
            int gidx = j * 256 + tid;
            int term = gidx >> 9;
            int idx = gidx & 511;
            int r = idx >> 2;
            int c = idx & 3;
            int re = (term < 2 && r > maxAr) ? maxAr : r;
            const uint4* src = (term == 0) ? gA0 : (term == 1) ? gA1
                             : (term == 2) ? gB0 : gB1;
            const uint4* gp = src + (size_t)re * rowU4 + kt * 4 + c;
            uint32_t sp = sb + (uint32_t)term * 10240u
                        + (uint32_t)(r * 80 + c * 16);
            CP16(sp, gp);
        }
        CP_COMMIT();
    };

    auto compute_stage = [&](int slot) {
        uint32_t sb = sbase + (uint32_t)slot * SLOT3;
        const uint32_t aOff[2] = {sb, sb + 10240u};
        const uint32_t bOff[2] = {sb + 20480u, sb + 30720u};
#pragma unroll
        for (int kk = 0; kk < 2; kk++) {
            const uint32_t colB = (uint32_t)(kk * 32) + ((lane & 16) ? 16u : 0u);
            uint32_t ah[4][4], al[4][4];
#pragma unroll
            for (int mt = 0; mt < 4; mt++) {
                int row = wm * 64 + mt * 16 + (lane & 15);
                LDSM4(ah[mt], aOff[0] + (uint32_t)(row * 80) + colB);
                LDSM4(al[mt], aOff[1] + (uint32_t)(row * 80) + colB);
            }
            uint32_t bh[4][2], bl[4][2];
#pragma unroll
            for (int nt2 = 0; nt2 < 2; nt2++) {
                int row = wn * 32 + nt2 * 16 + (lane & 15);
                uint32_t r4[4];
                LDSM4(r4, bOff[0] + (uint32_t)(row * 80) + colB);
                bh[nt2 * 2 + 0][0] = r4[0]; bh[nt2 * 2 + 0][1] = r4[2];
                bh[nt2 * 2 + 1][0] = r4[1]; bh[nt2 * 2 + 1][1] = r4[3];
                LDSM4(r4, bOff[1] + (uint32_t)(row * 80) + colB);
                bl[nt2 * 2 + 0][0] = r4[0]; bl[nt2 * 2 + 0][1] = r4[2];
                bl[nt2 * 2 + 1][0] = r4[1]; bl[nt2 * 2 + 1][1] = r4[3];
            }
#pragma unroll
            for (int mt = 0; mt < 4; mt++)
#pragma unroll
                for (int nt = 0; nt < 4; nt++) {
                    MMAF16(d[mt][nt], ah[mt], bh[nt]);
                    MMAF16(d[mt][nt], ah[mt], bl[nt]);
                    MMAF16(d[mt][nt], al[mt], bh[nt]);
                }
        }
    };

    load_stage(0, 0);
    load_stage(1, 1);
    for (int s = 0; s < nst; s++) {
        if (s + 1 < nst) { CP_WAIT1(); } else { CP_WAIT0(); }
        __syncthreads();
        if (s + 2 < nst) load_stage((s + 2) % 3, s + 2);
        compute_stage(s % 3);
    }

#pragma unroll
    for (int mt = 0; mt < 4; mt++) {
        int row0 = bm + wm * 64 + mt * 16 + (lane >> 2);
#pragma unroll
        for (int nt = 0; nt < 4; nt++) {
            int col = bn + wn * 32 + nt * 8 + (lane & 3) * 2;
            float2 bv = *(const float2*)&bias[col];
#pragma unroll
            for (int half = 0; half < 2; half++) {
                int row = row0 + half * 8;
                if (row >= M) continue;
                float v0 = d[mt][nt][half * 2 + 0] + bv.x;
                float v1 = d[mt][nt][half * 2 + 1] + bv.y;
                if (!isV) {
                    uint32_t p = (uint32_t)f16_of(v0) | ((uint32_t)f16_of(v1) << 16);
                    *(uint32_t*)&Ck[(size_t)row * EMBED + col] = p;
                } else {
                    // transposed write: vt[((b*8 + h)*80 + d)*80 + s]
                    int b = row / SEQ_S;
                    int s = row - b * SEQ_S;
                    int h = col / 80;
                    int dd = col - h * 80;
                    size_t base = ((size_t)(b * N_HEADS + h) * 80 + dd) * 80 + s;
                    Cvt[base] = f16_of(v0);
                    Cvt[base + 80] = f16_of(v1);   // d+1 row
                }
            }
        }
    }
}

// ---------------------------------------------------------------------------
// 1-term fp16 GEMM core: 4 slots, 3 preloads, single sync per stage, occ 2.
// ---------------------------------------------------------------------------
#define SLOT1 20480u
template <int OUT16>
__device__ __forceinline__ void gemm1_body(
    const unsigned short* __restrict__ Ah,
    const unsigned short* __restrict__ Bh,
    const float* __restrict__ bias, float* __restrict__ C,
    unsigned short* __restrict__ Chi, unsigned short* __restrict__ Clo,
    float oscale, int M, int K, char* smem) {
    const uint32_t sbase = smem_to_u32(smem);
    const int tid = threadIdx.x;
    const int lane = tid & 31;
    const int wid = tid >> 5;
    const int wm = wid >> 2;
    const int wn = wid & 3;
    const int bm = blockIdx.y * 128;
    const int bn = blockIdx.x * 128;
    const int rowU4 = K >> 3;
    const int nst = K >> 5;

    const uint4* gA0 = (const uint4*)(Ah + (size_t)bm * K);
    const uint4* gB0 = (const uint4*)(Bh + (size_t)bn * K);

    float d[4][4][4];
#pragma unroll
    for (int i = 0; i < 4; i++)
#pragma unroll
        for (int j = 0; j < 4; j++)
#pragma unroll
            for (int r = 0; r < 4; r++) d[i][j][r] = 0.f;

    auto load_stage = [&](int slot, int kt) {
        uint32_t sb = sbase + (uint32_t)slot * SLOT1;
#pragma unroll
        for (int j = 0; j < 4; j++) {
            int gidx = j * 256 + tid;
            int term = gidx >> 9;
            int idx = gidx & 511;
            int r = idx >> 2;
            int c = idx & 3;
            const uint4* src = (term == 0) ? gA0 : gB0;
            const uint4* gp = src + (size_t)r * rowU4 + kt * 4 + c;
            uint32_t sp = sb + (uint32_t)term * 10240u
                        + (uint32_t)(r * 80 + c * 16);
            CP16(sp, gp);
        }
        CP_COMMIT();
    };

    auto compute_stage = [&](int slot) {
        uint32_t sb = sbase + (uint32_t)slot * SLOT1;
        const uint32_t aOff = sb;
        const uint32_t bOff = sb + 10240u;
#pragma unroll
        for (int kk = 0; kk < 2; kk++) {
            const uint32_t colB = (uint32_t)(kk * 32) + ((lane & 16) ? 16u : 0u);
            uint32_t ah[4][4];
#pragma unroll
            for (int mt = 0; mt < 4; mt++) {
                int row = wm * 64 + mt * 16 + (lane & 15);
                LDSM4(ah[mt], aOff + (uint32_t)(row * 80) + colB);
            }
            uint32_t bh[4][2];
#pragma unroll
            for (int nt2 = 0; nt2 < 2; nt2++) {
                int row = wn * 32 + nt2 * 16 + (lane & 15);
                uint32_t r4[4];
                LDSM4(r4, bOff + (uint32_t)(row * 80) + colB);
                bh[nt2 * 2 + 0][0] = r4[0]; bh[nt2 * 2 + 0][1] = r4[2];
                bh[nt2 * 2 + 1][0] = r4[1]; bh[nt2 * 2 + 1][1] = r4[3];
            }
#pragma unroll
            for (int mt = 0; mt < 4; mt++)
#pragma unroll
                for (int nt = 0; nt < 4; nt++)
                    MMAF16(d[mt][nt], ah[mt], bh[nt]);
        }
    };

    load_stage(0, 0);
    load_stage(1, 1);
    load_stage(2, 2);
    for (int s = 0; s < nst; s++) {
        if (s + 2 < nst) { CP_WAIT2(); }
        else if (s + 1 < nst) { CP_WAIT1(); }
        else { CP_WAIT0(); }
        __syncthreads();
        if (s + 3 < nst) load_stage((s + 3) & 3, s + 3);
        compute_stage(s & 3);
    }

#pragma unroll
    for (int mt = 0; mt < 4; mt++) {
        int row0 = bm + wm * 64 + mt * 16 + (lane >> 2);
#pragma unroll
        for (int nt = 0; nt < 4; nt++) {
            int col = bn + wn * 32 + nt * 8 + (lane & 3) * 2;
            float2 bv = *(const float2*)&bias[col];
#pragma unroll
            for (int half = 0; half < 2; half++) {
                int row = row0 + half * 8;
                float v0 = (d[mt][nt][half * 2 + 0] + bv.x) * oscale;
                float v1 = (d[mt][nt][half * 2 + 1] + bv.y) * oscale;
                if (OUT16) {
                    float r0, r1;
                    unsigned short h0 = f16_hi(v0, r0);
                    unsigned short h1 = f16_hi(v1, r1);
                    *(uint32_t*)&Chi[(size_t)row * EMBED + col] =
                        (uint32_t)h0 | ((uint32_t)h1 << 16);
                    *(uint32_t*)&Clo[(size_t)row * EMBED + col] =
                        (uint32_t)f16_of(r0) | ((uint32_t)f16_of(r1) << 16);
                } else {
                    *(float2*)&C[(size_t)row * EMBED + col] = make_float2(v0, v1);
                }
            }
        }
    }
}

// O projection: fp32 output
__global__ __launch_bounds__(256, 2)
void gemm_mma1(const unsigned short* __restrict__ Ah,
               const unsigned short* __restrict__ Bh,
               const float* __restrict__ bias, float* __restrict__ C,
               int M, int K) {
    extern __shared__ char smem[];
    gemm1_body<0>(Ah, Bh, bias, C, nullptr, nullptr, 1.0f, M, K, smem);
}

// Q projection: scaled fp16 hi/lo output
__global__ __launch_bounds__(256, 2)
void gemm_mma1q(const unsigned short* __restrict__ Ah,
                const unsigned short* __restrict__ Bh,
                const float* __restrict__ bias,
                unsigned short* __restrict__ Chi,
                unsigned short* __restrict__ Clo,
                int M, int K) {
    extern __shared__ char smem[];
    gemm1_body<1>(Ah, Bh, bias, nullptr, Chi, Clo,
                  0.11180339887498949f, M, K, smem);
}

// ---------------------------------------------------------------------------
// Tensor-core attention: block = 64 t-rows x one (b,h), 4 warps x 16 rows.
// V arrives pre-transposed (vt[b][h][d][s], pads already zero) -> all staging
// is vectorized uint4 copies.
// ---------------------------------------------------------------------------
#define AT_STR 88
#define AT_T 128
__global__ __launch_bounds__(AT_T)
void attn_mma(const unsigned short* __restrict__ qhi,
              const unsigned short* __restrict__ qlo,
              const unsigned short* __restrict__ khi,
              const unsigned short* __restrict__ vt,
              unsigned short* __restrict__ ohi) {
    extern __shared__ unsigned short smh[];
    unsigned short* sqh = smh;                    // 64*88
    unsigned short* sql = sqh + 64 * AT_STR;      // 64*88
    unsigned short* skh = sql + 64 * AT_STR;      // 80*88
    unsigned short* svt = skh + 80 * AT_STR;      // 80*88 (d rows, s cols)

    const int b = blockIdx.z;
    const int h = blockIdx.y;
    const int t0 = blockIdx.x * 64;
    const int tid = threadIdx.x;
    const int w = tid >> 5;
    const int lane = tid & 31;

    // ---- zero pads: skh rows 77..79 only (svt pads come zero from gmem) ----
    for (int i = tid; i < 3 * AT_STR; i += AT_T)
        skh[77 * AT_STR + i] = 0;

    // ---- staging (all vectorized) ----
    for (int i = tid; i < 640; i += AT_T) {       // q hi/lo: 64 rows x 10 uint4
        int t = i / 10, c = i - t * 10;
        size_t gi = ((size_t)(b * SEQ_T + t0 + t)) * 80 + h * 10 + c;
        *(uint4*)&sqh[t * AT_STR + c * 8] = ((const uint4*)qhi)[gi];
        *(uint4*)&sql[t * AT_STR + c * 8] = ((const uint4*)qlo)[gi];
    }
    for (int i = tid; i < 770; i += AT_T) {       // k: 77 rows x 10 uint4
        int s = i / 10, c = i - s * 10;
        size_t gi = ((size_t)(b * SEQ_S + s)) * 80 + h * 10 + c;
        *(uint4*)&skh[s * AT_STR + c * 8] = ((const uint4*)khi)[gi];
    }
    {   // v^T: 80 d-rows x 10 uint4, contiguous in vt
        const uint4* vsrc = (const uint4*)(vt + ((size_t)(b * N_HEADS + h) * 80) * 80);
        for (int i = tid; i < 800; i += AT_T) {
            int dd = i / 10, c = i - dd * 10;
            *(uint4*)&svt[dd * AT_STR + c * 8] = vsrc[dd * 10 + c];
        }
    }
    __syncthreads();

    const uint32_t sqh_b = smem_to_u32(sqh);
    const uint32_t sql_b = smem_to_u32(sql);
    const uint32_t skh_b = smem_to_u32(skh);
    const uint32_t svt_b = smem_to_u32(svt);
    const uint32_t lrow = (uint32_t)(lane & 15) * (AT_STR * 2);
    const uint32_t loff = (lane & 16) ? 16u : 0u;

    float d[10][4];
#pragma unroll
    for (int nt = 0; nt < 10; nt++)
#pragma unroll
        for (int c = 0; c < 4; c++) d[nt][c] = 0.f;

#pragma unroll
    for (int ks = 0; ks < 5; ks++) {
        const uint32_t ca = (uint32_t)(ks * 32) + loff;
        uint32_t ah[4], al[4];
        LDSM4(ah, sqh_b + (uint32_t)(w * 16) * (AT_STR * 2) + lrow + ca);
        LDSM4(al, sql_b + (uint32_t)(w * 16) * (AT_STR * 2) + lrow + ca);
#pragma unroll
        for (int nt2 = 0; nt2 < 5; nt2++) {
            uint32_t r4[4];
            LDSM4(r4, skh_b + (uint32_t)(nt2 * 16) * (AT_STR * 2) + lrow + ca);
            uint32_t b0[2] = {r4[0], r4[2]};
            uint32_t b1[2] = {r4[1], r4[3]};
            MMAF16(d[nt2 * 2 + 0], ah, b0);
            MMAF16(d[nt2 * 2 + 0], al, b0);
            MMAF16(d[nt2 * 2 + 1], ah, b1);
            MMAF16(d[nt2 * 2 + 1], al, b1);
        }
    }

    {
        int colb = 72 + (lane & 3) * 2;
        if (colb >= 77)     { d[9][0] = -1e30f; d[9][2] = -1e30f; }
        if (colb + 1 >= 77) { d[9][1] = -1e30f; d[9][3] = -1e30f; }
    }

    {
        float mA = -1e30f, mB = -1e30f;
#pragma unroll
        for (int nt = 0; nt < 10; nt++) {
            mA = fmaxf(mA, fmaxf(d[nt][0], d[nt][1]));
            mB = fmaxf(mB, fmaxf(d[nt][2], d[nt][3]));
        }
        mA = fmaxf(mA, __shfl_xor_sync(0xFFFFFFFFu, mA, 1));
        mA = fmaxf(mA, __shfl_xor_sync(0xFFFFFFFFu, mA, 2));
        mB = fmaxf(mB, __shfl_xor_sync(0xFFFFFFFFu, mB, 1));
        mB = fmaxf(mB, __shfl_xor_sync(0xFFFFFFFFu, mB, 2));
        float sA = 0.f, sB = 0.f;
#pragma unroll
        for (int nt = 0; nt < 10; nt++) {
            d[nt][0] = __expf(d[nt][0] - mA); sA += d[nt][0];
            d[nt][1] = __expf(d[nt][1] - mA); sA += d[nt][1];
            d[nt][2] = __expf(d[nt][2] - mB); sB += d[nt][2];
            d[nt][3] = __expf(d[nt][3] - mB); sB += d[nt][3];
        }
        sA += __shfl_xor_sync(0xFFFFFFFFu, sA, 1);
        sA += __shfl_xor_sync(0xFFFFFFFFu, sA, 2);
        sB += __shfl_xor_sync(0xFFFFFFFFu, sB, 1);
        sB += __shfl_xor_sync(0xFFFFFFFFu, sB, 2);
        float rA = 1.f / sA, rB = 1.f / sB;
#pragma unroll
        for (int nt = 0; nt < 10; nt++) {
            d[nt][0] *= rA; d[nt][1] *= rA;
            d[nt][2] *= rB; d[nt][3] *= rB;
        }
    }

    uint32_t pa[5][4];
#pragma unroll
    for (int kp = 0; kp < 5; kp++) {
        pa[kp][0] = pack_f16x2(d[2 * kp][0],     d[2 * kp][1]);
        pa[kp][1] = pack_f16x2(d[2 * kp][2],     d[2 * kp][3]);
        pa[kp][2] = pack_f16x2(d[2 * kp + 1][0], d[2 * kp + 1][1]);
        pa[kp][3] = pack_f16x2(d[2 * kp + 1][2], d[2 * kp + 1][3]);
    }

    float o[10][4];
#pragma unroll
    for (int nt = 0; nt < 10; nt++)
#pragma unroll
        for (int c = 0; c < 4; c++) o[nt][c] = 0.f;

#pragma unroll
    for (int kp = 0; kp < 5; kp++) {
        const uint32_t ca = (uint32_t)(kp * 32) + loff;
#pragma unroll
        for (int nt2 = 0; nt2 < 5; nt2++) {
            uint32_t r4[4];
            LDSM4(r4, svt_b + (uint32_t)(nt2 * 16) * (AT_STR * 2) + lrow + ca);
            uint32_t b0[2] = {r4[0], r4[2]};
            uint32_t b1[2] = {r4[1], r4[3]};
            MMAF16(o[nt2 * 2 + 0], pa[kp], b0);
            MMAF16(o[nt2 * 2 + 1], pa[kp], b1);
        }
    }

    {
        const size_t rbase = (size_t)(b * SEQ_T + t0 + w * 16 + (lane >> 2));
        const int col = h * 80 + (lane & 3) * 2;
#pragma unroll
        for (int nt = 0; nt < 10; nt++) {
            *(uint32_t*)&ohi[rbase * EMBED + col + nt * 8] =
                pack_f16x2(o[nt][0], o[nt][1]);
            *(uint32_t*)&ohi[(rbase + 8) * EMBED + col + nt * 8] =
                pack_f16x2(o[nt][2], o[nt][3]);
        }
    }
}

// ---------------------------------------------------------------------------
extern "C" void kernel_launch(void* const* d_in, const int* in_sizes, int n_in,
                              void* d_out, int out_size) {
    const float* x  = (const float*)d_in[0];
    const float* y  = (const float*)d_in[1];
    const float* Wq = (const float*)d_in[2];
    const float* bq = (const float*)d_in[3];
    const float* Wk = (const float*)d_in[4];
    const float* bk = (const float*)d_in[5];
    const float* Wv = (const float*)d_in[6];
    const float* bv = (const float*)d_in[7];
    const float* Wo = (const float*)d_in[8];
    const float* bo = (const float*)d_in[9];
    float* out = (float*)d_out;

    unsigned short *xhi, *qhi, *qlo, *khi, *vt, *yhi, *ylo;
    unsigned short *wq, *wo, *wkhi, *wklo, *wvhi, *wvlo;
    cudaGetSymbolAddress((void**)&xhi, g_xhi);
    cudaGetSymbolAddress((void**)&qhi, g_qhi);
    cudaGetSymbolAddress((void**)&qlo, g_qlo);
    cudaGetSymbolAddress((void**)&khi, g_khi);
    cudaGetSymbolAddress((void**)&vt, g_vt);
    cudaGetSymbolAddress((void**)&yhi, g_yhi);
    cudaGetSymbolAddress((void**)&ylo, g_ylo);
    cudaGetSymbolAddress((void**)&wq, g_wq);
    cudaGetSymbolAddress((void**)&wo, g_wo);
    cudaGetSymbolAddress((void**)&wkhi, g_wkhi);
    cudaGetSymbolAddress((void**)&wklo, g_wklo);
    cudaGetSymbolAddress((void**)&wvhi, g_wvhi);
    cudaGetSymbolAddress((void**)&wvlo, g_wvlo);

    const int smem_attn = (64 * AT_STR * 2 + 80 * AT_STR * 2) * 2;  // 50688 B
    cudaFuncSetAttribute(attn_mma, cudaFuncAttributeMaxDynamicSharedMemorySize, smem_attn);
    const int smem_m3 = 3 * (int)SLOT3;  // 122880
    cudaFuncSetAttribute(gemm_mma3kv, cudaFuncAttributeMaxDynamicSharedMemorySize, smem_m3);
    const int smem_m1 = 4 * (int)SLOT1;  // 81920
    cudaFuncSetAttribute(gemm_mma1, cudaFuncAttributeMaxDynamicSharedMemorySize, smem_m1);
    cudaFuncSetAttribute(gemm_mma1q, cudaFuncAttributeMaxDynamicSharedMemorySize, smem_m1);

    const int MKV = BATCH * SEQ_S;             // 616

    // --- 1. fused preprocessing ---
    {
        int nblk = PREP_XB + PREP_YB + PREP_WQB + PREP_WKVB + PREP_WOB;
        prep_all<<<nblk, 256>>>((const float4*)x, (const float4*)y,
                                Wq, Wk, Wv, Wo,
                                (uint4*)xhi, (uint4*)yhi, (uint4*)ylo,
                                wq, wkhi, wklo, wvhi, wvlo, wo);
    }

    // --- 2. Q projection ---
    {
        dim3 grid(EMBED / 128, (BATCH * SEQ_T) / 128);
        gemm_mma1q<<<grid, 256, smem_m1>>>(xhi, wq, bq, qhi, qlo, BATCH * SEQ_T, EMBED);
    }

    // --- 3. K/V projections fused (V written transposed) ---
    {
        dim3 grid(EMBED / 128, (MKV + 127) / 128, 2);
        gemm_mma3kv<<<grid, 256, smem_m3>>>(yhi, ylo, wkhi, wklo, wvhi, wvlo,
                                            bk, bv, khi, vt, MKV, CROSS);
    }

    // --- 4. attention ---
    {
        dim3 grid(SEQ_T / 64, N_HEADS, BATCH);
        attn_mma<<<grid, AT_T, smem_attn>>>(qhi, qlo, khi, vt, xhi);
    }

    // --- 5. O projection ---
    {
        dim3 grid(EMBED / 128, (BATCH * SEQ_T) / 128);
        gemm_mma1<<<grid, 256, smem_m1>>>(xhi, wo, bo, out, BATCH * SEQ_T, EMBED);
    }
}

// round 15
// speedup vs baseline: 7.1005x; 1.1289x over previous
#include <cuda_runtime.h>
#include <cuda_fp16.h>
#include <cstdint>
#include <math.h>

#define N_HEADS 8
#define EMBED 640
#define CROSS 768
#define HEAD 80
#define BATCH 8
#define SEQ_T 4096
#define SEQ_S 77

// ---------------------------------------------------------------------------
// Scratch (no cudaMalloc allowed)
// ---------------------------------------------------------------------------
__device__ __align__(16) unsigned short g_xhi[BATCH * SEQ_T * EMBED];
__device__ __align__(16) unsigned short g_qhi[BATCH * SEQ_T * EMBED];
__device__ __align__(16) unsigned short g_qlo[BATCH * SEQ_T * EMBED];
__device__ __align__(16) unsigned short g_khi[BATCH * SEQ_S * EMBED];
// V transposed: [b][h][d][s], s-stride 80; pads s>=77 stay zero forever.
__device__ __align__(16) unsigned short g_vt[BATCH * N_HEADS * 80 * 80];
__device__ __align__(16) unsigned short g_yhi[BATCH * SEQ_S * CROSS];
__device__ __align__(16) unsigned short g_ylo[BATCH * SEQ_S * CROSS];
__device__ __align__(16) unsigned short g_wq[EMBED * EMBED];
__device__ __align__(16) unsigned short g_wo[EMBED * EMBED];
__device__ __align__(16) unsigned short g_wkhi[EMBED * CROSS];
__device__ __align__(16) unsigned short g_wklo[EMBED * CROSS];
__device__ __align__(16) unsigned short g_wvhi[EMBED * CROSS];
__device__ __align__(16) unsigned short g_wvlo[EMBED * CROSS];

// ---------------------------------------------------------------------------
// PTX helpers
// ---------------------------------------------------------------------------
__device__ __forceinline__ uint32_t smem_to_u32(const void* smem_ptr) {
    uint32_t addr;
    asm("{ .reg .u64 tmp; cvta.to.shared.u64 tmp, %1; cvt.u32.u64 %0, tmp; }"
        : "=r"(addr) : "l"(smem_ptr));
    return addr;
}

#define LDSM4(r, addr) \
    asm volatile("ldmatrix.sync.aligned.m8n8.x4.shared.b16 {%0,%1,%2,%3},[%4];" \
        : "=r"((r)[0]), "=r"((r)[1]), "=r"((r)[2]), "=r"((r)[3]) : "r"(addr))

#define MMAF16(d, a, b) \
    asm volatile("mma.sync.aligned.m16n8k16.row.col.f32.f16.f16.f32 " \
        "{%0,%1,%2,%3},{%4,%5,%6,%7},{%8,%9},{%0,%1,%2,%3};" \
        : "+f"((d)[0]), "+f"((d)[1]), "+f"((d)[2]), "+f"((d)[3]) \
        : "r"((a)[0]), "r"((a)[1]), "r"((a)[2]), "r"((a)[3]), \
          "r"((b)[0]), "r"((b)[1]))

#define CP16(sp, gp) \
    asm volatile("cp.async.cg.shared.global [%0],[%1],16;" :: "r"(sp), "l"(gp))
#define CP_COMMIT() asm volatile("cp.async.commit_group;")
#define CP_WAIT2()  asm volatile("cp.async.wait_group 2;")
#define CP_WAIT1()  asm volatile("cp.async.wait_group 1;")
#define CP_WAIT0()  asm volatile("cp.async.wait_group 0;")

__device__ __forceinline__ unsigned short f16_hi(float f, float& rem) {
    __half h = __float2half_rn(f);
    rem = f - __half2float(h);
    return *(unsigned short*)&h;
}
__device__ __forceinline__ unsigned short f16_of(float f) {
    __half h = __float2half_rn(f);
    return *(unsigned short*)&h;
}
__device__ __forceinline__ uint32_t pack_f16x2(float lo, float hi) {
    uint32_t r;
    asm("cvt.rn.f16x2.f32 %0, %1, %2;" : "=r"(r) : "f"(hi), "f"(lo));
    return r;
}

// ---------------------------------------------------------------------------
// Fused preprocessing (x conv | y split | Wq tr | Wk/Wv tr+split | Wo tr)
// ---------------------------------------------------------------------------
#define PREP_XB   10240
#define PREP_YB   231
#define PREP_WQB  400
#define PREP_WKVB 960
#define PREP_WOB  400
__global__ void prep_all(const float4* __restrict__ x4,
                         const float4* __restrict__ y4,
                         const float* __restrict__ Wq,
                         const float* __restrict__ Wk,
                         const float* __restrict__ Wv,
                         const float* __restrict__ Wo,
                         uint4* __restrict__ xhi,
                         uint4* __restrict__ yhi, uint4* __restrict__ ylo,
                         unsigned short* __restrict__ wq,
                         unsigned short* __restrict__ wkhi, unsigned short* __restrict__ wklo,
                         unsigned short* __restrict__ wvhi, unsigned short* __restrict__ wvlo,
                         unsigned short* __restrict__ wo) {
    __shared__ float tile[32][33];
    const int blk = blockIdx.x;
    const int tid = threadIdx.x;

    if (blk < PREP_XB) {
        int i = blk * 256 + tid;
        float4 a = x4[2 * i];
        float4 b = x4[2 * i + 1];
        uint4 hv;
        hv.x = (uint32_t)f16_of(a.x) | ((uint32_t)f16_of(a.y) << 16);
        hv.y = (uint32_t)f16_of(a.z) | ((uint32_t)f16_of(a.w) << 16);
        hv.z = (uint32_t)f16_of(b.x) | ((uint32_t)f16_of(b.y) << 16);
        hv.w = (uint32_t)f16_of(b.z) | ((uint32_t)f16_of(b.w) << 16);
        xhi[i] = hv;
        return;
    }
    if (blk < PREP_XB + PREP_YB) {
        int i = (blk - PREP_XB) * 256 + tid;
        float4 a = y4[2 * i];
        float4 b = y4[2 * i + 1];
        float r[8];
        unsigned short h[8];
        h[0] = f16_hi(a.x, r[0]); h[1] = f16_hi(a.y, r[1]);
        h[2] = f16_hi(a.z, r[2]); h[3] = f16_hi(a.w, r[3]);
        h[4] = f16_hi(b.x, r[4]); h[5] = f16_hi(b.y, r[5]);
        h[6] = f16_hi(b.z, r[6]); h[7] = f16_hi(b.w, r[7]);
        uint4 hv, lv;
        hv.x = (uint32_t)h[0] | ((uint32_t)h[1] << 16);
        hv.y = (uint32_t)h[2] | ((uint32_t)h[3] << 16);
        hv.z = (uint32_t)h[4] | ((uint32_t)h[5] << 16);
        hv.w = (uint32_t)h[6] | ((uint32_t)h[7] << 16);
        lv.x = (uint32_t)f16_of(r[0]) | ((uint32_t)f16_of(r[1]) << 16);
        lv.y = (uint32_t)f16_of(r[2]) | ((uint32_t)f16_of(r[3]) << 16);
        lv.z = (uint32_t)f16_of(r[4]) | ((uint32_t)f16_of(r[5]) << 16);
        lv.w = (uint32_t)f16_of(r[6]) | ((uint32_t)f16_of(r[7]) << 16);
        yhi[i] = hv;
        ylo[i] = lv;
        return;
    }

    const int tx = tid & 31;
    const int ty = tid >> 5;

    const float* W;
    unsigned short *thi, *tlo = nullptr;
    int K, t;
    if (blk < PREP_XB + PREP_YB + PREP_WQB) {
        t = blk - (PREP_XB + PREP_YB);
        W = Wq; thi = wq; K = EMBED;
    } else if (blk < PREP_XB + PREP_YB + PREP_WQB + PREP_WKVB) {
        t = blk - (PREP_XB + PREP_YB + PREP_WQB);
        int z = t / 480;
        t = t % 480;
        W = z ? Wv : Wk;
        thi = z ? wvhi : wkhi;
        tlo = z ? wvlo : wklo;
        K = CROSS;
    } else {
        t = blk - (PREP_XB + PREP_YB + PREP_WQB + PREP_WKVB);
        W = Wo; thi = wo; K = EMBED;
    }
    const int n0 = (t % 20) * 32;
    const int k0 = (t / 20) * 32;
#pragma unroll
    for (int i = 0; i < 32; i += 8)
        tile[ty + i][tx] = W[(size_t)(k0 + ty + i) * EMBED + n0 + tx];
    __syncthreads();
#pragma unroll
    for (int i = 0; i < 32; i += 8) {
        float v = tile[tx][ty + i];
        size_t oi = (size_t)(n0 + ty + i) * K + k0 + tx;
        if (tlo) {
            float rem;
            unsigned short h = f16_hi(v, rem);
            thi[oi] = h;
            tlo[oi] = f16_of(rem);
        } else {
            thi[oi] = f16_of(v);
        }
    }
}

// ---------------------------------------------------------------------------
// Fused K+V projections (z=0 -> K normal; z=1 -> V transposed into vt)
// ---------------------------------------------------------------------------
#define SLOT3 40960u
__global__ __launch_bounds__(256, 1)
void gemm_mma3kv(const unsigned short* __restrict__ Ahi,
                 const unsigned short* __restrict__ Alo,
                 const unsigned short* __restrict__ Bhi0,
                 const unsigned short* __restrict__ Blo0,
                 const unsigned short* __restrict__ Bhi1,
                 const unsigned short* __restrict__ Blo1,
                 const float* __restrict__ bias0,
                 const float* __restrict__ bias1,
                 unsigned short* __restrict__ Ck,
                 unsigned short* __restrict__ Cvt,
                 int M, int K) {
    extern __shared__ char smem[];
    const uint32_t sbase = smem_to_u32(smem);
    const int tid = threadIdx.x;
    const int lane = tid & 31;
    const int wid = tid >> 5;
    const int wm = wid >> 2;
    const int wn = wid & 3;
    const int bm = blockIdx.y * 128;
    const int bn = blockIdx.x * 128;
    const int rowU4 = K >> 3;
    const int nst = K >> 5;
    const int maxAr = (M - bm - 1 < 127) ? (M - bm - 1) : 127;
    const int isV = blockIdx.z;

    const unsigned short* Bhi = isV ? Bhi1 : Bhi0;
    const unsigned short* Blo = isV ? Blo1 : Blo0;
    const float* bias = isV ? bias1 : bias0;

    const uint4* gA0 = (const uint4*)(Ahi + (size_t)bm * K);
    const uint4* gA1 = (const uint4*)(Alo + (size_t)bm * K);
    const uint4* gB0 = (const uint4*)(Bhi + (size_t)bn * K);
    const uint4* gB1 = (const uint4*)(Blo + (size_t)bn * K);

    float d[4][4][4];
#pragma unroll
    for (int i = 0; i < 4; i++)
#pragma unroll
        for (int j = 0; j < 4; j++)
#pragma unroll
            for (int r = 0; r < 4; r++) d[i][j][r] = 0.f;

    auto load_stage = [&](int slot, int kt) {
        uint32_t sb = sbase + (uint32_t)slot * SLOT3;
#pragma unroll
        for (int j = 0; j < 8; j++) {
            int gidx = j * 256 + tid;
            int term = gidx >> 9;
            int idx = gidx & 511;
            int r = idx >> 2;
            int c = idx & 3;
            int re = (term < 2 && r > maxAr) ? maxAr : r;
            const uint4* src = (term == 0) ? gA0 : (term == 1) ? gA1
                             : (term == 2) ? gB0 : gB1;
            const uint4* gp = src + (size_t)re * rowU4 + kt * 4 + c;
            uint32_t sp = sb + (uint32_t)term * 10240u
                        + (uint32_t)(r * 80 + c * 16);
            CP16(sp, gp);
        }
        CP_COMMIT();
    };

    auto compute_stage = [&](int slot) {
        uint32_t sb = sbase + (uint32_t)slot * SLOT3;
        const uint32_t aOff[2] = {sb, sb + 10240u};
        const uint32_t bOff[2] = {sb + 20480u, sb + 30720u};
#pragma unroll
        for (int kk = 0; kk < 2; kk++) {
            const uint32_t colB = (uint32_t)(kk * 32) + ((lane & 16) ? 16u : 0u);
            uint32_t ah[4][4], al[4][4];
#pragma unroll
            for (int mt = 0; mt < 4; mt++) {
                int row = wm * 64 + mt * 16 + (lane & 15);
                LDSM4(ah[mt], aOff[0] + (uint32_t)(row * 80) + colB);
                LDSM4(al[mt], aOff[1] + (uint32_t)(row * 80) + colB);
            }
            uint32_t bh[4][2], bl[4][2];
#pragma unroll
            for (int nt2 = 0; nt2 < 2; nt2++) {
                int row = wn * 32 + nt2 * 16 + (lane & 15);
                uint32_t r4[4];
                LDSM4(r4, bOff[0] + (uint32_t)(row * 80) + colB);
                bh[nt2 * 2 + 0][0] = r4[0]; bh[nt2 * 2 + 0][1] = r4[2];
                bh[nt2 * 2 + 1][0] = r4[1]; bh[nt2 * 2 + 1][1] = r4[3];
                LDSM4(r4, bOff[1] + (uint32_t)(row * 80) + colB);
                bl[nt2 * 2 + 0][0] = r4[0]; bl[nt2 * 2 + 0][1] = r4[2];
                bl[nt2 * 2 + 1][0] = r4[1]; bl[nt2 * 2 + 1][1] = r4[3];
            }
#pragma unroll
            for (int mt = 0; mt < 4; mt++)
#pragma unroll
                for (int nt = 0; nt < 4; nt++) {
                    MMAF16(d[mt][nt], ah[mt], bh[nt]);
                    MMAF16(d[mt][nt], ah[mt], bl[nt]);
                    MMAF16(d[mt][nt], al[mt], bh[nt]);
                }
        }
    };

    load_stage(0, 0);
    load_stage(1, 1);
    for (int s = 0; s < nst; s++) {
        if (s + 1 < nst) { CP_WAIT1(); } else { CP_WAIT0(); }
        __syncthreads();
        if (s + 2 < nst) load_stage((s + 2) % 3, s + 2);
        compute_stage(s % 3);
    }

#pragma unroll
    for (int mt = 0; mt < 4; mt++) {
        int row0 = bm + wm * 64 + mt * 16 + (lane >> 2);
#pragma unroll
        for (int nt = 0; nt < 4; nt++) {
            int col = bn + wn * 32 + nt * 8 + (lane & 3) * 2;
            float2 bv = *(const float2*)&bias[col];
#pragma unroll
            for (int half = 0; half < 2; half++) {
                int row = row0 + half * 8;
                if (row >= M) continue;
                float v0 = d[mt][nt][half * 2 + 0] + bv.x;
                float v1 = d[mt][nt][half * 2 + 1] + bv.y;
                if (!isV) {
                    uint32_t p = (uint32_t)f16_of(v0) | ((uint32_t)f16_of(v1) << 16);
                    *(uint32_t*)&Ck[(size_t)row * EMBED + col] = p;
                } else {
                    int b = row / SEQ_S;
                    int s = row - b * SEQ_S;
                    int h = col / 80;
                    int dd = col - h * 80;
                    size_t base = ((size_t)(b * N_HEADS + h) * 80 + dd) * 80 + s;
                    Cvt[base] = f16_of(v0);
                    Cvt[base + 80] = f16_of(v1);
                }
            }
        }
    }
}

// ---------------------------------------------------------------------------
// 1-term fp16 GEMM core
// ---------------------------------------------------------------------------
#define SLOT1 20480u
template <int OUT16>
__device__ __forceinline__ void gemm1_body(
    const unsigned short* __restrict__ Ah,
    const unsigned short* __restrict__ Bh,
    const float* __restrict__ bias, float* __restrict__ C,
    unsigned short* __restrict__ Chi, unsigned short* __restrict__ Clo,
    float oscale, int M, int K, char* smem) {
    const uint32_t sbase = smem_to_u32(smem);
    const int tid = threadIdx.x;
    const int lane = tid & 31;
    const int wid = tid >> 5;
    const int wm = wid >> 2;
    const int wn = wid & 3;
    const int bm = blockIdx.y * 128;
    const int bn = blockIdx.x * 128;
    const int rowU4 = K >> 3;
    const int nst = K >> 5;

    const uint4* gA0 = (const uint4*)(Ah + (size_t)bm * K);
    const uint4* gB0 = (const uint4*)(Bh + (size_t)bn * K);

    float d[4][4][4];
#pragma unroll
    for (int i = 0; i < 4; i++)
#pragma unroll
        for (int j = 0; j < 4; j++)
#pragma unroll
            for (int r = 0; r < 4; r++) d[i][j][r] = 0.f;

    auto load_stage = [&](int slot, int kt) {
        uint32_t sb = sbase + (uint32_t)slot * SLOT1;
#pragma unroll
        for (int j = 0; j < 4; j++) {
            int gidx = j * 256 + tid;
            int term = gidx >> 9;
            int idx = gidx & 511;
            int r = idx >> 2;
            int c = idx & 3;
            const uint4* src = (term == 0) ? gA0 : gB0;
            const uint4* gp = src + (size_t)r * rowU4 + kt * 4 + c;
            uint32_t sp = sb + (uint32_t)term * 10240u
                        + (uint32_t)(r * 80 + c * 16);
            CP16(sp, gp);
        }
        CP_COMMIT();
    };

    auto compute_stage = [&](int slot) {
        uint32_t sb = sbase + (uint32_t)slot * SLOT1;
        const uint32_t aOff = sb;
        const uint32_t bOff = sb + 10240u;
#pragma unroll
        for (int kk = 0; kk < 2; kk++) {
            const uint32_t colB = (uint32_t)(kk * 32) + ((lane & 16) ? 16u : 0u);
            uint32_t ah[4][4];
#pragma unroll
            for (int mt = 0; mt < 4; mt++) {
                int row = wm * 64 + mt * 16 + (lane & 15);
                LDSM4(ah[mt], aOff + (uint32_t)(row * 80) + colB);
            }
            uint32_t bh[4][2];
#pragma unroll
            for (int nt2 = 0; nt2 < 2; nt2++) {
                int row = wn * 32 + nt2 * 16 + (lane & 15);
                uint32_t r4[4];
                LDSM4(r4, bOff + (uint32_t)(row * 80) + colB);
                bh[nt2 * 2 + 0][0] = r4[0]; bh[nt2 * 2 + 0][1] = r4[2];
                bh[nt2 * 2 + 1][0] = r4[1]; bh[nt2 * 2 + 1][1] = r4[3];
            }
#pragma unroll
            for (int mt = 0; mt < 4; mt++)
#pragma unroll
                for (int nt = 0; nt < 4; nt++)
                    MMAF16(d[mt][nt], ah[mt], bh[nt]);
        }
    };

    load_stage(0, 0);
    load_stage(1, 1);
    load_stage(2, 2);
    for (int s = 0; s < nst; s++) {
        if (s + 2 < nst) { CP_WAIT2(); }
        else if (s + 1 < nst) { CP_WAIT1(); }
        else { CP_WAIT0(); }
        __syncthreads();
        if (s + 3 < nst) load_stage((s + 3) & 3, s + 3);
        compute_stage(s & 3);
    }

#pragma unroll
    for (int mt = 0; mt < 4; mt++) {
        int row0 = bm + wm * 64 + mt * 16 + (lane >> 2);
#pragma unroll
        for (int nt = 0; nt < 4; nt++) {
            int col = bn + wn * 32 + nt * 8 + (lane & 3) * 2;
            float2 bv = *(const float2*)&bias[col];
#pragma unroll
            for (int half = 0; half < 2; half++) {
                int row = row0 + half * 8;
                float v0 = (d[mt][nt][half * 2 + 0] + bv.x) * oscale;
                float v1 = (d[mt][nt][half * 2 + 1] + bv.y) * oscale;
                if (OUT16) {
                    float r0, r1;
                    unsigned short h0 = f16_hi(v0, r0);
                    unsigned short h1 = f16_hi(v1, r1);
                    *(uint32_t*)&Chi[(size_t)row * EMBED + col] =
                        (uint32_t)h0 | ((uint32_t)h1 << 16);
                    *(uint32_t*)&Clo[(size_t)row * EMBED + col] =
                        (uint32_t)f16_of(r0) | ((uint32_t)f16_of(r1) << 16);
                } else {
                    *(float2*)&C[(size_t)row * EMBED + col] = make_float2(v0, v1);
                }
            }
        }
    }
}

__global__ __launch_bounds__(256, 2)
void gemm_mma1(const unsigned short* __restrict__ Ah,
               const unsigned short* __restrict__ Bh,
               const float* __restrict__ bias, float* __restrict__ C,
               int M, int K) {
    extern __shared__ char smem[];
    gemm1_body<0>(Ah, Bh, bias, C, nullptr, nullptr, 1.0f, M, K, smem);
}

__global__ __launch_bounds__(256, 2)
void gemm_mma1q(const unsigned short* __restrict__ Ah,
                const unsigned short* __restrict__ Bh,
                const float* __restrict__ bias,
                unsigned short* __restrict__ Chi,
                unsigned short* __restrict__ Clo,
                int M, int K) {
    extern __shared__ char smem[];
    gemm1_body<1>(Ah, Bh, bias, nullptr, Chi, Clo,
                  0.11180339887498949f, M, K, smem);
}

// ---------------------------------------------------------------------------
// Tensor-core attention: 64 t-rows x (b,h), 4 warps. q A-fragments loaded
// DIRECTLY from global (no q smem) -> smem = k + v^T only (28.2 KB).
// ---------------------------------------------------------------------------
#define AT_STR 88
#define AT_T 128
__global__ __launch_bounds__(AT_T)
void attn_mma(const unsigned short* __restrict__ qhi,
              const unsigned short* __restrict__ qlo,
              const unsigned short* __restrict__ khi,
              const unsigned short* __restrict__ vt,
              unsigned short* __restrict__ ohi) {
    extern __shared__ unsigned short smh[];
    unsigned short* skh = smh;                    // 80*88
    unsigned short* svt = skh + 80 * AT_STR;      // 80*88

    const int b = blockIdx.z;
    const int h = blockIdx.y;
    const int t0 = blockIdx.x * 64;
    const int tid = threadIdx.x;
    const int w = tid >> 5;
    const int lane = tid & 31;

    // ---- zero pads: skh rows 77..79 (svt pads come zero from gmem) ----
    for (int i = tid; i < 3 * AT_STR; i += AT_T)
        skh[77 * AT_STR + i] = 0;

    // ---- staging (vectorized) ----
    for (int i = tid; i < 770; i += AT_T) {       // k: 77 rows x 10 uint4
        int s = i / 10, c = i - s * 10;
        size_t gi = ((size_t)(b * SEQ_S + s)) * 80 + h * 10 + c;
        *(uint4*)&skh[s * AT_STR + c * 8] = ((const uint4*)khi)[gi];
    }
    {   // v^T: 80 d-rows x 10 uint4, contiguous in vt
        const uint4* vsrc = (const uint4*)(vt + ((size_t)(b * N_HEADS + h) * 80) * 80);
        for (int i = tid; i < 800; i += AT_T) {
            int dd = i / 10, c = i - dd * 10;
            *(uint4*)&svt[dd * AT_STR + c * 8] = vsrc[dd * 10 + c];
        }
    }

    // ---- q fragment base addresses in global (A-layout of m16n8k16) ----
    const size_t qrow0 = (size_t)(b * SEQ_T + t0 + w * 16 + (lane >> 2));
    const size_t qb0 = qrow0 * EMBED + h * 80 + (lane & 3) * 2;
    const size_t qb1 = qb0 + 8 * EMBED;   // row +8

    __syncthreads();

    const uint32_t skh_b = smem_to_u32(skh);
    const uint32_t svt_b = smem_to_u32(svt);
    const uint32_t lrow = (uint32_t)(lane & 15) * (AT_STR * 2);
    const uint32_t loff = (lane & 16) ? 16u : 0u;

    // ---- QK^T: q frags from gmem, k frags via ldmatrix ----
    float d[10][4];
#pragma unroll
    for (int nt = 0; nt < 10; nt++)
#pragma unroll
        for (int c = 0; c < 4; c++) d[nt][c] = 0.f;

#pragma unroll
    for (int ks = 0; ks < 5; ks++) {
        const uint32_t ca = (uint32_t)(ks * 32) + loff;
        uint32_t ah[4], al[4];
        ah[0] = *(const uint32_t*)&qhi[qb0 + ks * 16];
        ah[1] = *(const uint32_t*)&qhi[qb1 + ks * 16];
        ah[2] = *(const uint32_t*)&qhi[qb0 + ks * 16 + 8];
        ah[3] = *(const uint32_t*)&qhi[qb1 + ks * 16 + 8];
        al[0] = *(const uint32_t*)&qlo[qb0 + ks * 16];
        al[1] = *(const uint32_t*)&qlo[qb1 + ks * 16];
        al[2] = *(const uint32_t*)&qlo[qb0 + ks * 16 + 8];
        al[3] = *(const uint32_t*)&qlo[qb1 + ks * 16 + 8];
#pragma unroll
        for (int nt2 = 0; nt2 < 5; nt2++) {
            uint32_t r4[4];
            LDSM4(r4, skh_b + (uint32_t)(nt2 * 16) * (AT_STR * 2) + lrow + ca);
            uint32_t b0[2] = {r4[0], r4[2]};
            uint32_t b1[2] = {r4[1], r4[3]};
            MMAF16(d[nt2 * 2 + 0], ah, b0);
            MMAF16(d[nt2 * 2 + 0], al, b0);
            MMAF16(d[nt2 * 2 + 1], ah, b1);
            MMAF16(d[nt2 * 2 + 1], al, b1);
        }
    }

    {
        int colb = 72 + (lane & 3) * 2;
        if (colb >= 77)     { d[9][0] = -1e30f; d[9][2] = -1e30f; }
        if (colb + 1 >= 77) { d[9][1] = -1e30f; d[9][3] = -1e30f; }
    }

    {
        float mA = -1e30f, mB = -1e30f;
#pragma unroll
        for (int nt = 0; nt < 10; nt++) {
            mA = fmaxf(mA, fmaxf(d[nt][0], d[nt][1]));
            mB = fmaxf(mB, fmaxf(d[nt][2], d[nt][3]));
        }
        mA = fmaxf(mA, __shfl_xor_sync(0xFFFFFFFFu, mA, 1));
        mA = fmaxf(mA, __shfl_xor_sync(0xFFFFFFFFu, mA, 2));
        mB = fmaxf(mB, __shfl_xor_sync(0xFFFFFFFFu, mB, 1));
        mB = fmaxf(mB, __shfl_xor_sync(0xFFFFFFFFu, mB, 2));
        float sA = 0.f, sB = 0.f;
#pragma unroll
        for (int nt = 0; nt < 10; nt++) {
            d[nt][0] = __expf(d[nt][0] - mA); sA += d[nt][0];
            d[nt][1] = __expf(d[nt][1] - mA); sA += d[nt][1];
            d[nt][2] = __expf(d[nt][2] - mB); sB += d[nt][2];
            d[nt][3] = __expf(d[nt][3] - mB); sB += d[nt][3];
        }
        sA += __shfl_xor_sync(0xFFFFFFFFu, sA, 1);
        sA += __shfl_xor_sync(0xFFFFFFFFu, sA, 2);
        sB += __shfl_xor_sync(0xFFFFFFFFu, sB, 1);
        sB += __shfl_xor_sync(0xFFFFFFFFu, sB, 2);
        float rA = 1.f / sA, rB = 1.f / sB;
#pragma unroll
        for (int nt = 0; nt < 10; nt++) {
            d[nt][0] *= rA; d[nt][1] *= rA;
            d[nt][2] *= rB; d[nt][3] *= rB;
        }
    }

    uint32_t pa[5][4];
#pragma unroll
    for (int kp = 0; kp < 5; kp++) {
        pa[kp][0] = pack_f16x2(d[2 * kp][0],     d[2 * kp][1]);
        pa[kp][1] = pack_f16x2(d[2 * kp][2],     d[2 * kp][3]);
        pa[kp][2] = pack_f16x2(d[2 * kp + 1][0], d[2 * kp + 1][1]);
        pa[kp][3] = pack_f16x2(d[2 * kp + 1][2], d[2 * kp + 1][3]);
    }

    float o[10][4];
#pragma unroll
    for (int nt = 0; nt < 10; nt++)
#pragma unroll
        for (int c = 0; c < 4; c++) o[nt][c] = 0.f;

#pragma unroll
    for (int kp = 0; kp < 5; kp++) {
        const uint32_t ca = (uint32_t)(kp * 32) + loff;
#pragma unroll
        for (int nt2 = 0; nt2 < 5; nt2++) {
            uint32_t r4[4];
            LDSM4(r4, svt_b + (uint32_t)(nt2 * 16) * (AT_STR * 2) + lrow + ca);
            uint32_t b0[2] = {r4[0], r4[2]};
            uint32_t b1[2] = {r4[1], r4[3]};
            MMAF16(o[nt2 * 2 + 0], pa[kp], b0);
            MMAF16(o[nt2 * 2 + 1], pa[kp], b1);
        }
    }

    {
        const size_t rbase = (size_t)(b * SEQ_T + t0 + w * 16 + (lane >> 2));
        const int col = h * 80 + (lane & 3) * 2;
#pragma unroll
        for (int nt = 0; nt < 10; nt++) {
            *(uint32_t*)&ohi[rbase * EMBED + col + nt * 8] =
                pack_f16x2(o[nt][0], o[nt][1]);
            *(uint32_t*)&ohi[(rbase + 8) * EMBED + col + nt * 8] =
                pack_f16x2(o[nt][2], o[nt][3]);
        }
    }
}

// ---------------------------------------------------------------------------
extern "C" void kernel_launch(void* const* d_in, const int* in_sizes, int n_in,
                              void* d_out, int out_size) {
    const float* x  = (const float*)d_in[0];
    const float* y  = (const float*)d_in[1];
    const float* Wq = (const float*)d_in[2];
    const float* bq = (const float*)d_in[3];
    const float* Wk = (const float*)d_in[4];
    const float* bk = (const float*)d_in[5];
    const float* Wv = (const float*)d_in[6];
    const float* bv = (const float*)d_in[7];
    const float* Wo = (const float*)d_in[8];
    const float* bo = (const float*)d_in[9];
    float* out = (float*)d_out;

    unsigned short *xhi, *qhi, *qlo, *khi, *vt, *yhi, *ylo;
    unsigned short *wq, *wo, *wkhi, *wklo, *wvhi, *wvlo;
    cudaGetSymbolAddress((void**)&xhi, g_xhi);
    cudaGetSymbolAddress((void**)&qhi, g_qhi);
    cudaGetSymbolAddress((void**)&qlo, g_qlo);
    cudaGetSymbolAddress((void**)&khi, g_khi);
    cudaGetSymbolAddress((void**)&vt, g_vt);
    cudaGetSymbolAddress((void**)&yhi, g_yhi);
    cudaGetSymbolAddress((void**)&ylo, g_ylo);
    cudaGetSymbolAddress((void**)&wq, g_wq);
    cudaGetSymbolAddress((void**)&wo, g_wo);
    cudaGetSymbolAddress((void**)&wkhi, g_wkhi);
    cudaGetSymbolAddress((void**)&wklo, g_wklo);
    cudaGetSymbolAddress((void**)&wvhi, g_wvhi);
    cudaGetSymbolAddress((void**)&wvlo, g_wvlo);

    const int smem_attn = (80 * AT_STR * 2) * 2;  // 28160 B
    cudaFuncSetAttribute(attn_mma, cudaFuncAttributeMaxDynamicSharedMemorySize, smem_attn);
    const int smem_m3 = 3 * (int)SLOT3;
    cudaFuncSetAttribute(gemm_mma3kv, cudaFuncAttributeMaxDynamicSharedMemorySize, smem_m3);
    const int smem_m1 = 4 * (int)SLOT1;
    cudaFuncSetAttribute(gemm_mma1, cudaFuncAttributeMaxDynamicSharedMemorySize, smem_m1);
    cudaFuncSetAttribute(gemm_mma1q, cudaFuncAttributeMaxDynamicSharedMemorySize, smem_m1);

    const int MKV = BATCH * SEQ_S;

    // side stream for the KV projection (fork-join inside graph capture)
    cudaStream_t s2;
    cudaEvent_t e1, e2;
    cudaStreamCreateWithFlags(&s2, cudaStreamNonBlocking);
    cudaEventCreateWithFlags(&e1, cudaEventDisableTiming);
    cudaEventCreateWithFlags(&e2, cudaEventDisableTiming);

    // --- 1. fused preprocessing ---
    {
        int nblk = PREP_XB + PREP_YB + PREP_WQB + PREP_WKVB + PREP_WOB;
        prep_all<<<nblk, 256>>>((const float4*)x, (const float4*)y,
                                Wq, Wk, Wv, Wo,
                                (uint4*)xhi, (uint4*)yhi, (uint4*)ylo,
                                wq, wkhi, wklo, wvhi, wvlo, wo);
    }
    cudaEventRecord(e1, 0);
    cudaStreamWaitEvent(s2, e1, 0);

    // --- 2a. K/V projections on side stream (concurrent with Q-proj) ---
    {
        dim3 grid(EMBED / 128, (MKV + 127) / 128, 2);
        gemm_mma3kv<<<grid, 256, smem_m3, s2>>>(yhi, ylo, wkhi, wklo, wvhi, wvlo,
                                                bk, bv, khi, vt, MKV, CROSS);
    }
    cudaEventRecord(e2, s2);

    // --- 2b. Q projection on main stream ---
    {
        dim3 grid(EMBED / 128, (BATCH * SEQ_T) / 128);
        gemm_mma1q<<<grid, 256, smem_m1>>>(xhi, wq, bq, qhi, qlo, BATCH * SEQ_T, EMBED);
    }
    cudaStreamWaitEvent(0, e2, 0);

    // --- 3. attention ---
    {
        dim3 grid(SEQ_T / 64, N_HEADS, BATCH);
        attn_mma<<<grid, AT_T, smem_attn>>>(qhi, qlo, khi, vt, xhi);
    }

    // --- 4. O projection ---
    {
        dim3 grid(EMBED / 128, (BATCH * SEQ_T) / 128);
        gemm_mma1<<<grid, 256, smem_m1>>>(xhi, wo, bo, out, BATCH * SEQ_T, EMBED);
    }

    cudaEventDestroy(e1);
    cudaEventDestroy(e2);
    cudaStreamDestroy(s2);
}

// round 16
// speedup vs baseline: 7.7976x; 1.0982x over previous
#include <cuda_runtime.h>
#include <cuda_fp16.h>
#include <cstdint>
#include <math.h>

#define N_HEADS 8
#define EMBED 640
#define CROSS 768
#define HEAD 80
#define BATCH 8
#define SEQ_T 4096
#define SEQ_S 77

// ---------------------------------------------------------------------------
// Scratch (no cudaMalloc allowed)
// ---------------------------------------------------------------------------
__device__ __align__(16) unsigned short g_xhi[BATCH * SEQ_T * EMBED];
__device__ __align__(16) unsigned short g_qhi[BATCH * SEQ_T * EMBED];  // scaled q (fp16)
__device__ __align__(16) unsigned short g_khi[BATCH * SEQ_S * EMBED];
// V transposed: [b][h][d][s], s-stride 80; pads s>=77 stay zero forever.
__device__ __align__(16) unsigned short g_vt[BATCH * N_HEADS * 80 * 80];
__device__ __align__(16) unsigned short g_yhi[BATCH * SEQ_S * CROSS];
__device__ __align__(16) unsigned short g_ylo[BATCH * SEQ_S * CROSS];
__device__ __align__(16) unsigned short g_wq[EMBED * EMBED];
__device__ __align__(16) unsigned short g_wo[EMBED * EMBED];
__device__ __align__(16) unsigned short g_wkhi[EMBED * CROSS];
__device__ __align__(16) unsigned short g_wklo[EMBED * CROSS];
__device__ __align__(16) unsigned short g_wvhi[EMBED * CROSS];
__device__ __align__(16) unsigned short g_wvlo[EMBED * CROSS];

// ---------------------------------------------------------------------------
// PTX helpers
// ---------------------------------------------------------------------------
__device__ __forceinline__ uint32_t smem_to_u32(const void* smem_ptr) {
    uint32_t addr;
    asm("{ .reg .u64 tmp; cvta.to.shared.u64 tmp, %1; cvt.u32.u64 %0, tmp; }"
        : "=r"(addr) : "l"(smem_ptr));
    return addr;
}

#define LDSM4(r, addr) \
    asm volatile("ldmatrix.sync.aligned.m8n8.x4.shared.b16 {%0,%1,%2,%3},[%4];" \
        : "=r"((r)[0]), "=r"((r)[1]), "=r"((r)[2]), "=r"((r)[3]) : "r"(addr))

#define MMAF16(d, a, b) \
    asm volatile("mma.sync.aligned.m16n8k16.row.col.f32.f16.f16.f32 " \
        "{%0,%1,%2,%3},{%4,%5,%6,%7},{%8,%9},{%0,%1,%2,%3};" \
        : "+f"((d)[0]), "+f"((d)[1]), "+f"((d)[2]), "+f"((d)[3]) \
        : "r"((a)[0]), "r"((a)[1]), "r"((a)[2]), "r"((a)[3]), \
          "r"((b)[0]), "r"((b)[1]))

#define CP16(sp, gp) \
    asm volatile("cp.async.cg.shared.global [%0],[%1],16;" :: "r"(sp), "l"(gp))
#define CP_COMMIT() asm volatile("cp.async.commit_group;")
#define CP_WAIT2()  asm volatile("cp.async.wait_group 2;")
#define CP_WAIT1()  asm volatile("cp.async.wait_group 1;")
#define CP_WAIT0()  asm volatile("cp.async.wait_group 0;")

__device__ __forceinline__ unsigned short f16_hi(float f, float& rem) {
    __half h = __float2half_rn(f);
    rem = f - __half2float(h);
    return *(unsigned short*)&h;
}
__device__ __forceinline__ unsigned short f16_of(float f) {
    __half h = __float2half_rn(f);
    return *(unsigned short*)&h;
}
__device__ __forceinline__ uint32_t pack_f16x2(float lo, float hi) {
    uint32_t r;
    asm("cvt.rn.f16x2.f32 %0, %1, %2;" : "=r"(r) : "f"(hi), "f"(lo));
    return r;
}

// ---------------------------------------------------------------------------
// Fused preprocessing (x conv | y split | Wq tr | Wk/Wv tr+split | Wo tr)
// ---------------------------------------------------------------------------
#define PREP_XB   10240
#define PREP_YB   231
#define PREP_WQB  400
#define PREP_WKVB 960
#define PREP_WOB  400
__global__ void prep_all(const float4* __restrict__ x4,
                         const float4* __restrict__ y4,
                         const float* __restrict__ Wq,
                         const float* __restrict__ Wk,
                         const float* __restrict__ Wv,
                         const float* __restrict__ Wo,
                         uint4* __restrict__ xhi,
                         uint4* __restrict__ yhi, uint4* __restrict__ ylo,
                         unsigned short* __restrict__ wq,
                         unsigned short* __restrict__ wkhi, unsigned short* __restrict__ wklo,
                         unsigned short* __restrict__ wvhi, unsigned short* __restrict__ wvlo,
                         unsigned short* __restrict__ wo) {
    __shared__ float tile[32][33];
    const int blk = blockIdx.x;
    const int tid = threadIdx.x;

    if (blk < PREP_XB) {
        int i = blk * 256 + tid;
        float4 a = x4[2 * i];
        float4 b = x4[2 * i + 1];
        uint4 hv;
        hv.x = (uint32_t)f16_of(a.x) | ((uint32_t)f16_of(a.y) << 16);
        hv.y = (uint32_t)f16_of(a.z) | ((uint32_t)f16_of(a.w) << 16);
        hv.z = (uint32_t)f16_of(b.x) | ((uint32_t)f16_of(b.y) << 16);
        hv.w = (uint32_t)f16_of(b.z) | ((uint32_t)f16_of(b.w) << 16);
        xhi[i] = hv;
        return;
    }
    if (blk < PREP_XB + PREP_YB) {
        int i = (blk - PREP_XB) * 256 + tid;
        float4 a = y4[2 * i];
        float4 b = y4[2 * i + 1];
        float r[8];
        unsigned short h[8];
        h[0] = f16_hi(a.x, r[0]); h[1] = f16_hi(a.y, r[1]);
        h[2] = f16_hi(a.z, r[2]); h[3] = f16_hi(a.w, r[3]);
        h[4] = f16_hi(b.x, r[4]); h[5] = f16_hi(b.y, r[5]);
        h[6] = f16_hi(b.z, r[6]); h[7] = f16_hi(b.w, r[7]);
        uint4 hv, lv;
        hv.x = (uint32_t)h[0] | ((uint32_t)h[1] << 16);
        hv.y = (uint32_t)h[2] | ((uint32_t)h[3] << 16);
        hv.z = (uint32_t)h[4] | ((uint32_t)h[5] << 16);
        hv.w = (uint32_t)h[6] | ((uint32_t)h[7] << 16);
        lv.x = (uint32_t)f16_of(r[0]) | ((uint32_t)f16_of(r[1]) << 16);
        lv.y = (uint32_t)f16_of(r[2]) | ((uint32_t)f16_of(r[3]) << 16);
        lv.z = (uint32_t)f16_of(r[4]) | ((uint32_t)f16_of(r[5]) << 16);
        lv.w = (uint32_t)f16_of(r[6]) | ((uint32_t)f16_of(r[7]) << 16);
        yhi[i] = hv;
        ylo[i] = lv;
        return;
    }

    const int tx = tid & 31;
    const int ty = tid >> 5;

    const float* W;
    unsigned short *thi, *tlo = nullptr;
    int K, t;
    if (blk < PREP_XB + PREP_YB + PREP_WQB) {
        t = blk - (PREP_XB + PREP_YB);
        W = Wq; thi = wq; K = EMBED;
    } else if (blk < PREP_XB + PREP_YB + PREP_WQB + PREP_WKVB) {
        t = blk - (PREP_XB + PREP_YB + PREP_WQB);
        int z = t / 480;
        t = t % 480;
        W = z ? Wv : Wk;
        thi = z ? wvhi : wkhi;
        tlo = z ? wvlo : wklo;
        K = CROSS;
    } else {
        t = blk - (PREP_XB + PREP_YB + PREP_WQB + PREP_WKVB);
        W = Wo; thi = wo; K = EMBED;
    }
    const int n0 = (t % 20) * 32;
    const int k0 = (t / 20) * 32;
#pragma unroll
    for (int i = 0; i < 32; i += 8)
        tile[ty + i][tx] = W[(size_t)(k0 + ty + i) * EMBED + n0 + tx];
    __syncthreads();
#pragma unroll
    for (int i = 0; i < 32; i += 8) {
        float v = tile[tx][ty + i];
        size_t oi = (size_t)(n0 + ty + i) * K + k0 + tx;
        if (tlo) {
            float rem;
            unsigned short h = f16_hi(v, rem);
            thi[oi] = h;
            tlo[oi] = f16_of(rem);
        } else {
            thi[oi] = f16_of(v);
        }
    }
}

// ---------------------------------------------------------------------------
// Fused K+V projections (z=0 -> K normal; z=1 -> V transposed into vt)
// ---------------------------------------------------------------------------
#define SLOT3 40960u
__global__ __launch_bounds__(256, 1)
void gemm_mma3kv(const unsigned short* __restrict__ Ahi,
                 const unsigned short* __restrict__ Alo,
                 const unsigned short* __restrict__ Bhi0,
                 const unsigned short* __restrict__ Blo0,
                 const unsigned short* __restrict__ Bhi1,
                 const unsigned short* __restrict__ Blo1,
                 const float* __restrict__ bias0,
                 const float* __restrict__ bias1,
                 unsigned short* __restrict__ Ck,
                 unsigned short* __restrict__ Cvt,
                 int M, int K) {
    extern __shared__ char smem[];
    const uint32_t sbase = smem_to_u32(smem);
    const int tid = threadIdx.x;
    const int lane = tid & 31;
    const int wid = tid >> 5;
    const int wm = wid >> 2;
    const int wn = wid & 3;
    const int bm = blockIdx.y * 128;
    const int bn = blockIdx.x * 128;
    const int rowU4 = K >> 3;
    const int nst = K >> 5;
    const int maxAr = (M - bm - 1 < 127) ? (M - bm - 1) : 127;
    const int isV = blockIdx.z;

    const unsigned short* Bhi = isV ? Bhi1 : Bhi0;
    const unsigned short* Blo = isV ? Blo1 : Blo0;
    const float* bias = isV ? bias1 : bias0;

    const uint4* gA0 = (const uint4*)(Ahi + (size_t)bm * K);
    const uint4* gA1 = (const uint4*)(Alo + (size_t)bm * K);
    const uint4* gB0 = (const uint4*)(Bhi + (size_t)bn * K);
    const uint4* gB1 = (const uint4*)(Blo + (size_t)bn * K);

    float d[4][4][4];
#pragma unroll
    for (int i = 0; i < 4; i++)
#pragma unroll
        for (int j = 0; j < 4; j++)
#pragma unroll
            for (int r = 0; r < 4; r++) d[i][j][r] = 0.f;

    auto load_stage = [&](int slot, int kt) {
        uint32_t sb = sbase + (uint32_t)slot * SLOT3;
#pragma unroll
        for (int j = 0; j < 8; j++) {
            int gidx = j * 256 + tid;
            int term = gidx >> 9;
            int idx = gidx & 511;
            int r = idx >> 2;
            int c = idx & 3;
            int re = (term < 2 && r > maxAr) ? maxAr : r;
            const uint4* src = (term == 0) ? gA0 : (term == 1) ? gA1
                             : (term == 2) ? gB0 : gB1;
            const uint4* gp = src + (size_t)re * rowU4 + kt * 4 + c;
            uint32_t sp = sb + (uint32_t)term * 10240u
                        + (uint32_t)(r * 80 + c * 16);
            CP16(sp, gp);
        }
        CP_COMMIT();
    };

    auto compute_stage = [&](int slot) {
        uint32_t sb = sbase + (uint32_t)slot * SLOT3;
        const uint32_t aOff[2] = {sb, sb + 10240u};
        const uint32_t bOff[2] = {sb + 20480u, sb + 30720u};
#pragma unroll
        for (int kk = 0; kk < 2; kk++) {
            const uint32_t colB = (uint32_t)(kk * 32) + ((lane & 16) ? 16u : 0u);
            uint32_t ah[4][4], al[4][4];
#pragma unroll
            for (int mt = 0; mt < 4; mt++) {
                int row = wm * 64 + mt * 16 + (lane & 15);
                LDSM4(ah[mt], aOff[0] + (uint32_t)(row * 80) + colB);
                LDSM4(al[mt], aOff[1] + (uint32_t)(row * 80) + colB);
            }
            uint32_t bh[4][2], bl[4][2];
#pragma unroll
            for (int nt2 = 0; nt2 < 2; nt2++) {
                int row = wn * 32 + nt2 * 16 + (lane & 15);
                uint32_t r4[4];
                LDSM4(r4, bOff[0] + (uint32_t)(row * 80) + colB);
                bh[nt2 * 2 + 0][0] = r4[0]; bh[nt2 * 2 + 0][1] = r4[2];
                bh[nt2 * 2 + 1][0] = r4[1]; bh[nt2 * 2 + 1][1] = r4[3];
                LDSM4(r4, bOff[1] + (uint32_t)(row * 80) + colB);
                bl[nt2 * 2 + 0][0] = r4[0]; bl[nt2 * 2 + 0][1] = r4[2];
                bl[nt2 * 2 + 1][0] = r4[1]; bl[nt2 * 2 + 1][1] = r4[3];
            }
#pragma unroll
            for (int mt = 0; mt < 4; mt++)
#pragma unroll
                for (int nt = 0; nt < 4; nt++) {
                    MMAF16(d[mt][nt], ah[mt], bh[nt]);
                    MMAF16(d[mt][nt], ah[mt], bl[nt]);
                    MMAF16(d[mt][nt], al[mt], bh[nt]);
                }
        }
    };

    load_stage(0, 0);
    load_stage(1, 1);
    for (int s = 0; s < nst; s++) {
        if (s + 1 < nst) { CP_WAIT1(); } else { CP_WAIT0(); }
        __syncthreads();
        if (s + 2 < nst) load_stage((s + 2) % 3, s + 2);
        compute_stage(s % 3);
    }

#pragma unroll
    for (int mt = 0; mt < 4; mt++) {
        int row0 = bm + wm * 64 + mt * 16 + (lane >> 2);
#pragma unroll
        for (int nt = 0; nt < 4; nt++) {
            int col = bn + wn * 32 + nt * 8 + (lane & 3) * 2;
            float2 bv = *(const float2*)&bias[col];
#pragma unroll
            for (int half = 0; half < 2; half++) {
                int row = row0 + half * 8;
                if (row >= M) continue;
                float v0 = d[mt][nt][half * 2 + 0] + bv.x;
                float v1 = d[mt][nt][half * 2 + 1] + bv.y;
                if (!isV) {
                    uint32_t p = (uint32_t)f16_of(v0) | ((uint32_t)f16_of(v1) << 16);
                    *(uint32_t*)&Ck[(size_t)row * EMBED + col] = p;
                } else {
                    int b = row / SEQ_S;
                    int s = row - b * SEQ_S;
                    int h = col / 80;
                    int dd = col - h * 80;
                    size_t base = ((size_t)(b * N_HEADS + h) * 80 + dd) * 80 + s;
                    Cvt[base] = f16_of(v0);
                    Cvt[base + 80] = f16_of(v1);
                }
            }
        }
    }
}

// ---------------------------------------------------------------------------
// 1-term fp16 GEMM core. OUT: 0 = fp32, 2 = scaled fp16 (hi only)
// ---------------------------------------------------------------------------
#define SLOT1 20480u
template <int OUT>
__device__ __forceinline__ void gemm1_body(
    const unsigned short* __restrict__ Ah,
    const unsigned short* __restrict__ Bh,
    const float* __restrict__ bias, float* __restrict__ C,
    unsigned short* __restrict__ Chi,
    float oscale, int M, int K, char* smem) {
    const uint32_t sbase = smem_to_u32(smem);
    const int tid = threadIdx.x;
    const int lane = tid & 31;
    const int wid = tid >> 5;
    const int wm = wid >> 2;
    const int wn = wid & 3;
    const int bm = blockIdx.y * 128;
    const int bn = blockIdx.x * 128;
    const int rowU4 = K >> 3;
    const int nst = K >> 5;

    const uint4* gA0 = (const uint4*)(Ah + (size_t)bm * K);
    const uint4* gB0 = (const uint4*)(Bh + (size_t)bn * K);

    float d[4][4][4];
#pragma unroll
    for (int i = 0; i < 4; i++)
#pragma unroll
        for (int j = 0; j < 4; j++)
#pragma unroll
            for (int r = 0; r < 4; r++) d[i][j][r] = 0.f;

    auto load_stage = [&](int slot, int kt) {
        uint32_t sb = sbase + (uint32_t)slot * SLOT1;
#pragma unroll
        for (int j = 0; j < 4; j++) {
            int gidx = j * 256 + tid;
            int term = gidx >> 9;
            int idx = gidx & 511;
            int r = idx >> 2;
            int c = idx & 3;
            const uint4* src = (term == 0) ? gA0 : gB0;
            const uint4* gp = src + (size_t)r * rowU4 + kt * 4 + c;
            uint32_t sp = sb + (uint32_t)term * 10240u
                        + (uint32_t)(r * 80 + c * 16);
            CP16(sp, gp);
        }
        CP_COMMIT();
    };

    auto compute_stage = [&](int slot) {
        uint32_t sb = sbase + (uint32_t)slot * SLOT1;
        const uint32_t aOff = sb;
        const uint32_t bOff = sb + 10240u;
#pragma unroll
        for (int kk = 0; kk < 2; kk++) {
            const uint32_t colB = (uint32_t)(kk * 32) + ((lane & 16) ? 16u : 0u);
            uint32_t ah[4][4];
#pragma unroll
            for (int mt = 0; mt < 4; mt++) {
                int row = wm * 64 + mt * 16 + (lane & 15);
                LDSM4(ah[mt], aOff + (uint32_t)(row * 80) + colB);
            }
            uint32_t bh[4][2];
#pragma unroll
            for (int nt2 = 0; nt2 < 2; nt2++) {
                int row = wn * 32 + nt2 * 16 + (lane & 15);
                uint32_t r4[4];
                LDSM4(r4, bOff + (uint32_t)(row * 80) + colB);
                bh[nt2 * 2 + 0][0] = r4[0]; bh[nt2 * 2 + 0][1] = r4[2];
                bh[nt2 * 2 + 1][0] = r4[1]; bh[nt2 * 2 + 1][1] = r4[3];
            }
#pragma unroll
            for (int mt = 0; mt < 4; mt++)
#pragma unroll
                for (int nt = 0; nt < 4; nt++)
                    MMAF16(d[mt][nt], ah[mt], bh[nt]);
        }
    };

    load_stage(0, 0);
    load_stage(1, 1);
    load_stage(2, 2);
    for (int s = 0; s < nst; s++) {
        if (s + 2 < nst) { CP_WAIT2(); }
        else if (s + 1 < nst) { CP_WAIT1(); }
        else { CP_WAIT0(); }
        __syncthreads();
        if (s + 3 < nst) load_stage((s + 3) & 3, s + 3);
        compute_stage(s & 3);
    }

#pragma unroll
    for (int mt = 0; mt < 4; mt++) {
        int row0 = bm + wm * 64 + mt * 16 + (lane >> 2);
#pragma unroll
        for (int nt = 0; nt < 4; nt++) {
            int col = bn + wn * 32 + nt * 8 + (lane & 3) * 2;
            float2 bv = *(const float2*)&bias[col];
#pragma unroll
            for (int half = 0; half < 2; half++) {
                int row = row0 + half * 8;
                float v0 = (d[mt][nt][half * 2 + 0] + bv.x) * oscale;
                float v1 = (d[mt][nt][half * 2 + 1] + bv.y) * oscale;
                if (OUT == 2) {
                    *(uint32_t*)&Chi[(size_t)row * EMBED + col] =
                        (uint32_t)f16_of(v0) | ((uint32_t)f16_of(v1) << 16);
                } else {
                    *(float2*)&C[(size_t)row * EMBED + col] = make_float2(v0, v1);
                }
            }
        }
    }
}

__global__ __launch_bounds__(256, 2)
void gemm_mma1(const unsigned short* __restrict__ Ah,
               const unsigned short* __restrict__ Bh,
               const float* __restrict__ bias, float* __restrict__ C,
               int M, int K) {
    extern __shared__ char smem[];
    gemm1_body<0>(Ah, Bh, bias, C, nullptr, 1.0f, M, K, smem);
}

__global__ __launch_bounds__(256, 2)
void gemm_mma1q(const unsigned short* __restrict__ Ah,
                const unsigned short* __restrict__ Bh,
                const float* __restrict__ bias,
                unsigned short* __restrict__ Chi,
                int M, int K) {
    extern __shared__ char smem[];
    gemm1_body<2>(Ah, Bh, bias, nullptr, Chi,
                  0.11180339887498949f, M, K, smem);
}

// ---------------------------------------------------------------------------
// Tensor-core attention: 64 t-rows x (b,h), 4 warps. q A-fragments loaded
// directly from gmem (1-term fp16); smem = k + v^T (28.2 KB).
// ---------------------------------------------------------------------------
#define AT_STR 88
#define AT_T 128
__global__ __launch_bounds__(AT_T)
void attn_mma(const unsigned short* __restrict__ qhi,
              const unsigned short* __restrict__ khi,
              const unsigned short* __restrict__ vt,
              unsigned short* __restrict__ ohi) {
    extern __shared__ unsigned short smh[];
    unsigned short* skh = smh;                    // 80*88
    unsigned short* svt = skh + 80 * AT_STR;      // 80*88

    const int b = blockIdx.z;
    const int h = blockIdx.y;
    const int t0 = blockIdx.x * 64;
    const int tid = threadIdx.x;
    const int w = tid >> 5;
    const int lane = tid & 31;

    for (int i = tid; i < 3 * AT_STR; i += AT_T)
        skh[77 * AT_STR + i] = 0;

    for (int i = tid; i < 770; i += AT_T) {
        int s = i / 10, c = i - s * 10;
        size_t gi = ((size_t)(b * SEQ_S + s)) * 80 + h * 10 + c;
        *(uint4*)&skh[s * AT_STR + c * 8] = ((const uint4*)khi)[gi];
    }
    {
        const uint4* vsrc = (const uint4*)(vt + ((size_t)(b * N_HEADS + h) * 80) * 80);
        for (int i = tid; i < 800; i += AT_T) {
            int dd = i / 10, c = i - dd * 10;
            *(uint4*)&svt[dd * AT_STR + c * 8] = vsrc[dd * 10 + c];
        }
    }

    const size_t qrow0 = (size_t)(b * SEQ_T + t0 + w * 16 + (lane >> 2));
    const size_t qb0 = qrow0 * EMBED + h * 80 + (lane & 3) * 2;
    const size_t qb1 = qb0 + 8 * EMBED;

    __syncthreads();

    const uint32_t skh_b = smem_to_u32(skh);
    const uint32_t svt_b = smem_to_u32(svt);
    const uint32_t lrow = (uint32_t)(lane & 15) * (AT_STR * 2);
    const uint32_t loff = (lane & 16) ? 16u : 0u;

    float d[10][4];
#pragma unroll
    for (int nt = 0; nt < 10; nt++)
#pragma unroll
        for (int c = 0; c < 4; c++) d[nt][c] = 0.f;

#pragma unroll
    for (int ks = 0; ks < 5; ks++) {
        const uint32_t ca = (uint32_t)(ks * 32) + loff;
        uint32_t ah[4];
        ah[0] = *(const uint32_t*)&qhi[qb0 + ks * 16];
        ah[1] = *(const uint32_t*)&qhi[qb1 + ks * 16];
        ah[2] = *(const uint32_t*)&qhi[qb0 + ks * 16 + 8];
        ah[3] = *(const uint32_t*)&qhi[qb1 + ks * 16 + 8];
#pragma unroll
        for (int nt2 = 0; nt2 < 5; nt2++) {
            uint32_t r4[4];
            LDSM4(r4, skh_b + (uint32_t)(nt2 * 16) * (AT_STR * 2) + lrow + ca);
            uint32_t b0[2] = {r4[0], r4[2]};
            uint32_t b1[2] = {r4[1], r4[3]};
            MMAF16(d[nt2 * 2 + 0], ah, b0);
            MMAF16(d[nt2 * 2 + 1], ah, b1);
        }
    }

    {
        int colb = 72 + (lane & 3) * 2;
        if (colb >= 77)     { d[9][0] = -1e30f; d[9][2] = -1e30f; }
        if (colb + 1 >= 77) { d[9][1] = -1e30f; d[9][3] = -1e30f; }
    }

    {
        float mA = -1e30f, mB = -1e30f;
#pragma unroll
        for (int nt = 0; nt < 10; nt++) {
            mA = fmaxf(mA, fmaxf(d[nt][0], d[nt][1]));
            mB = fmaxf(mB, fmaxf(d[nt][2], d[nt][3]));
        }
        mA = fmaxf(mA, __shfl_xor_sync(0xFFFFFFFFu, mA, 1));
        mA = fmaxf(mA, __shfl_xor_sync(0xFFFFFFFFu, mA, 2));
        mB = fmaxf(mB, __shfl_xor_sync(0xFFFFFFFFu, mB, 1));
        mB = fmaxf(mB, __shfl_xor_sync(0xFFFFFFFFu, mB, 2));
        float sA = 0.f, sB = 0.f;
#pragma unroll
        for (int nt = 0; nt < 10; nt++) {
            d[nt][0] = __expf(d[nt][0] - mA); sA += d[nt][0];
            d[nt][1] = __expf(d[nt][1] - mA); sA += d[nt][1];
            d[nt][2] = __expf(d[nt][2] - mB); sB += d[nt][2];
            d[nt][3] = __expf(d[nt][3] - mB); sB += d[nt][3];
        }
        sA += __shfl_xor_sync(0xFFFFFFFFu, sA, 1);
        sA += __shfl_xor_sync(0xFFFFFFFFu, sA, 2);
        sB += __shfl_xor_sync(0xFFFFFFFFu, sB, 1);
        sB += __shfl_xor_sync(0xFFFFFFFFu, sB, 2);
        float rA = 1.f / sA, rB = 1.f / sB;
#pragma unroll
        for (int nt = 0; nt < 10; nt++) {
            d[nt][0] *= rA; d[nt][1] *= rA;
            d[nt][2] *= rB; d[nt][3] *= rB;
        }
    }

    uint32_t pa[5][4];
#pragma unroll
    for (int kp = 0; kp < 5; kp++) {
        pa[kp][0] = pack_f16x2(d[2 * kp][0],     d[2 * kp][1]);
        pa[kp][1] = pack_f16x2(d[2 * kp][2],     d[2 * kp][3]);
        pa[kp][2] = pack_f16x2(d[2 * kp + 1][0], d[2 * kp + 1][1]);
        pa[kp][3] = pack_f16x2(d[2 * kp + 1][2], d[2 * kp + 1][3]);
    }

    float o[10][4];
#pragma unroll
    for (int nt = 0; nt < 10; nt++)
#pragma unroll
        for (int c = 0; c < 4; c++) o[nt][c] = 0.f;

#pragma unroll
    for (int kp = 0; kp < 5; kp++) {
        const uint32_t ca = (uint32_t)(kp * 32) + loff;
#pragma unroll
        for (int nt2 = 0; nt2 < 5; nt2++) {
            uint32_t r4[4];
            LDSM4(r4, svt_b + (uint32_t)(nt2 * 16) * (AT_STR * 2) + lrow + ca);
            uint32_t b0[2] = {r4[0], r4[2]};
            uint32_t b1[2] = {r4[1], r4[3]};
            MMAF16(o[nt2 * 2 + 0], pa[kp], b0);
            MMAF16(o[nt2 * 2 + 1], pa[kp], b1);
        }
    }

    {
        const size_t rbase = (size_t)(b * SEQ_T + t0 + w * 16 + (lane >> 2));
        const int col = h * 80 + (lane & 3) * 2;
#pragma unroll
        for (int nt = 0; nt < 10; nt++) {
            *(uint32_t*)&ohi[rbase * EMBED + col + nt * 8] =
                pack_f16x2(o[nt][0], o[nt][1]);
            *(uint32_t*)&ohi[(rbase + 8) * EMBED + col + nt * 8] =
                pack_f16x2(o[nt][2], o[nt][3]);
        }
    }
}

// ---------------------------------------------------------------------------
extern "C" void kernel_launch(void* const* d_in, const int* in_sizes, int n_in,
                              void* d_out, int out_size) {
    const float* x  = (const float*)d_in[0];
    const float* y  = (const float*)d_in[1];
    const float* Wq = (const float*)d_in[2];
    const float* bq = (const float*)d_in[3];
    const float* Wk = (const float*)d_in[4];
    const float* bk = (const float*)d_in[5];
    const float* Wv = (const float*)d_in[6];
    const float* bv = (const float*)d_in[7];
    const float* Wo = (const float*)d_in[8];
    const float* bo = (const float*)d_in[9];
    float* out = (float*)d_out;

    unsigned short *xhi, *qhi, *khi, *vt, *yhi, *ylo;
    unsigned short *wq, *wo, *wkhi, *wklo, *wvhi, *wvlo;
    cudaGetSymbolAddress((void**)&xhi, g_xhi);
    cudaGetSymbolAddress((void**)&qhi, g_qhi);
    cudaGetSymbolAddress((void**)&khi, g_khi);
    cudaGetSymbolAddress((void**)&vt, g_vt);
    cudaGetSymbolAddress((void**)&yhi, g_yhi);
    cudaGetSymbolAddress((void**)&ylo, g_ylo);
    cudaGetSymbolAddress((void**)&wq, g_wq);
    cudaGetSymbolAddress((void**)&wo, g_wo);
    cudaGetSymbolAddress((void**)&wkhi, g_wkhi);
    cudaGetSymbolAddress((void**)&wklo, g_wklo);
    cudaGetSymbolAddress((void**)&wvhi, g_wvhi);
    cudaGetSymbolAddress((void**)&wvlo, g_wvlo);

    const int smem_attn = (80 * AT_STR * 2) * 2;  // 28160 B
    cudaFuncSetAttribute(attn_mma, cudaFuncAttributeMaxDynamicSharedMemorySize, smem_attn);
    const int smem_m3 = 3 * (int)SLOT3;
    cudaFuncSetAttribute(gemm_mma3kv, cudaFuncAttributeMaxDynamicSharedMemorySize, smem_m3);
    const int smem_m1 = 4 * (int)SLOT1;
    cudaFuncSetAttribute(gemm_mma1, cudaFuncAttributeMaxDynamicSharedMemorySize, smem_m1);
    cudaFuncSetAttribute(gemm_mma1q, cudaFuncAttributeMaxDynamicSharedMemorySize, smem_m1);

    const int MKV = BATCH * SEQ_S;

    cudaStream_t s2;
    cudaEvent_t e1, e2;
    cudaStreamCreateWithFlags(&s2, cudaStreamNonBlocking);
    cudaEventCreateWithFlags(&e1, cudaEventDisableTiming);
    cudaEventCreateWithFlags(&e2, cudaEventDisableTiming);

    // --- 1. fused preprocessing ---
    {
        int nblk = PREP_XB + PREP_YB + PREP_WQB + PREP_WKVB + PREP_WOB;
        prep_all<<<nblk, 256>>>((const float4*)x, (const float4*)y,
                                Wq, Wk, Wv, Wo,
                                (uint4*)xhi, (uint4*)yhi, (uint4*)ylo,
                                wq, wkhi, wklo, wvhi, wvlo, wo);
    }
    cudaEventRecord(e1, 0);
    cudaStreamWaitEvent(s2, e1, 0);

    // --- 2a. K/V projections on side stream ---
    {
        dim3 grid(EMBED / 128, (MKV + 127) / 128, 2);
        gemm_mma3kv<<<grid, 256, smem_m3, s2>>>(yhi, ylo, wkhi, wklo, wvhi, wvlo,
                                                bk, bv, khi, vt, MKV, CROSS);
    }
    cudaEventRecord(e2, s2);

    // --- 2b. Q projection on main stream (scaled fp16 out) ---
    {
        dim3 grid(EMBED / 128, (BATCH * SEQ_T) / 128);
        gemm_mma1q<<<grid, 256, smem_m1>>>(xhi, wq, bq, qhi, BATCH * SEQ_T, EMBED);
    }
    cudaStreamWaitEvent(0, e2, 0);

    // --- 3. attention ---
    {
        dim3 grid(SEQ_T / 64, N_HEADS, BATCH);
        attn_mma<<<grid, AT_T, smem_attn>>>(qhi, khi, vt, xhi);
    }

    // --- 4. O projection ---
    {
        dim3 grid(EMBED / 128, (BATCH * SEQ_T) / 128);
        gemm_mma1<<<grid, 256, smem_m1>>>(xhi, wo, bo, out, BATCH * SEQ_T, EMBED);
    }

    cudaEventDestroy(e1);
    cudaEventDestroy(e2);
    cudaStreamDestroy(s2);
}

// round 17
// speedup vs baseline: 7.9506x; 1.0196x over previous
#include <cuda_runtime.h>
#include <cuda_fp16.h>
#include <cstdint>
#include <math.h>

#define N_HEADS 8
#define EMBED 640
#define CROSS 768
#define HEAD 80
#define BATCH 8
#define SEQ_T 4096
#define SEQ_S 77

// ---------------------------------------------------------------------------
// Scratch (no cudaMalloc allowed)
// ---------------------------------------------------------------------------
__device__ __align__(16) unsigned short g_xhi[BATCH * SEQ_T * EMBED];
__device__ __align__(16) unsigned short g_qhi[BATCH * SEQ_T * EMBED];  // scaled q (fp16)
__device__ __align__(16) unsigned short g_khi[BATCH * SEQ_S * EMBED];
// V transposed: [b][h][d][s], s-stride 80; pads s>=77 stay zero forever.
__device__ __align__(16) unsigned short g_vt[BATCH * N_HEADS * 80 * 80];
__device__ __align__(16) unsigned short g_yhi[BATCH * SEQ_S * CROSS];
__device__ __align__(16) unsigned short g_ylo[BATCH * SEQ_S * CROSS];
__device__ __align__(16) unsigned short g_wq[EMBED * EMBED];
__device__ __align__(16) unsigned short g_wo[EMBED * EMBED];
__device__ __align__(16) unsigned short g_wkhi[EMBED * CROSS];
__device__ __align__(16) unsigned short g_wklo[EMBED * CROSS];
__device__ __align__(16) unsigned short g_wvhi[EMBED * CROSS];
__device__ __align__(16) unsigned short g_wvlo[EMBED * CROSS];

// ---------------------------------------------------------------------------
// PTX helpers
// ---------------------------------------------------------------------------
__device__ __forceinline__ uint32_t smem_to_u32(const void* smem_ptr) {
    uint32_t addr;
    asm("{ .reg .u64 tmp; cvta.to.shared.u64 tmp, %1; cvt.u32.u64 %0, tmp; }"
        : "=r"(addr) : "l"(smem_ptr));
    return addr;
}

#define LDSM4(r, addr) \
    asm volatile("ldmatrix.sync.aligned.m8n8.x4.shared.b16 {%0,%1,%2,%3},[%4];" \
        : "=r"((r)[0]), "=r"((r)[1]), "=r"((r)[2]), "=r"((r)[3]) : "r"(addr))

#define MMAF16(d, a, b) \
    asm volatile("mma.sync.aligned.m16n8k16.row.col.f32.f16.f16.f32 " \
        "{%0,%1,%2,%3},{%4,%5,%6,%7},{%8,%9},{%0,%1,%2,%3};" \
        : "+f"((d)[0]), "+f"((d)[1]), "+f"((d)[2]), "+f"((d)[3]) \
        : "r"((a)[0]), "r"((a)[1]), "r"((a)[2]), "r"((a)[3]), \
          "r"((b)[0]), "r"((b)[1]))

#define CP16(sp, gp) \
    asm volatile("cp.async.cg.shared.global [%0],[%1],16;" :: "r"(sp), "l"(gp))
#define CP_COMMIT() asm volatile("cp.async.commit_group;")
#define CP_WAIT2()  asm volatile("cp.async.wait_group 2;")
#define CP_WAIT1()  asm volatile("cp.async.wait_group 1;")
#define CP_WAIT0()  asm volatile("cp.async.wait_group 0;")

__device__ __forceinline__ unsigned short f16_hi(float f, float& rem) {
    __half h = __float2half_rn(f);
    rem = f - __half2float(h);
    return *(unsigned short*)&h;
}
__device__ __forceinline__ unsigned short f16_of(float f) {
    __half h = __float2half_rn(f);
    return *(unsigned short*)&h;
}
__device__ __forceinline__ uint32_t pack_f16x2(float lo, float hi) {
    uint32_t r;
    asm("cvt.rn.f16x2.f32 %0, %1, %2;" : "=r"(r) : "f"(hi), "f"(lo));
    return r;
}

// ---------------------------------------------------------------------------
// Fused preprocessing (x conv | y split | Wq tr | Wk/Wv tr+split | Wo tr)
// ---------------------------------------------------------------------------
#define PREP_XB   10240
#define PREP_YB   231
#define PREP_WQB  400
#define PREP_WKVB 960
#define PREP_WOB  400
__global__ void prep_all(const float4* __restrict__ x4,
                         const float4* __restrict__ y4,
                         const float* __restrict__ Wq,
                         const float* __restrict__ Wk,
                         const float* __restrict__ Wv,
                         const float* __restrict__ Wo,
                         uint4* __restrict__ xhi,
                         uint4* __restrict__ yhi, uint4* __restrict__ ylo,
                         unsigned short* __restrict__ wq,
                         unsigned short* __restrict__ wkhi, unsigned short* __restrict__ wklo,
                         unsigned short* __restrict__ wvhi, unsigned short* __restrict__ wvlo,
                         unsigned short* __restrict__ wo) {
    __shared__ float tile[32][33];
    const int blk = blockIdx.x;
    const int tid = threadIdx.x;

    if (blk < PREP_XB) {
        int i = blk * 256 + tid;
        float4 a = x4[2 * i];
        float4 b = x4[2 * i + 1];
        uint4 hv;
        hv.x = (uint32_t)f16_of(a.x) | ((uint32_t)f16_of(a.y) << 16);
        hv.y = (uint32_t)f16_of(a.z) | ((uint32_t)f16_of(a.w) << 16);
        hv.z = (uint32_t)f16_of(b.x) | ((uint32_t)f16_of(b.y) << 16);
        hv.w = (uint32_t)f16_of(b.z) | ((uint32_t)f16_of(b.w) << 16);
        xhi[i] = hv;
        return;
    }
    if (blk < PREP_XB + PREP_YB) {
        int i = (blk - PREP_XB) * 256 + tid;
        float4 a = y4[2 * i];
        float4 b = y4[2 * i + 1];
        float r[8];
        unsigned short h[8];
        h[0] = f16_hi(a.x, r[0]); h[1] = f16_hi(a.y, r[1]);
        h[2] = f16_hi(a.z, r[2]); h[3] = f16_hi(a.w, r[3]);
        h[4] = f16_hi(b.x, r[4]); h[5] = f16_hi(b.y, r[5]);
        h[6] = f16_hi(b.z, r[6]); h[7] = f16_hi(b.w, r[7]);
        uint4 hv, lv;
        hv.x = (uint32_t)h[0] | ((uint32_t)h[1] << 16);
        hv.y = (uint32_t)h[2] | ((uint32_t)h[3] << 16);
        hv.z = (uint32_t)h[4] | ((uint32_t)h[5] << 16);
        hv.w = (uint32_t)h[6] | ((uint32_t)h[7] << 16);
        lv.x = (uint32_t)f16_of(r[0]) | ((uint32_t)f16_of(r[1]) << 16);
        lv.y = (uint32_t)f16_of(r[2]) | ((uint32_t)f16_of(r[3]) << 16);
        lv.z = (uint32_t)f16_of(r[4]) | ((uint32_t)f16_of(r[5]) << 16);
        lv.w = (uint32_t)f16_of(r[6]) | ((uint32_t)f16_of(r[7]) << 16);
        yhi[i] = hv;
        ylo[i] = lv;
        return;
    }

    const int tx = tid & 31;
    const int ty = tid >> 5;

    const float* W;
    unsigned short *thi, *tlo = nullptr;
    int K, t;
    if (blk < PREP_XB + PREP_YB + PREP_WQB) {
        t = blk - (PREP_XB + PREP_YB);
        W = Wq; thi = wq; K = EMBED;
    } else if (blk < PREP_XB + PREP_YB + PREP_WQB + PREP_WKVB) {
        t = blk - (PREP_XB + PREP_YB + PREP_WQB);
        int z = t / 480;
        t = t % 480;
        W = z ? Wv : Wk;
        thi = z ? wvhi : wkhi;
        tlo = z ? wvlo : wklo;
        K = CROSS;
    } else {
        t = blk - (PREP_XB + PREP_YB + PREP_WQB + PREP_WKVB);
        W = Wo; thi = wo; K = EMBED;
    }
    const int n0 = (t % 20) * 32;
    const int k0 = (t / 20) * 32;
#pragma unroll
    for (int i = 0; i < 32; i += 8)
        tile[ty + i][tx] = W[(size_t)(k0 + ty + i) * EMBED + n0 + tx];
    __syncthreads();
#pragma unroll
    for (int i = 0; i < 32; i += 8) {
        float v = tile[tx][ty + i];
        size_t oi = (size_t)(n0 + ty + i) * K + k0 + tx;
        if (tlo) {
            float rem;
            unsigned short h = f16_hi(v, rem);
            thi[oi] = h;
            tlo[oi] = f16_of(rem);
        } else {
            thi[oi] = f16_of(v);
        }
    }
}

// ---------------------------------------------------------------------------
// Fused K+V projections (z=0 -> K normal; z=1 -> V transposed into vt)
// ---------------------------------------------------------------------------
#define SLOT3 40960u
__global__ __launch_bounds__(256, 1)
void gemm_mma3kv(const unsigned short* __restrict__ Ahi,
                 const unsigned short* __restrict__ Alo,
                 const unsigned short* __restrict__ Bhi0,
                 const unsigned short* __restrict__ Blo0,
                 const unsigned short* __restrict__ Bhi1,
                 const unsigned short* __restrict__ Blo1,
                 const float* __restrict__ bias0,
                 const float* __restrict__ bias1,
                 unsigned short* __restrict__ Ck,
                 unsigned short* __restrict__ Cvt,
                 int M, int K) {
    extern __shared__ char smem[];
    const uint32_t sbase = smem_to_u32(smem);
    const int tid = threadIdx.x;
    const int lane = tid & 31;
    const int wid = tid >> 5;
    const int wm = wid >> 2;
    const int wn = wid & 3;
    const int bm = blockIdx.y * 128;
    const int bn = blockIdx.x * 128;
    const int rowU4 = K >> 3;
    const int nst = K >> 5;
    const int maxAr = (M - bm - 1 < 127) ? (M - bm - 1) : 127;
    const int isV = blockIdx.z;

    const unsigned short* Bhi = isV ? Bhi1 : Bhi0;
    const unsigned short* Blo = isV ? Blo1 : Blo0;
    const float* bias = isV ? bias1 : bias0;

    const uint4* gA0 = (const uint4*)(Ahi + (size_t)bm * K);
    const uint4* gA1 = (const uint4*)(Alo + (size_t)bm * K);
    const uint4* gB0 = (const uint4*)(Bhi + (size_t)bn * K);
    const uint4* gB1 = (const uint4*)(Blo + (size_t)bn * K);

    float d[4][4][4];
#pragma unroll
    for (int i = 0; i < 4; i++)
#pragma unroll
        for (int j = 0; j < 4; j++)
#pragma unroll
            for (int r = 0; r < 4; r++) d[i][j][r] = 0.f;

    auto load_stage = [&](int slot, int kt) {
        uint32_t sb = sbase + (uint32_t)slot * SLOT3;
#pragma unroll
        for (int j = 0; j < 8; j++) {
            int gidx = j * 256 + tid;
            int term = gidx >> 9;
            int idx = gidx & 511;
            int r = idx >> 2;
            int c = idx & 3;
            int re = (term < 2 && r > maxAr) ? maxAr : r;
            const uint4* src = (term == 0) ? gA0 : (term == 1) ? gA1
                             : (term == 2) ? gB0 : gB1;
            const uint4* gp = src + (size_t)re * rowU4 + kt * 4 + c;
            uint32_t sp = sb + (uint32_t)term * 10240u
                        + (uint32_t)(r * 80 + c * 16);
            CP16(sp, gp);
        }
        CP_COMMIT();
    };

    auto compute_stage = [&](int slot) {
        uint32_t sb = sbase + (uint32_t)slot * SLOT3;
        const uint32_t aOff[2] = {sb, sb + 10240u};
        const uint32_t bOff[2] = {sb + 20480u, sb + 30720u};
#pragma unroll
        for (int kk = 0; kk < 2; kk++) {
            const uint32_t colB = (uint32_t)(kk * 32) + ((lane & 16) ? 16u : 0u);
            uint32_t ah[4][4], al[4][4];
#pragma unroll
            for (int mt = 0; mt < 4; mt++) {
                int row = wm * 64 + mt * 16 + (lane & 15);
                LDSM4(ah[mt], aOff[0] + (uint32_t)(row * 80) + colB);
                LDSM4(al[mt], aOff[1] + (uint32_t)(row * 80) + colB);
            }
            uint32_t bh[4][2], bl[4][2];
#pragma unroll
            for (int nt2 = 0; nt2 < 2; nt2++) {
                int row = wn * 32 + nt2 * 16 + (lane & 15);
                uint32_t r4[4];
                LDSM4(r4, bOff[0] + (uint32_t)(row * 80) + colB);
                bh[nt2 * 2 + 0][0] = r4[0]; bh[nt2 * 2 + 0][1] = r4[2];
                bh[nt2 * 2 + 1][0] = r4[1]; bh[nt2 * 2 + 1][1] = r4[3];
                LDSM4(r4, bOff[1] + (uint32_t)(row * 80) + colB);
                bl[nt2 * 2 + 0][0] = r4[0]; bl[nt2 * 2 + 0][1] = r4[2];
                bl[nt2 * 2 + 1][0] = r4[1]; bl[nt2 * 2 + 1][1] = r4[3];
            }
#pragma unroll
            for (int mt = 0; mt < 4; mt++)
#pragma unroll
                for (int nt = 0; nt < 4; nt++) {
                    MMAF16(d[mt][nt], ah[mt], bh[nt]);
                    MMAF16(d[mt][nt], ah[mt], bl[nt]);
                    MMAF16(d[mt][nt], al[mt], bh[nt]);
                }
        }
    };

    load_stage(0, 0);
    load_stage(1, 1);
    for (int s = 0; s < nst; s++) {
        if (s + 1 < nst) { CP_WAIT1(); } else { CP_WAIT0(); }
        __syncthreads();
        if (s + 2 < nst) load_stage((s + 2) % 3, s + 2);
        compute_stage(s % 3);
    }

#pragma unroll
    for (int mt = 0; mt < 4; mt++) {
        int row0 = bm + wm * 64 + mt * 16 + (lane >> 2);
#pragma unroll
        for (int nt = 0; nt < 4; nt++) {
            int col = bn + wn * 32 + nt * 8 + (lane & 3) * 2;
            float2 bv = *(const float2*)&bias[col];
#pragma unroll
            for (int half = 0; half < 2; half++) {
                int row = row0 + half * 8;
                if (row >= M) continue;
                float v0 = d[mt][nt][half * 2 + 0] + bv.x;
                float v1 = d[mt][nt][half * 2 + 1] + bv.y;
                if (!isV) {
                    uint32_t p = (uint32_t)f16_of(v0) | ((uint32_t)f16_of(v1) << 16);
                    *(uint32_t*)&Ck[(size_t)row * EMBED + col] = p;
                } else {
                    int b = row / SEQ_S;
                    int s = row - b * SEQ_S;
                    int h = col / 80;
                    int dd = col - h * 80;
                    size_t base = ((size_t)(b * N_HEADS + h) * 80 + dd) * 80 + s;
                    Cvt[base] = f16_of(v0);
                    Cvt[base + 80] = f16_of(v1);
                }
            }
        }
    }
}

// ---------------------------------------------------------------------------
// 1-term fp16 GEMM core. OUT: 0 = fp32, 2 = scaled fp16 (hi only)
// ---------------------------------------------------------------------------
#define SLOT1 20480u
template <int OUT>
__device__ __forceinline__ void gemm1_body(
    const unsigned short* __restrict__ Ah,
    const unsigned short* __restrict__ Bh,
    const float* __restrict__ bias, float* __restrict__ C,
    unsigned short* __restrict__ Chi,
    float oscale, int M, int K, char* smem) {
    const uint32_t sbase = smem_to_u32(smem);
    const int tid = threadIdx.x;
    const int lane = tid & 31;
    const int wid = tid >> 5;
    const int wm = wid >> 2;
    const int wn = wid & 3;
    const int bm = blockIdx.y * 128;
    const int bn = blockIdx.x * 128;
    const int rowU4 = K >> 3;
    const int nst = K >> 5;

    const uint4* gA0 = (const uint4*)(Ah + (size_t)bm * K);
    const uint4* gB0 = (const uint4*)(Bh + (size_t)bn * K);

    float d[4][4][4];
#pragma unroll
    for (int i = 0; i < 4; i++)
#pragma unroll
        for (int j = 0; j < 4; j++)
#pragma unroll
            for (int r = 0; r < 4; r++) d[i][j][r] = 0.f;

    auto load_stage = [&](int slot, int kt) {
        uint32_t sb = sbase + (uint32_t)slot * SLOT1;
#pragma unroll
        for (int j = 0; j < 4; j++) {
            int gidx = j * 256 + tid;
            int term = gidx >> 9;
            int idx = gidx & 511;
            int r = idx >> 2;
            int c = idx & 3;
            const uint4* src = (term == 0) ? gA0 : gB0;
            const uint4* gp = src + (size_t)r * rowU4 + kt * 4 + c;
            uint32_t sp = sb + (uint32_t)term * 10240u
                        + (uint32_t)(r * 80 + c * 16);
            CP16(sp, gp);
        }
        CP_COMMIT();
    };

    auto compute_stage = [&](int slot) {
        uint32_t sb = sbase + (uint32_t)slot * SLOT1;
        const uint32_t aOff = sb;
        const uint32_t bOff = sb + 10240u;
#pragma unroll
        for (int kk = 0; kk < 2; kk++) {
            const uint32_t colB = (uint32_t)(kk * 32) + ((lane & 16) ? 16u : 0u);
            uint32_t ah[4][4];
#pragma unroll
            for (int mt = 0; mt < 4; mt++) {
                int row = wm * 64 + mt * 16 + (lane & 15);
                LDSM4(ah[mt], aOff + (uint32_t)(row * 80) + colB);
            }
            uint32_t bh[4][2];
#pragma unroll
            for (int nt2 = 0; nt2 < 2; nt2++) {
                int row = wn * 32 + nt2 * 16 + (lane & 15);
                uint32_t r4[4];
                LDSM4(r4, bOff + (uint32_t)(row * 80) + colB);
                bh[nt2 * 2 + 0][0] = r4[0]; bh[nt2 * 2 + 0][1] = r4[2];
                bh[nt2 * 2 + 1][0] = r4[1]; bh[nt2 * 2 + 1][1] = r4[3];
            }
#pragma unroll
            for (int mt = 0; mt < 4; mt++)
#pragma unroll
                for (int nt = 0; nt < 4; nt++)
                    MMAF16(d[mt][nt], ah[mt], bh[nt]);
        }
    };

    load_stage(0, 0);
    load_stage(1, 1);
    load_stage(2, 2);
    for (int s = 0; s < nst; s++) {
        if (s + 2 < nst) { CP_WAIT2(); }
        else if (s + 1 < nst) { CP_WAIT1(); }
        else { CP_WAIT0(); }
        __syncthreads();
        if (s + 3 < nst) load_stage((s + 3) & 3, s + 3);
        compute_stage(s & 3);
    }

#pragma unroll
    for (int mt = 0; mt < 4; mt++) {
        int row0 = bm + wm * 64 + mt * 16 + (lane >> 2);
#pragma unroll
        for (int nt = 0; nt < 4; nt++) {
            int col = bn + wn * 32 + nt * 8 + (lane & 3) * 2;
            float2 bv = *(const float2*)&bias[col];
#pragma unroll
            for (int half = 0; half < 2; half++) {
                int row = row0 + half * 8;
                float v0 = (d[mt][nt][half * 2 + 0] + bv.x) * oscale;
                float v1 = (d[mt][nt][half * 2 + 1] + bv.y) * oscale;
                if (OUT == 2) {
                    *(uint32_t*)&Chi[(size_t)row * EMBED + col] =
                        (uint32_t)f16_of(v0) | ((uint32_t)f16_of(v1) << 16);
                } else {
                    *(float2*)&C[(size_t)row * EMBED + col] = make_float2(v0, v1);
                }
            }
        }
    }
}

__global__ __launch_bounds__(256, 2)
void gemm_mma1(const unsigned short* __restrict__ Ah,
               const unsigned short* __restrict__ Bh,
               const float* __restrict__ bias, float* __restrict__ C,
               int M, int K) {
    extern __shared__ char smem[];
    gemm1_body<0>(Ah, Bh, bias, C, nullptr, 1.0f, M, K, smem);
}

__global__ __launch_bounds__(256, 2)
void gemm_mma1q(const unsigned short* __restrict__ Ah,
                const unsigned short* __restrict__ Bh,
                const float* __restrict__ bias,
                unsigned short* __restrict__ Chi,
                int M, int K) {
    extern __shared__ char smem[];
    gemm1_body<2>(Ah, Bh, bias, nullptr, Chi,
                  0.11180339887498949f, M, K, smem);
}

// ---------------------------------------------------------------------------
// Tensor-core attention: 128 t-rows x (b,h), 8 warps x 16 rows.
// q A-fragments direct from gmem; smem = k + v^T only (28.2 KB) -> blocks
// halve vs 64-row version, halving k/v staging traffic.
// ---------------------------------------------------------------------------
#define AT_STR 88
#define AT_T 256
__global__ __launch_bounds__(AT_T)
void attn_mma(const unsigned short* __restrict__ qhi,
              const unsigned short* __restrict__ khi,
              const unsigned short* __restrict__ vt,
              unsigned short* __restrict__ ohi) {
    extern __shared__ unsigned short smh[];
    unsigned short* skh = smh;                    // 80*88
    unsigned short* svt = skh + 80 * AT_STR;      // 80*88

    const int b = blockIdx.z;
    const int h = blockIdx.y;
    const int t0 = blockIdx.x * 128;
    const int tid = threadIdx.x;
    const int w = tid >> 5;
    const int lane = tid & 31;

    for (int i = tid; i < 3 * AT_STR; i += AT_T)
        skh[77 * AT_STR + i] = 0;

    for (int i = tid; i < 770; i += AT_T) {
        int s = i / 10, c = i - s * 10;
        size_t gi = ((size_t)(b * SEQ_S + s)) * 80 + h * 10 + c;
        *(uint4*)&skh[s * AT_STR + c * 8] = ((const uint4*)khi)[gi];
    }
    {
        const uint4* vsrc = (const uint4*)(vt + ((size_t)(b * N_HEADS + h) * 80) * 80);
        for (int i = tid; i < 800; i += AT_T) {
            int dd = i / 10, c = i - dd * 10;
            *(uint4*)&svt[dd * AT_STR + c * 8] = vsrc[dd * 10 + c];
        }
    }

    const size_t qrow0 = (size_t)(b * SEQ_T + t0 + w * 16 + (lane >> 2));
    const size_t qb0 = qrow0 * EMBED + h * 80 + (lane & 3) * 2;
    const size_t qb1 = qb0 + 8 * EMBED;

    __syncthreads();

    const uint32_t skh_b = smem_to_u32(skh);
    const uint32_t svt_b = smem_to_u32(svt);
    const uint32_t lrow = (uint32_t)(lane & 15) * (AT_STR * 2);
    const uint32_t loff = (lane & 16) ? 16u : 0u;

    float d[10][4];
#pragma unroll
    for (int nt = 0; nt < 10; nt++)
#pragma unroll
        for (int c = 0; c < 4; c++) d[nt][c] = 0.f;

#pragma unroll
    for (int ks = 0; ks < 5; ks++) {
        const uint32_t ca = (uint32_t)(ks * 32) + loff;
        uint32_t ah[4];
        ah[0] = *(const uint32_t*)&qhi[qb0 + ks * 16];
        ah[1] = *(const uint32_t*)&qhi[qb1 + ks * 16];
        ah[2] = *(const uint32_t*)&qhi[qb0 + ks * 16 + 8];
        ah[3] = *(const uint32_t*)&qhi[qb1 + ks * 16 + 8];
#pragma unroll
        for (int nt2 = 0; nt2 < 5; nt2++) {
            uint32_t r4[4];
            LDSM4(r4, skh_b + (uint32_t)(nt2 * 16) * (AT_STR * 2) + lrow + ca);
            uint32_t b0[2] = {r4[0], r4[2]};
            uint32_t b1[2] = {r4[1], r4[3]};
            MMAF16(d[nt2 * 2 + 0], ah, b0);
            MMAF16(d[nt2 * 2 + 1], ah, b1);
        }
    }

    {
        int colb = 72 + (lane & 3) * 2;
        if (colb >= 77)     { d[9][0] = -1e30f; d[9][2] = -1e30f; }
        if (colb + 1 >= 77) { d[9][1] = -1e30f; d[9][3] = -1e30f; }
    }

    {
        float mA = -1e30f, mB = -1e30f;
#pragma unroll
        for (int nt = 0; nt < 10; nt++) {
            mA = fmaxf(mA, fmaxf(d[nt][0], d[nt][1]));
            mB = fmaxf(mB, fmaxf(d[nt][2], d[nt][3]));
        }
        mA = fmaxf(mA, __shfl_xor_sync(0xFFFFFFFFu, mA, 1));
        mA = fmaxf(mA, __shfl_xor_sync(0xFFFFFFFFu, mA, 2));
        mB = fmaxf(mB, __shfl_xor_sync(0xFFFFFFFFu, mB, 1));
        mB = fmaxf(mB, __shfl_xor_sync(0xFFFFFFFFu, mB, 2));
        float sA = 0.f, sB = 0.f;
#pragma unroll
        for (int nt = 0; nt < 10; nt++) {
            d[nt][0] = __expf(d[nt][0] - mA); sA += d[nt][0];
            d[nt][1] = __expf(d[nt][1] - mA); sA += d[nt][1];
            d[nt][2] = __expf(d[nt][2] - mB); sB += d[nt][2];
            d[nt][3] = __expf(d[nt][3] - mB); sB += d[nt][3];
        }
        sA += __shfl_xor_sync(0xFFFFFFFFu, sA, 1);
        sA += __shfl_xor_sync(0xFFFFFFFFu, sA, 2);
        sB += __shfl_xor_sync(0xFFFFFFFFu, sB, 1);
        sB += __shfl_xor_sync(0xFFFFFFFFu, sB, 2);
        float rA = 1.f / sA, rB = 1.f / sB;
#pragma unroll
        for (int nt = 0; nt < 10; nt++) {
            d[nt][0] *= rA; d[nt][1] *= rA;
            d[nt][2] *= rB; d[nt][3] *= rB;
        }
    }

    uint32_t pa[5][4];
#pragma unroll
    for (int kp = 0; kp < 5; kp++) {
        pa[kp][0] = pack_f16x2(d[2 * kp][0],     d[2 * kp][1]);
        pa[kp][1] = pack_f16x2(d[2 * kp][2],     d[2 * kp][3]);
        pa[kp][2] = pack_f16x2(d[2 * kp + 1][0], d[2 * kp + 1][1]);
        pa[kp][3] = pack_f16x2(d[2 * kp + 1][2], d[2 * kp + 1][3]);
    }

    float o[10][4];
#pragma unroll
    for (int nt = 0; nt < 10; nt++)
#pragma unroll
        for (int c = 0; c < 4; c++) o[nt][c] = 0.f;

#pragma unroll
    for (int kp = 0; kp < 5; kp++) {
        const uint32_t ca = (uint32_t)(kp * 32) + loff;
#pragma unroll
        for (int nt2 = 0; nt2 < 5; nt2++) {
            uint32_t r4[4];
            LDSM4(r4, svt_b + (uint32_t)(nt2 * 16) * (AT_STR * 2) + lrow + ca);
            uint32_t b0[2] = {r4[0], r4[2]};
            uint32_t b1[2] = {r4[1], r4[3]};
            MMAF16(o[nt2 * 2 + 0], pa[kp], b0);
            MMAF16(o[nt2 * 2 + 1], pa[kp], b1);
        }
    }

    {
        const size_t rbase = (size_t)(b * SEQ_T + t0 + w * 16 + (lane >> 2));
        const int col = h * 80 + (lane & 3) * 2;
#pragma unroll
        for (int nt = 0; nt < 10; nt++) {
            *(uint32_t*)&ohi[rbase * EMBED + col + nt * 8] =
                pack_f16x2(o[nt][0], o[nt][1]);
            *(uint32_t*)&ohi[(rbase + 8) * EMBED + col + nt * 8] =
                pack_f16x2(o[nt][2], o[nt][3]);
        }
    }
}

// ---------------------------------------------------------------------------
extern "C" void kernel_launch(void* const* d_in, const int* in_sizes, int n_in,
                              void* d_out, int out_size) {
    const float* x  = (const float*)d_in[0];
    const float* y  = (const float*)d_in[1];
    const float* Wq = (const float*)d_in[2];
    const float* bq = (const float*)d_in[3];
    const float* Wk = (const float*)d_in[4];
    const float* bk = (const float*)d_in[5];
    const float* Wv = (const float*)d_in[6];
    const float* bv = (const float*)d_in[7];
    const float* Wo = (const float*)d_in[8];
    const float* bo = (const float*)d_in[9];
    float* out = (float*)d_out;

    unsigned short *xhi, *qhi, *khi, *vt, *yhi, *ylo;
    unsigned short *wq, *wo, *wkhi, *wklo, *wvhi, *wvlo;
    cudaGetSymbolAddress((void**)&xhi, g_xhi);
    cudaGetSymbolAddress((void**)&qhi, g_qhi);
    cudaGetSymbolAddress((void**)&khi, g_khi);
    cudaGetSymbolAddress((void**)&vt, g_vt);
    cudaGetSymbolAddress((void**)&yhi, g_yhi);
    cudaGetSymbolAddress((void**)&ylo, g_ylo);
    cudaGetSymbolAddress((void**)&wq, g_wq);
    cudaGetSymbolAddress((void**)&wo, g_wo);
    cudaGetSymbolAddress((void**)&wkhi, g_wkhi);
    cudaGetSymbolAddress((void**)&wklo, g_wklo);
    cudaGetSymbolAddress((void**)&wvhi, g_wvhi);
    cudaGetSymbolAddress((void**)&wvlo, g_wvlo);

    const int smem_attn = (80 * AT_STR * 2) * 2;  // 28160 B
    cudaFuncSetAttribute(attn_mma, cudaFuncAttributeMaxDynamicSharedMemorySize, smem_attn);
    const int smem_m3 = 3 * (int)SLOT3;
    cudaFuncSetAttribute(gemm_mma3kv, cudaFuncAttributeMaxDynamicSharedMemorySize, smem_m3);
    const int smem_m1 = 4 * (int)SLOT1;
    cudaFuncSetAttribute(gemm_mma1, cudaFuncAttributeMaxDynamicSharedMemorySize, smem_m1);
    cudaFuncSetAttribute(gemm_mma1q, cudaFuncAttributeMaxDynamicSharedMemorySize, smem_m1);

    const int MKV = BATCH * SEQ_S;

    cudaStream_t s2;
    cudaEvent_t e1, e2;
    cudaStreamCreateWithFlags(&s2, cudaStreamNonBlocking);
    cudaEventCreateWithFlags(&e1, cudaEventDisableTiming);
    cudaEventCreateWithFlags(&e2, cudaEventDisableTiming);

    // --- 1. fused preprocessing ---
    {
        int nblk = PREP_XB + PREP_YB + PREP_WQB + PREP_WKVB + PREP_WOB;
        prep_all<<<nblk, 256>>>((const float4*)x, (const float4*)y,
                                Wq, Wk, Wv, Wo,
                                (uint4*)xhi, (uint4*)yhi, (uint4*)ylo,
                                wq, wkhi, wklo, wvhi, wvlo, wo);
    }
    cudaEventRecord(e1, 0);
    cudaStreamWaitEvent(s2, e1, 0);

    // --- 2a. K/V projections on side stream ---
    {
        dim3 grid(EMBED / 128, (MKV + 127) / 128, 2);
        gemm_mma3kv<<<grid, 256, smem_m3, s2>>>(yhi, ylo, wkhi, wklo, wvhi, wvlo,
                                                bk, bv, khi, vt, MKV, CROSS);
    }
    cudaEventRecord(e2, s2);

    // --- 2b. Q projection on main stream (scaled fp16 out) ---
    {
        dim3 grid(EMBED / 128, (BATCH * SEQ_T) / 128);
        gemm_mma1q<<<grid, 256, smem_m1>>>(xhi, wq, bq, qhi, BATCH * SEQ_T, EMBED);
    }
    cudaStreamWaitEvent(0, e2, 0);

    // --- 3. attention (128 t-rows per block) ---
    {
        dim3 grid(SEQ_T / 128, N_HEADS, BATCH);
        attn_mma<<<grid, AT_T, smem_attn>>>(qhi, khi, vt, xhi);
    }

    // --- 4. O projection ---
    {
        dim3 grid(EMBED / 128, (BATCH * SEQ_T) / 128);
        gemm_mma1<<<grid, 256, smem_m1>>>(xhi, wo, bo, out, BATCH * SEQ_T, EMBED);
    }

    cudaEventDestroy(e1);
    cudaEventDestroy(e2);
    cudaStreamDestroy(s2);
}